// round 2
// baseline (speedup 1.0000x reference)
#include <cuda_runtime.h>

#define BB 8
#define MM 8192
#define NN 512
#define RR 256
#define EPSV 1e-16f

// scratch (no allocations allowed)
__device__ float g_v2[BB * RR];                 // ||v_r||^2 per batch
__device__ float g_S[BB * RR];                  // column sums of u
__device__ float g_Spart[BB * 32 * RR];         // partial column sums
__device__ float g_part[BB * 4 * NN * RR];      // split-K partials for v (16MB)

// ---------------------------------------------------------------------------
// v2[b][r] = sum_n x[b, inds[r], n]^2   (one warp per (b,r))
// ---------------------------------------------------------------------------
__global__ void k_v2(const float* __restrict__ x, const int* __restrict__ inds) {
    int gw = (blockIdx.x * blockDim.x + threadIdx.x) >> 5;
    int lane = threadIdx.x & 31;
    if (gw >= BB * RR) return;
    int b = gw >> 8, r = gw & 255;
    const float* row = x + ((size_t)b * MM + inds[r]) * NN;
    float s = 0.f;
    const float4* row4 = (const float4*)row;
    #pragma unroll
    for (int i = lane; i < NN / 4; i += 32) {
        float4 v = row4[i];
        s += v.x * v.x + v.y * v.y + v.z * v.z + v.w * v.w;
    }
    #pragma unroll
    for (int o = 16; o; o >>= 1) s += __shfl_xor_sync(0xffffffffu, s, o);
    if (lane == 0) g_v2[gw] = s;
}

// ---------------------------------------------------------------------------
// GEMM1 fused: xv = x @ V^T, d = relu(x2 - 2 xv + v2), u = softmax(-d/alpha)
// Block: 256 thr, tile 64(m) x 256(r, full row), BK=16, micro 8x8.
// Warp w owns rows w*8..w*8+7 -> full softmax row inside one warp.
// ---------------------------------------------------------------------------
__global__ __launch_bounds__(256, 2) void k_gemm1(
    const float* __restrict__ x, const float* __restrict__ alpha,
    const int* __restrict__ inds, float* __restrict__ u)
{
    __shared__ float As[16][64];
    __shared__ float Bs[16][256];
    __shared__ float sv2[256];
    __shared__ float sx2[64];
    __shared__ int   sind[256];

    const int t  = threadIdx.x;
    const int b  = blockIdx.x >> 7;          // 128 m-tiles per batch
    const int m0 = (blockIdx.x & 127) << 6;
    const int w  = t >> 5, l = t & 31;

    sind[t] = inds[t];
    sv2[t]  = g_v2[(b << 8) + t];
    const float aval = alpha[0];
    __syncthreads();

    const float* xb   = x + (size_t)b * MM * NN;
    const float* arow = xb + (size_t)(m0 + (t >> 2)) * NN + ((t & 3) << 2);
    const float* brow = xb + (size_t)sind[t] * NN;

    float acc[8][8];
    #pragma unroll
    for (int i = 0; i < 8; i++)
        #pragma unroll
        for (int j = 0; j < 8; j++) acc[i][j] = 0.f;
    float xsq = 0.f;

    for (int k0 = 0; k0 < NN; k0 += 16) {
        float4 av = *(const float4*)(arow + k0);
        float4 b0 = *(const float4*)(brow + k0);
        float4 b1 = *(const float4*)(brow + k0 + 4);
        float4 b2 = *(const float4*)(brow + k0 + 8);
        float4 b3 = *(const float4*)(brow + k0 + 12);
        __syncthreads();
        {
            int kk = (t & 3) << 2, mm = t >> 2;
            As[kk + 0][mm] = av.x; As[kk + 1][mm] = av.y;
            As[kk + 2][mm] = av.z; As[kk + 3][mm] = av.w;
            xsq += av.x * av.x + av.y * av.y + av.z * av.z + av.w * av.w;
            Bs[0][t] = b0.x;  Bs[1][t] = b0.y;  Bs[2][t] = b0.z;  Bs[3][t] = b0.w;
            Bs[4][t] = b1.x;  Bs[5][t] = b1.y;  Bs[6][t] = b1.z;  Bs[7][t] = b1.w;
            Bs[8][t] = b2.x;  Bs[9][t] = b2.y;  Bs[10][t] = b2.z; Bs[11][t] = b2.w;
            Bs[12][t] = b3.x; Bs[13][t] = b3.y; Bs[14][t] = b3.z; Bs[15][t] = b3.w;
        }
        __syncthreads();
        #pragma unroll
        for (int kk = 0; kk < 16; kk++) {
            float4 a0 = *(const float4*)&As[kk][w << 3];
            float4 a1 = *(const float4*)&As[kk][(w << 3) + 4];
            float4 c0 = *(const float4*)&Bs[kk][l << 2];
            float4 c1 = *(const float4*)&Bs[kk][128 + (l << 2)];
            float ar[8] = {a0.x, a0.y, a0.z, a0.w, a1.x, a1.y, a1.z, a1.w};
            float br[8] = {c0.x, c0.y, c0.z, c0.w, c1.x, c1.y, c1.z, c1.w};
            #pragma unroll
            for (int i = 0; i < 8; i++)
                #pragma unroll
                for (int j = 0; j < 8; j++)
                    acc[i][j] += ar[i] * br[j];
        }
    }

    // finish x2 per row (threads t, t^1, t^2, t^3 share row t>>2)
    xsq += __shfl_xor_sync(0xffffffffu, xsq, 1);
    xsq += __shfl_xor_sync(0xffffffffu, xsq, 2);
    if ((t & 3) == 0) sx2[t >> 2] = xsq;
    __syncthreads();

    // softmax per row (row fully inside warp w)
    float* urow_base = u + ((size_t)b * MM + m0) * RR;
    #pragma unroll
    for (int i = 0; i < 8; i++) {
        const int row = (w << 3) + i;
        const float x2i = sx2[row];
        float z[8];
        #pragma unroll
        for (int j = 0; j < 8; j++) {
            int r = (j < 4) ? ((l << 2) + j) : (128 + (l << 2) + (j - 4));
            float d = fmaxf(x2i - 2.0f * acc[i][j] + sv2[r], 0.0f);
            z[j] = (-d) / aval;
        }
        float mx = z[0];
        #pragma unroll
        for (int j = 1; j < 8; j++) mx = fmaxf(mx, z[j]);
        #pragma unroll
        for (int o = 16; o; o >>= 1) mx = fmaxf(mx, __shfl_xor_sync(0xffffffffu, mx, o));
        float e[8], sum = 0.f;
        #pragma unroll
        for (int j = 0; j < 8; j++) { e[j] = __expf(z[j] - mx); sum += e[j]; }
        #pragma unroll
        for (int o = 16; o; o >>= 1) sum += __shfl_xor_sync(0xffffffffu, sum, o);
        float inv = 1.0f / sum;
        float4 o0 = {e[0] * inv, e[1] * inv, e[2] * inv, e[3] * inv};
        float4 o1 = {e[4] * inv, e[5] * inv, e[6] * inv, e[7] * inv};
        float* ur = urow_base + (size_t)row * RR;
        *(float4*)(ur + (l << 2)) = o0;
        *(float4*)(ur + 128 + (l << 2)) = o1;
    }
}

// ---------------------------------------------------------------------------
// Column sums of u: two deterministic passes (no atomics)
// ---------------------------------------------------------------------------
__global__ void k_colsum_part(const float* __restrict__ u) {
    int b = blockIdx.x >> 5, chunk = blockIdx.x & 31;
    int r = threadIdx.x;
    const float* p = u + ((size_t)b * MM + (size_t)chunk * 256) * RR + r;
    float s0 = 0.f, s1 = 0.f, s2 = 0.f, s3 = 0.f;
    for (int m = 0; m < 256; m += 4) {
        s0 += p[(size_t)(m + 0) * RR];
        s1 += p[(size_t)(m + 1) * RR];
        s2 += p[(size_t)(m + 2) * RR];
        s3 += p[(size_t)(m + 3) * RR];
    }
    g_Spart[((size_t)blockIdx.x << 8) + r] = (s0 + s1) + (s2 + s3);
}

__global__ void k_colsum_final() {
    int i = blockIdx.x * blockDim.x + threadIdx.x;
    if (i >= BB * RR) return;
    int b = i >> 8, r = i & 255;
    float s = 0.f;
    #pragma unroll
    for (int c = 0; c < 32; c++) s += g_Spart[(((size_t)(b * 32 + c)) << 8) + r];
    g_S[i] = s;
}

// ---------------------------------------------------------------------------
// GEMM2 split-K: part[b][s] = x[k-range]^T @ ((u[k-range]+eps) * rinv[r])
// Block: 256 thr, tile 128(n) x 128(r), BK=16, micro 16x4, split K=8192 into 4.
// ---------------------------------------------------------------------------
__global__ __launch_bounds__(256, 2) void k_gemm2(
    const float* __restrict__ x, const float* __restrict__ u)
{
    const int blk = blockIdx.x;
    const int sp  = blk & 3;
    const int rt  = (blk >> 2) & 1;
    const int nt  = (blk >> 3) & 3;
    const int b   = blk >> 5;
    const int n0 = nt << 7, r0 = rt << 7;
    const int kb = sp * 2048, ke = kb + 2048;

    __shared__ float As[16][128];
    __shared__ float Bs[16][128];
    __shared__ float srinv[128];

    const int t = threadIdx.x;
    const int w = t >> 5, l = t & 31;
    if (t < 128) srinv[t] = 1.0f / (g_S[(b << 8) + r0 + t] + EPSV);

    const float* xb = x + (size_t)b * MM * NN;
    const float* ub = u + (size_t)b * MM * RR;

    float acc[16][4];
    #pragma unroll
    for (int i = 0; i < 16; i++)
        #pragma unroll
        for (int j = 0; j < 4; j++) acc[i][j] = 0.f;

    const int kkA = t >> 5;          // 0..7
    const int cf  = (t & 31) << 2;   // 0..124

    for (int k0 = kb; k0 < ke; k0 += 16) {
        float4 a0 = *(const float4*)(xb + (size_t)(k0 + kkA) * NN + n0 + cf);
        float4 a1 = *(const float4*)(xb + (size_t)(k0 + kkA + 8) * NN + n0 + cf);
        float4 b0 = *(const float4*)(ub + (size_t)(k0 + kkA) * RR + r0 + cf);
        float4 b1 = *(const float4*)(ub + (size_t)(k0 + kkA + 8) * RR + r0 + cf);
        __syncthreads();
        *(float4*)&As[kkA][cf]     = a0;
        *(float4*)&As[kkA + 8][cf] = a1;
        float4 rv = *(const float4*)&srinv[cf];
        float4 q0 = {(b0.x + EPSV) * rv.x, (b0.y + EPSV) * rv.y,
                     (b0.z + EPSV) * rv.z, (b0.w + EPSV) * rv.w};
        float4 q1 = {(b1.x + EPSV) * rv.x, (b1.y + EPSV) * rv.y,
                     (b1.z + EPSV) * rv.z, (b1.w + EPSV) * rv.w};
        *(float4*)&Bs[kkA][cf]     = q0;
        *(float4*)&Bs[kkA + 8][cf] = q1;
        __syncthreads();
        #pragma unroll
        for (int kk = 0; kk < 16; kk++) {
            float4 bv = *(const float4*)&Bs[kk][l << 2];
            float4 av0 = *(const float4*)&As[kk][(w << 4)];
            float4 av1 = *(const float4*)&As[kk][(w << 4) + 4];
            float4 av2 = *(const float4*)&As[kk][(w << 4) + 8];
            float4 av3 = *(const float4*)&As[kk][(w << 4) + 12];
            float ar[16] = {av0.x, av0.y, av0.z, av0.w, av1.x, av1.y, av1.z, av1.w,
                            av2.x, av2.y, av2.z, av2.w, av3.x, av3.y, av3.z, av3.w};
            float br[4] = {bv.x, bv.y, bv.z, bv.w};
            #pragma unroll
            for (int i = 0; i < 16; i++)
                #pragma unroll
                for (int j = 0; j < 4; j++)
                    acc[i][j] += ar[i] * br[j];
        }
    }

    float* base = g_part + ((size_t)(b * 4 + sp) * NN + n0 + (w << 4)) * RR + r0 + (l << 2);
    #pragma unroll
    for (int i = 0; i < 16; i++) {
        float4 o = {acc[i][0], acc[i][1], acc[i][2], acc[i][3]};
        *(float4*)(base + (size_t)i * RR) = o;
    }
}

__global__ void k_vred(float* __restrict__ vout) {
    int i = blockIdx.x * blockDim.x + threadIdx.x;   // B*N*R = 1048576
    int b = i >> 17;
    int nr = i & 131071;
    float s = 0.f;
    #pragma unroll
    for (int sp = 0; sp < 4; sp++)
        s += g_part[((size_t)(b * 4 + sp)) * (NN * RR) + nr];
    vout[i] = s;
}

// ---------------------------------------------------------------------------
extern "C" void kernel_launch(void* const* d_in, const int* in_sizes, int n_in,
                              void* d_out, int out_size) {
    const float* x     = (const float*)d_in[0];
    const float* alpha = (const float*)d_in[1];
    const int*   inds  = (const int*)d_in[2];
    float* u = (float*)d_out;
    float* v = u + (size_t)BB * MM * RR;

    k_v2<<<(BB * RR) / 8, 256>>>(x, inds);
    k_gemm1<<<BB * (MM / 64), 256>>>(x, alpha, inds, u);
    k_colsum_part<<<BB * 32, 256>>>(u);
    k_colsum_final<<<8, 256>>>();
    k_gemm2<<<256, 256>>>(x, u);
    k_vred<<<(BB * NN * RR) / 256, 256>>>(v);
}

// round 5
// speedup vs baseline: 1.3681x; 1.3681x over previous
#include <cuda_runtime.h>
#include <cstdint>

#define BB 8
#define MM 8192
#define NN 512
#define RR 256
#define EPSV 1e-16f

// scratch (no allocations allowed)
__device__ float g_v2[BB * RR];
__device__ float g_S[BB * RR];
__device__ float g_Spart[BB * 32 * RR];
__device__ float g_part[BB * 4 * NN * RR];   // split-K partials for v

__device__ __forceinline__ uint32_t f2tf32(float f) {
    uint32_t r; asm("cvt.rna.tf32.f32 %0, %1;" : "=r"(r) : "f"(f)); return r;
}
__device__ __forceinline__ void mma_tf32(float4& d,
    uint32_t a0, uint32_t a1, uint32_t a2, uint32_t a3,
    uint32_t b0, uint32_t b1)
{
    asm volatile(
        "mma.sync.aligned.m16n8k8.row.col.f32.tf32.tf32.f32 "
        "{%0,%1,%2,%3}, {%4,%5,%6,%7}, {%8,%9}, {%0,%1,%2,%3};"
        : "+f"(d.x), "+f"(d.y), "+f"(d.z), "+f"(d.w)
        : "r"(a0), "r"(a1), "r"(a2), "r"(a3), "r"(b0), "r"(b1));
}

// ---------------------------------------------------------------------------
// v2[b][r] = sum_n x[b, inds[r], n]^2
// ---------------------------------------------------------------------------
__global__ void k_v2(const float* __restrict__ x, const int* __restrict__ inds) {
    int gw = (blockIdx.x * blockDim.x + threadIdx.x) >> 5;
    int lane = threadIdx.x & 31;
    if (gw >= BB * RR) return;
    int b = gw >> 8, r = gw & 255;
    const float* row = x + ((size_t)b * MM + inds[r]) * NN;
    float s = 0.f;
    const float4* row4 = (const float4*)row;
    #pragma unroll
    for (int i = lane; i < NN / 4; i += 32) {
        float4 v = row4[i];
        s += v.x * v.x + v.y * v.y + v.z * v.z + v.w * v.w;
    }
    #pragma unroll
    for (int o = 16; o; o >>= 1) s += __shfl_xor_sync(0xffffffffu, s, o);
    if (lane == 0) g_v2[gw] = s;
}

// ---------------------------------------------------------------------------
// GEMM1 fused (FFMA): xv = x @ V^T, d = relu(x2 - 2 xv + v2), u = softmax(-d/alpha)
// ---------------------------------------------------------------------------
__global__ __launch_bounds__(256, 2) void k_gemm1(
    const float* __restrict__ x, const float* __restrict__ alpha,
    const int* __restrict__ inds, float* __restrict__ u)
{
    __shared__ float As[16][64];
    __shared__ float Bs[16][256];
    __shared__ float sv2[256];
    __shared__ float sx2[64];
    __shared__ int   sind[256];

    const int t  = threadIdx.x;
    const int b  = blockIdx.x >> 7;
    const int m0 = (blockIdx.x & 127) << 6;
    const int w  = t >> 5, l = t & 31;

    sind[t] = inds[t];
    sv2[t]  = g_v2[(b << 8) + t];
    const float aval = alpha[0];
    __syncthreads();

    const float* xb   = x + (size_t)b * MM * NN;
    const float* arow = xb + (size_t)(m0 + (t >> 2)) * NN + ((t & 3) << 2);
    const float* brow = xb + (size_t)sind[t] * NN;

    float acc[8][8];
    #pragma unroll
    for (int i = 0; i < 8; i++)
        #pragma unroll
        for (int j = 0; j < 8; j++) acc[i][j] = 0.f;
    float xsq = 0.f;

    for (int k0 = 0; k0 < NN; k0 += 16) {
        float4 av = *(const float4*)(arow + k0);
        float4 b0 = *(const float4*)(brow + k0);
        float4 b1 = *(const float4*)(brow + k0 + 4);
        float4 b2 = *(const float4*)(brow + k0 + 8);
        float4 b3 = *(const float4*)(brow + k0 + 12);
        __syncthreads();
        {
            int kk = (t & 3) << 2, mm = t >> 2;
            As[kk + 0][mm] = av.x; As[kk + 1][mm] = av.y;
            As[kk + 2][mm] = av.z; As[kk + 3][mm] = av.w;
            xsq += av.x * av.x + av.y * av.y + av.z * av.z + av.w * av.w;
            Bs[0][t] = b0.x;  Bs[1][t] = b0.y;  Bs[2][t] = b0.z;  Bs[3][t] = b0.w;
            Bs[4][t] = b1.x;  Bs[5][t] = b1.y;  Bs[6][t] = b1.z;  Bs[7][t] = b1.w;
            Bs[8][t] = b2.x;  Bs[9][t] = b2.y;  Bs[10][t] = b2.z; Bs[11][t] = b2.w;
            Bs[12][t] = b3.x; Bs[13][t] = b3.y; Bs[14][t] = b3.z; Bs[15][t] = b3.w;
        }
        __syncthreads();
        #pragma unroll
        for (int kk = 0; kk < 16; kk++) {
            float4 a0 = *(const float4*)&As[kk][w << 3];
            float4 a1 = *(const float4*)&As[kk][(w << 3) + 4];
            float4 c0 = *(const float4*)&Bs[kk][l << 2];
            float4 c1 = *(const float4*)&Bs[kk][128 + (l << 2)];
            float ar[8] = {a0.x, a0.y, a0.z, a0.w, a1.x, a1.y, a1.z, a1.w};
            float br[8] = {c0.x, c0.y, c0.z, c0.w, c1.x, c1.y, c1.z, c1.w};
            #pragma unroll
            for (int i = 0; i < 8; i++)
                #pragma unroll
                for (int j = 0; j < 8; j++)
                    acc[i][j] += ar[i] * br[j];
        }
    }

    xsq += __shfl_xor_sync(0xffffffffu, xsq, 1);
    xsq += __shfl_xor_sync(0xffffffffu, xsq, 2);
    if ((t & 3) == 0) sx2[t >> 2] = xsq;
    __syncthreads();

    float* urow_base = u + ((size_t)b * MM + m0) * RR;
    #pragma unroll
    for (int i = 0; i < 8; i++) {
        const int row = (w << 3) + i;
        const float x2i = sx2[row];
        float z[8];
        #pragma unroll
        for (int j = 0; j < 8; j++) {
            int r = (j < 4) ? ((l << 2) + j) : (128 + (l << 2) + (j - 4));
            float d = fmaxf(x2i - 2.0f * acc[i][j] + sv2[r], 0.0f);
            z[j] = (-d) / aval;
        }
        float mx = z[0];
        #pragma unroll
        for (int j = 1; j < 8; j++) mx = fmaxf(mx, z[j]);
        #pragma unroll
        for (int o = 16; o; o >>= 1) mx = fmaxf(mx, __shfl_xor_sync(0xffffffffu, mx, o));
        float e[8], sum = 0.f;
        #pragma unroll
        for (int j = 0; j < 8; j++) { e[j] = __expf(z[j] - mx); sum += e[j]; }
        #pragma unroll
        for (int o = 16; o; o >>= 1) sum += __shfl_xor_sync(0xffffffffu, sum, o);
        float inv = 1.0f / sum;
        float4 o0 = {e[0] * inv, e[1] * inv, e[2] * inv, e[3] * inv};
        float4 o1 = {e[4] * inv, e[5] * inv, e[6] * inv, e[7] * inv};
        float* ur = urow_base + (size_t)row * RR;
        *(float4*)(ur + (l << 2)) = o0;
        *(float4*)(ur + 128 + (l << 2)) = o1;
    }
}

// ---------------------------------------------------------------------------
// Column sums of u (two deterministic passes)
// ---------------------------------------------------------------------------
__global__ void k_colsum_part(const float* __restrict__ u) {
    int b = blockIdx.x >> 5, chunk = blockIdx.x & 31;
    int r = threadIdx.x;
    const float* p = u + ((size_t)b * MM + (size_t)chunk * 256) * RR + r;
    float s0 = 0.f, s1 = 0.f, s2 = 0.f, s3 = 0.f;
    for (int m = 0; m < 256; m += 4) {
        s0 += p[(size_t)(m + 0) * RR];
        s1 += p[(size_t)(m + 1) * RR];
        s2 += p[(size_t)(m + 2) * RR];
        s3 += p[(size_t)(m + 3) * RR];
    }
    g_Spart[((size_t)blockIdx.x << 8) + r] = (s0 + s1) + (s2 + s3);
}

__global__ void k_colsum_final() {
    int i = blockIdx.x * blockDim.x + threadIdx.x;
    if (i >= BB * RR) return;
    int b = i >> 8, r = i & 255;
    float s = 0.f;
    #pragma unroll
    for (int c = 0; c < 32; c++) s += g_Spart[(((size_t)(b * 32 + c)) << 8) + r];
    g_S[i] = s;
}

// ---------------------------------------------------------------------------
// GEMM2 on mma.sync tf32 tensor cores.
// v[n,r] = sum_m x[m,n] * (u[m,r]+eps)/S[r];  mma M'=n, N'=r, K'=m.
// Block: 256 thr (8 warps), tile 128(n) x 128(r), BK=16, split-K=4 -> 256 CTAs.
// Warp tile 64(n) x 32(r): 4x4 m16n8k8 tiles per k-step, 2 k-steps per k-tile.
// SMEM rows padded to 132 words so quad-pair fragment loads are conflict-free.
// ---------------------------------------------------------------------------
#define LDP 132

__global__ __launch_bounds__(256, 2) void k_gemm2_mma(
    const float* __restrict__ x, const float* __restrict__ u)
{
    const int blk = blockIdx.x;
    const int sp  = blk & 3;
    const int rt  = (blk >> 2) & 1;
    const int nt  = (blk >> 3) & 3;
    const int b   = blk >> 5;
    const int n0 = nt << 7, r0 = rt << 7;
    const int kb = sp * 2048, ke = kb + 2048;

    __shared__ uint32_t As[16 * LDP];
    __shared__ uint32_t Bs[16 * LDP];
    __shared__ float srinv[128];

    const int t = threadIdx.x;
    const int w = t >> 5, l = t & 31;
    const int gid = l >> 2, tig = l & 3;
    const int wn = (w >> 2) << 6;     // 0 or 64
    const int wr = (w & 3) << 5;      // 0,32,64,96
    if (t < 128) srinv[t] = 1.0f / (g_S[(b << 8) + r0 + t] + EPSV);
    __syncthreads();   // srinv must be visible to ALL warps before rv load (R4 bug)

    const float* xb = x + (size_t)b * MM * NN;
    const float* ub = u + (size_t)b * MM * RR;

    float4 acc[4][4];
    #pragma unroll
    for (int i = 0; i < 4; i++)
        #pragma unroll
        for (int j = 0; j < 4; j++) acc[i][j] = make_float4(0.f, 0.f, 0.f, 0.f);

    const int kkA = t >> 5;          // 0..7
    const int cf  = (t & 31) << 2;   // 0..124
    const float4 rv = *(const float4*)&srinv[cf];   // loop-invariant

    for (int k0 = kb; k0 < ke; k0 += 16) {
        float4 a0 = *(const float4*)(xb + (size_t)(k0 + kkA) * NN + n0 + cf);
        float4 a1 = *(const float4*)(xb + (size_t)(k0 + kkA + 8) * NN + n0 + cf);
        float4 b0 = *(const float4*)(ub + (size_t)(k0 + kkA) * RR + r0 + cf);
        float4 b1 = *(const float4*)(ub + (size_t)(k0 + kkA + 8) * RR + r0 + cf);
        __syncthreads();
        {
            uint4 qa0 = { f2tf32(a0.x), f2tf32(a0.y), f2tf32(a0.z), f2tf32(a0.w) };
            uint4 qa1 = { f2tf32(a1.x), f2tf32(a1.y), f2tf32(a1.z), f2tf32(a1.w) };
            uint4 qb0 = { f2tf32((b0.x + EPSV) * rv.x), f2tf32((b0.y + EPSV) * rv.y),
                          f2tf32((b0.z + EPSV) * rv.z), f2tf32((b0.w + EPSV) * rv.w) };
            uint4 qb1 = { f2tf32((b1.x + EPSV) * rv.x), f2tf32((b1.y + EPSV) * rv.y),
                          f2tf32((b1.z + EPSV) * rv.z), f2tf32((b1.w + EPSV) * rv.w) };
            *(uint4*)&As[kkA * LDP + cf]       = qa0;
            *(uint4*)&As[(kkA + 8) * LDP + cf] = qa1;
            *(uint4*)&Bs[kkA * LDP + cf]       = qb0;
            *(uint4*)&Bs[(kkA + 8) * LDP + cf] = qb1;
        }
        __syncthreads();
        #pragma unroll
        for (int kk = 0; kk < 16; kk += 8) {
            const uint32_t* Ak = &As[(kk + tig) * LDP];
            const uint32_t* Bk = &Bs[(kk + tig) * LDP];
            uint32_t af[4][4], bf[4][2];
            #pragma unroll
            for (int i = 0; i < 4; i++) {
                int base = wn + (i << 4) + gid;
                af[i][0] = Ak[base];
                af[i][1] = Ak[base + 8];
                af[i][2] = Ak[base + 4 * LDP];
                af[i][3] = Ak[base + 4 * LDP + 8];
            }
            #pragma unroll
            for (int j = 0; j < 4; j++) {
                int base = wr + (j << 3) + gid;
                bf[j][0] = Bk[base];
                bf[j][1] = Bk[base + 4 * LDP];
            }
            #pragma unroll
            for (int i = 0; i < 4; i++)
                #pragma unroll
                for (int j = 0; j < 4; j++)
                    mma_tf32(acc[i][j], af[i][0], af[i][1], af[i][2], af[i][3],
                             bf[j][0], bf[j][1]);
        }
    }

    // epilogue: n = n0+wn+i*16+gid(+8), r = r0+wr+j*8+tig*2(+1)
    float* pbase = g_part + ((size_t)(b * 4 + sp) * NN + n0 + wn + gid) * RR + r0 + wr + (tig << 1);
    #pragma unroll
    for (int i = 0; i < 4; i++) {
        #pragma unroll
        for (int j = 0; j < 4; j++) {
            float2 lo = { acc[i][j].x, acc[i][j].y };
            float2 hi = { acc[i][j].z, acc[i][j].w };
            float* p = pbase + (size_t)(i << 4) * RR + (j << 3);
            *(float2*)p = lo;
            *(float2*)(p + (size_t)8 * RR) = hi;
        }
    }
}

__global__ void k_vred(float* __restrict__ vout) {
    int i = blockIdx.x * blockDim.x + threadIdx.x;
    int b = i >> 17;
    int nr = i & 131071;
    float s = 0.f;
    #pragma unroll
    for (int sp = 0; sp < 4; sp++)
        s += g_part[((size_t)(b * 4 + sp)) * (NN * RR) + nr];
    vout[i] = s;
}

// ---------------------------------------------------------------------------
extern "C" void kernel_launch(void* const* d_in, const int* in_sizes, int n_in,
                              void* d_out, int out_size) {
    const float* x     = (const float*)d_in[0];
    const float* alpha = (const float*)d_in[1];
    const int*   inds  = (const int*)d_in[2];
    float* u = (float*)d_out;
    float* v = u + (size_t)BB * MM * RR;

    k_v2<<<(BB * RR) / 8, 256>>>(x, inds);
    k_gemm1<<<BB * (MM / 64), 256>>>(x, alpha, inds, u);
    k_colsum_part<<<BB * 32, 256>>>(u);
    k_colsum_final<<<8, 256>>>();
    k_gemm2_mma<<<256, 256>>>(x, u);
    k_vred<<<(BB * NN * RR) / 256, 256>>>(v);
}

// round 6
// speedup vs baseline: 1.4846x; 1.0851x over previous
#include <cuda_runtime.h>
#include <cstdint>

#define BB 8
#define MM 8192
#define NN 512
#define RR 256
#define EPSV 1e-16f

// scratch (no allocations allowed)
__device__ float g_v2[BB * RR];
__device__ float g_S[BB * RR];
__device__ float g_Spart[BB * 32 * RR];
__device__ float g_part[BB * 4 * NN * RR];   // split-K partials for v

__device__ __forceinline__ uint32_t f2tf32(float f) {
    uint32_t r; asm("cvt.rna.tf32.f32 %0, %1;" : "=r"(r) : "f"(f)); return r;
}
__device__ __forceinline__ void mma_tf32(float4& d,
    uint32_t a0, uint32_t a1, uint32_t a2, uint32_t a3,
    uint32_t b0, uint32_t b1)
{
    asm volatile(
        "mma.sync.aligned.m16n8k8.row.col.f32.tf32.tf32.f32 "
        "{%0,%1,%2,%3}, {%4,%5,%6,%7}, {%8,%9}, {%0,%1,%2,%3};"
        : "+f"(d.x), "+f"(d.y), "+f"(d.z), "+f"(d.w)
        : "r"(a0), "r"(a1), "r"(a2), "r"(a3), "r"(b0), "r"(b1));
}

// ---------------------------------------------------------------------------
// v2[b][r] = sum_n x[b, inds[r], n]^2
// ---------------------------------------------------------------------------
__global__ void k_v2(const float* __restrict__ x, const int* __restrict__ inds) {
    int gw = (blockIdx.x * blockDim.x + threadIdx.x) >> 5;
    int lane = threadIdx.x & 31;
    if (gw >= BB * RR) return;
    int b = gw >> 8, r = gw & 255;
    const float* row = x + ((size_t)b * MM + inds[r]) * NN;
    float s = 0.f;
    const float4* row4 = (const float4*)row;
    #pragma unroll
    for (int i = lane; i < NN / 4; i += 32) {
        float4 v = row4[i];
        s += v.x * v.x + v.y * v.y + v.z * v.z + v.w * v.w;
    }
    #pragma unroll
    for (int o = 16; o; o >>= 1) s += __shfl_xor_sync(0xffffffffu, s, o);
    if (lane == 0) g_v2[gw] = s;
}

// ---------------------------------------------------------------------------
// GEMM1 on tensor cores (3xTF32 split) + fused softmax.
// xv = x @ V^T with x = xhi + xlo (tf32 split); d = relu(x2 - 2xv + v2);
// u = softmax(-d/alpha).
// Block: 256 thr (8 warps), tile 64(m) x 256(r full row), BK=16.
// Warp grid 2m x 4r, warp tile 32m x 64r: per k8-step 2x8 tiles x 3 terms.
// ---------------------------------------------------------------------------
#define APITCH 70
#define BPITCH 264

__global__ __launch_bounds__(256) void k_gemm1_mma(
    const float* __restrict__ x, const float* __restrict__ alpha,
    const int* __restrict__ inds, float* __restrict__ u)
{
    __shared__ uint32_t Ahi[16 * APITCH];
    __shared__ uint32_t Alo[16 * APITCH];
    __shared__ uint32_t Bhi[16 * BPITCH];
    __shared__ uint32_t Blo[16 * BPITCH];
    __shared__ float sv2[256];
    __shared__ float sx2[64];
    __shared__ int   sind[256];
    __shared__ float red[4][72];

    const int t  = threadIdx.x;
    const int b  = blockIdx.x >> 7;            // 128 m-tiles per batch
    const int m0 = (blockIdx.x & 127) << 6;
    const int w = t >> 5, l = t & 31;
    const int gid = l >> 2, tig = l & 3;
    const int wm = w >> 2;                     // 0..1
    const int wr = w & 3;                      // 0..3

    sind[t] = inds[t];
    sv2[t]  = g_v2[(b << 8) + t];
    const float aval = alpha[0];
    __syncthreads();

    const float* xb = x + (size_t)b * MM * NN;
    const int arow = t >> 2, acb = (t & 3) << 2;
    const float* aptr = xb + (size_t)(m0 + arow) * NN + acb;
    const float* bptr = xb + (size_t)sind[t] * NN;

    float4 acc[2][8];
    #pragma unroll
    for (int i = 0; i < 2; i++)
        #pragma unroll
        for (int j = 0; j < 8; j++) acc[i][j] = make_float4(0.f, 0.f, 0.f, 0.f);
    float xsq = 0.f;

    for (int k0 = 0; k0 < NN; k0 += 16) {
        float4 av = *(const float4*)(aptr + k0);
        float4 q0 = *(const float4*)(bptr + k0);
        float4 q1 = *(const float4*)(bptr + k0 + 4);
        float4 q2 = *(const float4*)(bptr + k0 + 8);
        float4 q3 = *(const float4*)(bptr + k0 + 12);
        __syncthreads();
        {
            const float* ap = &av.x;
            #pragma unroll
            for (int c = 0; c < 4; c++) {
                float vv = ap[c];
                uint32_t h = f2tf32(vv);
                Ahi[(acb + c) * APITCH + arow] = h;
                Alo[(acb + c) * APITCH + arow] = f2tf32(vv - __uint_as_float(h));
                xsq += vv * vv;
            }
            float qa[16] = { q0.x, q0.y, q0.z, q0.w, q1.x, q1.y, q1.z, q1.w,
                             q2.x, q2.y, q2.z, q2.w, q3.x, q3.y, q3.z, q3.w };
            #pragma unroll
            for (int c = 0; c < 16; c++) {
                uint32_t h = f2tf32(qa[c]);
                Bhi[c * BPITCH + t] = h;
                Blo[c * BPITCH + t] = f2tf32(qa[c] - __uint_as_float(h));
            }
        }
        __syncthreads();
        #pragma unroll
        for (int kk = 0; kk < 16; kk += 8) {
            const uint32_t* Ah = &Ahi[(kk + tig) * APITCH + (wm << 5)];
            const uint32_t* Al = &Alo[(kk + tig) * APITCH + (wm << 5)];
            const uint32_t* Bh = &Bhi[(kk + tig) * BPITCH + (wr << 6)];
            const uint32_t* Bl = &Blo[(kk + tig) * BPITCH + (wr << 6)];
            uint32_t ah[2][4], al[2][4], bb[8][2];
            #pragma unroll
            for (int i = 0; i < 2; i++) {
                int base = (i << 4) + gid;
                ah[i][0] = Ah[base];
                ah[i][1] = Ah[base + 8];
                ah[i][2] = Ah[base + 4 * APITCH];
                ah[i][3] = Ah[base + 4 * APITCH + 8];
                al[i][0] = Al[base];
                al[i][1] = Al[base + 8];
                al[i][2] = Al[base + 4 * APITCH];
                al[i][3] = Al[base + 4 * APITCH + 8];
            }
            #pragma unroll
            for (int j = 0; j < 8; j++) {
                int base = (j << 3) + gid;
                bb[j][0] = Bh[base];
                bb[j][1] = Bh[base + 4 * BPITCH];
            }
            #pragma unroll
            for (int i = 0; i < 2; i++)
                #pragma unroll
                for (int j = 0; j < 8; j++)
                    mma_tf32(acc[i][j], ah[i][0], ah[i][1], ah[i][2], ah[i][3],
                             bb[j][0], bb[j][1]);
            #pragma unroll
            for (int i = 0; i < 2; i++)
                #pragma unroll
                for (int j = 0; j < 8; j++)
                    mma_tf32(acc[i][j], al[i][0], al[i][1], al[i][2], al[i][3],
                             bb[j][0], bb[j][1]);
            #pragma unroll
            for (int j = 0; j < 8; j++) {
                int base = (j << 3) + gid;
                bb[j][0] = Bl[base];
                bb[j][1] = Bl[base + 4 * BPITCH];
            }
            #pragma unroll
            for (int i = 0; i < 2; i++)
                #pragma unroll
                for (int j = 0; j < 8; j++)
                    mma_tf32(acc[i][j], ah[i][0], ah[i][1], ah[i][2], ah[i][3],
                             bb[j][0], bb[j][1]);
        }
    }

    // finish x2 per row (lanes t, t^1, t^2, t^3 share row arow)
    xsq += __shfl_xor_sync(0xffffffffu, xsq, 1);
    xsq += __shfl_xor_sync(0xffffffffu, xsq, 2);
    if ((t & 3) == 0) sx2[arow] = xsq;
    __syncthreads();

    // d -> z = -relu(x2 - 2xv + v2)/alpha, in place
    const int rlo = (wm << 5) + gid;           // + i*16 (+8 for hi half)
    float x2v[2][2];
    #pragma unroll
    for (int i = 0; i < 2; i++) {
        x2v[i][0] = sx2[rlo + (i << 4)];
        x2v[i][1] = sx2[rlo + (i << 4) + 8];
    }
    #pragma unroll
    for (int i = 0; i < 2; i++)
        #pragma unroll
        for (int j = 0; j < 8; j++) {
            int rr = (wr << 6) + (j << 3) + (tig << 1);
            float va = sv2[rr], vb = sv2[rr + 1];
            acc[i][j].x = -fmaxf(x2v[i][0] - 2.f * acc[i][j].x + va, 0.f) / aval;
            acc[i][j].y = -fmaxf(x2v[i][0] - 2.f * acc[i][j].y + vb, 0.f) / aval;
            acc[i][j].z = -fmaxf(x2v[i][1] - 2.f * acc[i][j].z + va, 0.f) / aval;
            acc[i][j].w = -fmaxf(x2v[i][1] - 2.f * acc[i][j].w + vb, 0.f) / aval;
        }

    // per-row max across the block's 256 cols
    float mx[2][2] = { { -1e30f, -1e30f }, { -1e30f, -1e30f } };
    #pragma unroll
    for (int i = 0; i < 2; i++)
        #pragma unroll
        for (int j = 0; j < 8; j++) {
            mx[i][0] = fmaxf(mx[i][0], fmaxf(acc[i][j].x, acc[i][j].y));
            mx[i][1] = fmaxf(mx[i][1], fmaxf(acc[i][j].z, acc[i][j].w));
        }
    #pragma unroll
    for (int i = 0; i < 2; i++)
        #pragma unroll
        for (int h = 0; h < 2; h++) {
            mx[i][h] = fmaxf(mx[i][h], __shfl_xor_sync(0xffffffffu, mx[i][h], 1));
            mx[i][h] = fmaxf(mx[i][h], __shfl_xor_sync(0xffffffffu, mx[i][h], 2));
        }
    if (tig == 0) {
        #pragma unroll
        for (int i = 0; i < 2; i++)
            #pragma unroll
            for (int h = 0; h < 2; h++)
                red[wr][rlo + (i << 4) + (h << 3)] = mx[i][h];
    }
    __syncthreads();
    float rmx[2][2];
    #pragma unroll
    for (int i = 0; i < 2; i++)
        #pragma unroll
        for (int h = 0; h < 2; h++) {
            int row = rlo + (i << 4) + (h << 3);
            rmx[i][h] = fmaxf(fmaxf(red[0][row], red[1][row]),
                              fmaxf(red[2][row], red[3][row]));
        }

    // exponentiate + row sums
    float sm[2][2] = { { 0.f, 0.f }, { 0.f, 0.f } };
    #pragma unroll
    for (int i = 0; i < 2; i++)
        #pragma unroll
        for (int j = 0; j < 8; j++) {
            acc[i][j].x = __expf(acc[i][j].x - rmx[i][0]);
            acc[i][j].y = __expf(acc[i][j].y - rmx[i][0]);
            acc[i][j].z = __expf(acc[i][j].z - rmx[i][1]);
            acc[i][j].w = __expf(acc[i][j].w - rmx[i][1]);
            sm[i][0] += acc[i][j].x + acc[i][j].y;
            sm[i][1] += acc[i][j].z + acc[i][j].w;
        }
    #pragma unroll
    for (int i = 0; i < 2; i++)
        #pragma unroll
        for (int h = 0; h < 2; h++) {
            sm[i][h] += __shfl_xor_sync(0xffffffffu, sm[i][h], 1);
            sm[i][h] += __shfl_xor_sync(0xffffffffu, sm[i][h], 2);
        }
    __syncthreads();   // red reuse
    if (tig == 0) {
        #pragma unroll
        for (int i = 0; i < 2; i++)
            #pragma unroll
            for (int h = 0; h < 2; h++)
                red[wr][rlo + (i << 4) + (h << 3)] = sm[i][h];
    }
    __syncthreads();
    float inv[2][2];
    #pragma unroll
    for (int i = 0; i < 2; i++)
        #pragma unroll
        for (int h = 0; h < 2; h++) {
            int row = rlo + (i << 4) + (h << 3);
            inv[i][h] = 1.0f / (red[0][row] + red[1][row] + red[2][row] + red[3][row]);
        }

    // write u
    float* ub = u + ((size_t)b * MM + m0) * RR;
    #pragma unroll
    for (int i = 0; i < 2; i++) {
        int row = rlo + (i << 4);
        #pragma unroll
        for (int j = 0; j < 8; j++) {
            int col = (wr << 6) + (j << 3) + (tig << 1);
            float2 lo = { acc[i][j].x * inv[i][0], acc[i][j].y * inv[i][0] };
            float2 hi = { acc[i][j].z * inv[i][1], acc[i][j].w * inv[i][1] };
            *(float2*)(ub + (size_t)row * RR + col) = lo;
            *(float2*)(ub + (size_t)(row + 8) * RR + col) = hi;
        }
    }
}

// ---------------------------------------------------------------------------
// Column sums of u (two deterministic passes)
// ---------------------------------------------------------------------------
__global__ void k_colsum_part(const float* __restrict__ u) {
    int b = blockIdx.x >> 5, chunk = blockIdx.x & 31;
    int r = threadIdx.x;
    const float* p = u + ((size_t)b * MM + (size_t)chunk * 256) * RR + r;
    float s0 = 0.f, s1 = 0.f, s2 = 0.f, s3 = 0.f;
    for (int m = 0; m < 256; m += 4) {
        s0 += p[(size_t)(m + 0) * RR];
        s1 += p[(size_t)(m + 1) * RR];
        s2 += p[(size_t)(m + 2) * RR];
        s3 += p[(size_t)(m + 3) * RR];
    }
    g_Spart[((size_t)blockIdx.x << 8) + r] = (s0 + s1) + (s2 + s3);
}

__global__ void k_colsum_final() {
    int i = blockIdx.x * blockDim.x + threadIdx.x;
    if (i >= BB * RR) return;
    int b = i >> 8, r = i & 255;
    float s = 0.f;
    #pragma unroll
    for (int c = 0; c < 32; c++) s += g_Spart[(((size_t)(b * 32 + c)) << 8) + r];
    g_S[i] = s;
}

// ---------------------------------------------------------------------------
// GEMM2 on mma.sync tf32 (unchanged from R5, proven)
// ---------------------------------------------------------------------------
#define LDP 132

__global__ __launch_bounds__(256, 2) void k_gemm2_mma(
    const float* __restrict__ x, const float* __restrict__ u)
{
    const int blk = blockIdx.x;
    const int sp  = blk & 3;
    const int rt  = (blk >> 2) & 1;
    const int nt  = (blk >> 3) & 3;
    const int b   = blk >> 5;
    const int n0 = nt << 7, r0 = rt << 7;
    const int kb = sp * 2048, ke = kb + 2048;

    __shared__ uint32_t As[16 * LDP];
    __shared__ uint32_t Bs[16 * LDP];
    __shared__ float srinv[128];

    const int t = threadIdx.x;
    const int w = t >> 5, l = t & 31;
    const int gid = l >> 2, tig = l & 3;
    const int wn = (w >> 2) << 6;
    const int wr = (w & 3) << 5;
    if (t < 128) srinv[t] = 1.0f / (g_S[(b << 8) + r0 + t] + EPSV);
    __syncthreads();

    const float* xb = x + (size_t)b * MM * NN;
    const float* ub = u + (size_t)b * MM * RR;

    float4 acc[4][4];
    #pragma unroll
    for (int i = 0; i < 4; i++)
        #pragma unroll
        for (int j = 0; j < 4; j++) acc[i][j] = make_float4(0.f, 0.f, 0.f, 0.f);

    const int kkA = t >> 5;
    const int cf  = (t & 31) << 2;
    const float4 rv = *(const float4*)&srinv[cf];

    for (int k0 = kb; k0 < ke; k0 += 16) {
        float4 a0 = *(const float4*)(xb + (size_t)(k0 + kkA) * NN + n0 + cf);
        float4 a1 = *(const float4*)(xb + (size_t)(k0 + kkA + 8) * NN + n0 + cf);
        float4 b0 = *(const float4*)(ub + (size_t)(k0 + kkA) * RR + r0 + cf);
        float4 b1 = *(const float4*)(ub + (size_t)(k0 + kkA + 8) * RR + r0 + cf);
        __syncthreads();
        {
            uint4 qa0 = { f2tf32(a0.x), f2tf32(a0.y), f2tf32(a0.z), f2tf32(a0.w) };
            uint4 qa1 = { f2tf32(a1.x), f2tf32(a1.y), f2tf32(a1.z), f2tf32(a1.w) };
            uint4 qb0 = { f2tf32((b0.x + EPSV) * rv.x), f2tf32((b0.y + EPSV) * rv.y),
                          f2tf32((b0.z + EPSV) * rv.z), f2tf32((b0.w + EPSV) * rv.w) };
            uint4 qb1 = { f2tf32((b1.x + EPSV) * rv.x), f2tf32((b1.y + EPSV) * rv.y),
                          f2tf32((b1.z + EPSV) * rv.z), f2tf32((b1.w + EPSV) * rv.w) };
            *(uint4*)&As[kkA * LDP + cf]       = qa0;
            *(uint4*)&As[(kkA + 8) * LDP + cf] = qa1;
            *(uint4*)&Bs[kkA * LDP + cf]       = qb0;
            *(uint4*)&Bs[(kkA + 8) * LDP + cf] = qb1;
        }
        __syncthreads();
        #pragma unroll
        for (int kk = 0; kk < 16; kk += 8) {
            const uint32_t* Ak = &As[(kk + tig) * LDP];
            const uint32_t* Bk = &Bs[(kk + tig) * LDP];
            uint32_t af[4][4], bf[4][2];
            #pragma unroll
            for (int i = 0; i < 4; i++) {
                int base = wn + (i << 4) + gid;
                af[i][0] = Ak[base];
                af[i][1] = Ak[base + 8];
                af[i][2] = Ak[base + 4 * LDP];
                af[i][3] = Ak[base + 4 * LDP + 8];
            }
            #pragma unroll
            for (int j = 0; j < 4; j++) {
                int base = wr + (j << 3) + gid;
                bf[j][0] = Bk[base];
                bf[j][1] = Bk[base + 4 * LDP];
            }
            #pragma unroll
            for (int i = 0; i < 4; i++)
                #pragma unroll
                for (int j = 0; j < 4; j++)
                    mma_tf32(acc[i][j], af[i][0], af[i][1], af[i][2], af[i][3],
                             bf[j][0], bf[j][1]);
        }
    }

    float* pbase = g_part + ((size_t)(b * 4 + sp) * NN + n0 + wn + gid) * RR + r0 + wr + (tig << 1);
    #pragma unroll
    for (int i = 0; i < 4; i++) {
        #pragma unroll
        for (int j = 0; j < 4; j++) {
            float2 lo = { acc[i][j].x, acc[i][j].y };
            float2 hi = { acc[i][j].z, acc[i][j].w };
            float* p = pbase + (size_t)(i << 4) * RR + (j << 3);
            *(float2*)p = lo;
            *(float2*)(p + (size_t)8 * RR) = hi;
        }
    }
}

__global__ void k_vred(float* __restrict__ vout) {
    int i = blockIdx.x * blockDim.x + threadIdx.x;
    int b = i >> 17;
    int nr = i & 131071;
    float s = 0.f;
    #pragma unroll
    for (int sp = 0; sp < 4; sp++)
        s += g_part[((size_t)(b * 4 + sp)) * (NN * RR) + nr];
    vout[i] = s;
}

// ---------------------------------------------------------------------------
extern "C" void kernel_launch(void* const* d_in, const int* in_sizes, int n_in,
                              void* d_out, int out_size) {
    const float* x     = (const float*)d_in[0];
    const float* alpha = (const float*)d_in[1];
    const int*   inds  = (const int*)d_in[2];
    float* u = (float*)d_out;
    float* v = u + (size_t)BB * MM * RR;

    k_v2<<<(BB * RR) / 8, 256>>>(x, inds);
    k_gemm1_mma<<<BB * (MM / 64), 256>>>(x, alpha, inds, u);
    k_colsum_part<<<BB * 32, 256>>>(u);
    k_colsum_final<<<8, 256>>>();
    k_gemm2_mma<<<256, 256>>>(x, u);
    k_vred<<<(BB * NN * RR) / 256, 256>>>(v);
}

// round 7
// speedup vs baseline: 1.6306x; 1.0983x over previous
#include <cuda_runtime.h>
#include <cstdint>

#define BB 8
#define MM 8192
#define NN 512
#define RR 256
#define EPSV 1e-16f

// scratch (no allocations allowed)
__device__ float g_v2[BB * RR];
__device__ float g_S[BB * RR];
__device__ float g_Spart[BB * 32 * RR];
__device__ float g_part[BB * 4 * NN * RR];       // split-K partials for v
__device__ uint32_t g_vhi[BB * NN * RR];         // VT hi tf32, [b][n][r]
__device__ uint32_t g_vlo[BB * NN * RR];         // VT lo tf32

__device__ __forceinline__ uint32_t f2tf32(float f) {
    uint32_t r; asm("cvt.rna.tf32.f32 %0, %1;" : "=r"(r) : "f"(f)); return r;
}
__device__ __forceinline__ void mma_tf32(float4& d,
    uint32_t a0, uint32_t a1, uint32_t a2, uint32_t a3,
    uint32_t b0, uint32_t b1)
{
    asm volatile(
        "mma.sync.aligned.m16n8k8.row.col.f32.tf32.tf32.f32 "
        "{%0,%1,%2,%3}, {%4,%5,%6,%7}, {%8,%9}, {%0,%1,%2,%3};"
        : "+f"(d.x), "+f"(d.y), "+f"(d.z), "+f"(d.w)
        : "r"(a0), "r"(a1), "r"(a2), "r"(a3), "r"(b0), "r"(b1));
}
__device__ __forceinline__ uint32_t smem_u32(const void* p) {
    uint32_t a;
    asm("{ .reg .u64 t; cvta.to.shared.u64 t, %1; cvt.u32.u64 %0, t; }" : "=r"(a) : "l"(p));
    return a;
}
__device__ __forceinline__ void cpa16(uint32_t dst, const void* src) {
    asm volatile("cp.async.cg.shared.global [%0], [%1], 16;" :: "r"(dst), "l"(src));
}

// ---------------------------------------------------------------------------
// v2[b][r] = sum_n x[b, inds[r], n]^2
// ---------------------------------------------------------------------------
__global__ void k_v2(const float* __restrict__ x, const int* __restrict__ inds) {
    int gw = (blockIdx.x * blockDim.x + threadIdx.x) >> 5;
    int lane = threadIdx.x & 31;
    if (gw >= BB * RR) return;
    int b = gw >> 8, r = gw & 255;
    const float* row = x + ((size_t)b * MM + inds[r]) * NN;
    float s = 0.f;
    const float4* row4 = (const float4*)row;
    #pragma unroll
    for (int i = lane; i < NN / 4; i += 32) {
        float4 v = row4[i];
        s += v.x * v.x + v.y * v.y + v.z * v.z + v.w * v.w;
    }
    #pragma unroll
    for (int o = 16; o; o >>= 1) s += __shfl_xor_sync(0xffffffffu, s, o);
    if (lane == 0) g_v2[gw] = s;
}

// ---------------------------------------------------------------------------
// Precompute VT hi/lo: g_v{hi,lo}[b][n][r] = tf32split(x[b, inds[r], n])
// grid 32 (b x 4 n-chunks), 256 thr (t = r)
// ---------------------------------------------------------------------------
__global__ void k_prep_v(const float* __restrict__ x, const int* __restrict__ inds) {
    int b  = blockIdx.x >> 2;
    int nc = (blockIdx.x & 3) << 7;
    int r  = threadIdx.x;
    const float* row = x + ((size_t)b * MM + inds[r]) * NN + nc;
    uint32_t* vh = g_vhi + ((size_t)(b * NN + nc)) * RR + r;
    uint32_t* vl = g_vlo + ((size_t)(b * NN + nc)) * RR + r;
    for (int n = 0; n < 128; n += 4) {
        float4 q = *(const float4*)(row + n);
        const float* qa = &q.x;
        #pragma unroll
        for (int c = 0; c < 4; c++) {
            float vv = qa[c];
            uint32_t h = f2tf32(vv);
            vh[(size_t)(n + c) * RR] = h;
            vl[(size_t)(n + c) * RR] = f2tf32(vv - __uint_as_float(h));
        }
    }
}

// ---------------------------------------------------------------------------
// GEMM1 on tensor cores (3xTF32) + fused softmax, cp.async double-buffered.
// Block 256 thr (8 warps), tile 64(m) x 256(r full row), BK=16.
// A: x split on the fly (registers), double-buffered in smem [k][m] pitch 70.
// B: precomputed VT hi/lo pulled via cp.async, smem [k][r] pitch 264.
// Dynamic smem word map:
//   A[buf]: buf*2240  (hi at +0, lo at +1120), 16x70 each
//   B[buf]: 4480 + buf*8448 (hi +0, lo +4224), 16x264 each
//   sv2: 21376 (256) | sx2: 21632 (64) | red: 21696 (4*72)
// ---------------------------------------------------------------------------
#define G1_SMEM_WORDS 21984
#define G1_SMEM_BYTES (G1_SMEM_WORDS * 4)

__global__ __launch_bounds__(256, 1) void k_gemm1_mma(
    const float* __restrict__ x, const float* __restrict__ alpha,
    float* __restrict__ u)
{
    extern __shared__ uint32_t smw[];
    const uint32_t smb = smem_u32(smw);

    const int t  = threadIdx.x;
    const int b  = blockIdx.x >> 7;
    const int m0 = (blockIdx.x & 127) << 6;
    const int w = t >> 5, l = t & 31;
    const int gid = l >> 2, tig = l & 3;
    const int wm = w >> 2;                     // 0..1
    const int wr = w & 3;                      // 0..3

    float* sv2p = (float*)(smw + 21376);
    float* sx2p = (float*)(smw + 21632);
    float* redp = (float*)(smw + 21696);       // [4][72]

    sv2p[t] = g_v2[(b << 8) + t];
    const float aval = alpha[0];

    const float* xb = x + (size_t)b * MM * NN;
    const int arow = t >> 2, acb = (t & 3) << 2;
    const float* aptr = xb + (size_t)(m0 + arow) * NN + acb;

    // ---- B staging via cp.async (8 x 16B per thread per buffer) ----
    const uint32_t* vsrc[2] = { g_vhi + (size_t)b * NN * RR,
                                g_vlo + (size_t)b * NN * RR };
    #define STAGE_B(buf, k0)                                                     \
        do {                                                                     \
            uint32_t bb_ = smb + (4480u + (buf) * 8448u) * 4u;                   \
            _Pragma("unroll")                                                    \
            for (int j_ = 0; j_ < 8; j_++) {                                     \
                int c_  = (j_ << 8) + t;                                         \
                int hl_ = j_ >> 2;                                               \
                int rw_ = (c_ >> 6) & 15;                                        \
                int pc_ = (c_ & 63) << 2;                                        \
                uint32_t dst_ = bb_ + (hl_ * 4224u + rw_ * 264u + pc_) * 4u;     \
                cpa16(dst_, vsrc[hl_] + ((size_t)((k0) + rw_)) * RR + pc_);      \
            }                                                                    \
        } while (0)

    float4 acc[2][8];
    #pragma unroll
    for (int i = 0; i < 2; i++)
        #pragma unroll
        for (int j = 0; j < 8; j++) acc[i][j] = make_float4(0.f, 0.f, 0.f, 0.f);
    float xsq = 0.f;

    // prologue
    STAGE_B(0, 0);
    asm volatile("cp.async.commit_group;" ::: "memory");
    float4 av = *(const float4*)(aptr);

    for (int i = 0; i < 32; i++) {
        const int buf = i & 1;
        // STS A(i) (hi/lo split in registers)
        {
            const float* ap = &av.x;
            uint32_t* Ahw = smw + buf * 2240;
            #pragma unroll
            for (int c = 0; c < 4; c++) {
                float vv = ap[c];
                uint32_t h = f2tf32(vv);
                Ahw[(acb + c) * 70 + arow]        = h;
                Ahw[1120 + (acb + c) * 70 + arow] = f2tf32(vv - __uint_as_float(h));
                xsq += vv * vv;
            }
        }
        float4 avn;
        if (i < 31) avn = *(const float4*)(aptr + (i + 1) * 16);
        asm volatile("cp.async.wait_group 0;" ::: "memory");
        __syncthreads();
        if (i < 31) {
            STAGE_B(buf ^ 1, (i + 1) * 16);
            asm volatile("cp.async.commit_group;" ::: "memory");
        }
        // MMA on buf
        #pragma unroll
        for (int kk = 0; kk < 16; kk += 8) {
            const uint32_t* Ah = smw + buf * 2240 + (kk + tig) * 70 + (wm << 5);
            const uint32_t* Al = Ah + 1120;
            const uint32_t* Bh = smw + 4480 + buf * 8448 + (kk + tig) * 264 + (wr << 6);
            const uint32_t* Bl = Bh + 4224;
            uint32_t ah[2][4], al[2][4], bb[8][2];
            #pragma unroll
            for (int i2 = 0; i2 < 2; i2++) {
                int base = (i2 << 4) + gid;
                ah[i2][0] = Ah[base];
                ah[i2][1] = Ah[base + 8];
                ah[i2][2] = Ah[base + 4 * 70];
                ah[i2][3] = Ah[base + 4 * 70 + 8];
                al[i2][0] = Al[base];
                al[i2][1] = Al[base + 8];
                al[i2][2] = Al[base + 4 * 70];
                al[i2][3] = Al[base + 4 * 70 + 8];
            }
            #pragma unroll
            for (int j = 0; j < 8; j++) {
                int base = (j << 3) + gid;
                bb[j][0] = Bh[base];
                bb[j][1] = Bh[base + 4 * 264];
            }
            #pragma unroll
            for (int i2 = 0; i2 < 2; i2++)
                #pragma unroll
                for (int j = 0; j < 8; j++)
                    mma_tf32(acc[i2][j], ah[i2][0], ah[i2][1], ah[i2][2], ah[i2][3],
                             bb[j][0], bb[j][1]);
            #pragma unroll
            for (int i2 = 0; i2 < 2; i2++)
                #pragma unroll
                for (int j = 0; j < 8; j++)
                    mma_tf32(acc[i2][j], al[i2][0], al[i2][1], al[i2][2], al[i2][3],
                             bb[j][0], bb[j][1]);
            #pragma unroll
            for (int j = 0; j < 8; j++) {
                int base = (j << 3) + gid;
                bb[j][0] = Bl[base];
                bb[j][1] = Bl[base + 4 * 264];
            }
            #pragma unroll
            for (int i2 = 0; i2 < 2; i2++)
                #pragma unroll
                for (int j = 0; j < 8; j++)
                    mma_tf32(acc[i2][j], ah[i2][0], ah[i2][1], ah[i2][2], ah[i2][3],
                             bb[j][0], bb[j][1]);
        }
        av = avn;
    }

    // x2 per row
    xsq += __shfl_xor_sync(0xffffffffu, xsq, 1);
    xsq += __shfl_xor_sync(0xffffffffu, xsq, 2);
    if ((t & 3) == 0) sx2p[arow] = xsq;
    __syncthreads();

    // z = -relu(x2 - 2xv + v2)/alpha
    const int rlo = (wm << 5) + gid;
    float x2v[2][2];
    #pragma unroll
    for (int i = 0; i < 2; i++) {
        x2v[i][0] = sx2p[rlo + (i << 4)];
        x2v[i][1] = sx2p[rlo + (i << 4) + 8];
    }
    #pragma unroll
    for (int i = 0; i < 2; i++)
        #pragma unroll
        for (int j = 0; j < 8; j++) {
            int rr = (wr << 6) + (j << 3) + (tig << 1);
            float va = sv2p[rr], vb = sv2p[rr + 1];
            acc[i][j].x = -fmaxf(x2v[i][0] - 2.f * acc[i][j].x + va, 0.f) / aval;
            acc[i][j].y = -fmaxf(x2v[i][0] - 2.f * acc[i][j].y + vb, 0.f) / aval;
            acc[i][j].z = -fmaxf(x2v[i][1] - 2.f * acc[i][j].z + va, 0.f) / aval;
            acc[i][j].w = -fmaxf(x2v[i][1] - 2.f * acc[i][j].w + vb, 0.f) / aval;
        }

    // row max across 256 cols
    float mx[2][2] = { { -1e30f, -1e30f }, { -1e30f, -1e30f } };
    #pragma unroll
    for (int i = 0; i < 2; i++)
        #pragma unroll
        for (int j = 0; j < 8; j++) {
            mx[i][0] = fmaxf(mx[i][0], fmaxf(acc[i][j].x, acc[i][j].y));
            mx[i][1] = fmaxf(mx[i][1], fmaxf(acc[i][j].z, acc[i][j].w));
        }
    #pragma unroll
    for (int i = 0; i < 2; i++)
        #pragma unroll
        for (int h = 0; h < 2; h++) {
            mx[i][h] = fmaxf(mx[i][h], __shfl_xor_sync(0xffffffffu, mx[i][h], 1));
            mx[i][h] = fmaxf(mx[i][h], __shfl_xor_sync(0xffffffffu, mx[i][h], 2));
        }
    if (tig == 0) {
        #pragma unroll
        for (int i = 0; i < 2; i++)
            #pragma unroll
            for (int h = 0; h < 2; h++)
                redp[wr * 72 + rlo + (i << 4) + (h << 3)] = mx[i][h];
    }
    __syncthreads();
    float rmx[2][2];
    #pragma unroll
    for (int i = 0; i < 2; i++)
        #pragma unroll
        for (int h = 0; h < 2; h++) {
            int row = rlo + (i << 4) + (h << 3);
            rmx[i][h] = fmaxf(fmaxf(redp[row], redp[72 + row]),
                              fmaxf(redp[144 + row], redp[216 + row]));
        }

    // exp + row sums
    float sm[2][2] = { { 0.f, 0.f }, { 0.f, 0.f } };
    #pragma unroll
    for (int i = 0; i < 2; i++)
        #pragma unroll
        for (int j = 0; j < 8; j++) {
            acc[i][j].x = __expf(acc[i][j].x - rmx[i][0]);
            acc[i][j].y = __expf(acc[i][j].y - rmx[i][0]);
            acc[i][j].z = __expf(acc[i][j].z - rmx[i][1]);
            acc[i][j].w = __expf(acc[i][j].w - rmx[i][1]);
            sm[i][0] += acc[i][j].x + acc[i][j].y;
            sm[i][1] += acc[i][j].z + acc[i][j].w;
        }
    #pragma unroll
    for (int i = 0; i < 2; i++)
        #pragma unroll
        for (int h = 0; h < 2; h++) {
            sm[i][h] += __shfl_xor_sync(0xffffffffu, sm[i][h], 1);
            sm[i][h] += __shfl_xor_sync(0xffffffffu, sm[i][h], 2);
        }
    __syncthreads();
    if (tig == 0) {
        #pragma unroll
        for (int i = 0; i < 2; i++)
            #pragma unroll
            for (int h = 0; h < 2; h++)
                redp[wr * 72 + rlo + (i << 4) + (h << 3)] = sm[i][h];
    }
    __syncthreads();
    float inv[2][2];
    #pragma unroll
    for (int i = 0; i < 2; i++)
        #pragma unroll
        for (int h = 0; h < 2; h++) {
            int row = rlo + (i << 4) + (h << 3);
            inv[i][h] = 1.0f / (redp[row] + redp[72 + row] + redp[144 + row] + redp[216 + row]);
        }

    float* ub = u + ((size_t)b * MM + m0) * RR;
    #pragma unroll
    for (int i = 0; i < 2; i++) {
        int row = rlo + (i << 4);
        #pragma unroll
        for (int j = 0; j < 8; j++) {
            int col = (wr << 6) + (j << 3) + (tig << 1);
            float2 lo = { acc[i][j].x * inv[i][0], acc[i][j].y * inv[i][0] };
            float2 hi = { acc[i][j].z * inv[i][1], acc[i][j].w * inv[i][1] };
            *(float2*)(ub + (size_t)row * RR + col) = lo;
            *(float2*)(ub + (size_t)(row + 8) * RR + col) = hi;
        }
    }
    #undef STAGE_B
}

// ---------------------------------------------------------------------------
// Column sums of u (two deterministic passes)
// ---------------------------------------------------------------------------
__global__ void k_colsum_part(const float* __restrict__ u) {
    int b = blockIdx.x >> 5, chunk = blockIdx.x & 31;
    int r = threadIdx.x;
    const float* p = u + ((size_t)b * MM + (size_t)chunk * 256) * RR + r;
    float s0 = 0.f, s1 = 0.f, s2 = 0.f, s3 = 0.f;
    for (int m = 0; m < 256; m += 4) {
        s0 += p[(size_t)(m + 0) * RR];
        s1 += p[(size_t)(m + 1) * RR];
        s2 += p[(size_t)(m + 2) * RR];
        s3 += p[(size_t)(m + 3) * RR];
    }
    g_Spart[((size_t)blockIdx.x << 8) + r] = (s0 + s1) + (s2 + s3);
}

__global__ void k_colsum_final() {
    int i = blockIdx.x * blockDim.x + threadIdx.x;
    if (i >= BB * RR) return;
    int b = i >> 8, r = i & 255;
    float s = 0.f;
    #pragma unroll
    for (int c = 0; c < 32; c++) s += g_Spart[(((size_t)(b * 32 + c)) << 8) + r];
    g_S[i] = s;
}

// ---------------------------------------------------------------------------
// GEMM2 on mma.sync tf32 (unchanged, proven)
// ---------------------------------------------------------------------------
#define LDP 132

__global__ __launch_bounds__(256, 2) void k_gemm2_mma(
    const float* __restrict__ x, const float* __restrict__ u)
{
    const int blk = blockIdx.x;
    const int sp  = blk & 3;
    const int rt  = (blk >> 2) & 1;
    const int nt  = (blk >> 3) & 3;
    const int b   = blk >> 5;
    const int n0 = nt << 7, r0 = rt << 7;
    const int kb = sp * 2048, ke = kb + 2048;

    __shared__ uint32_t As[16 * LDP];
    __shared__ uint32_t Bs[16 * LDP];
    __shared__ float srinv[128];

    const int t = threadIdx.x;
    const int w = t >> 5, l = t & 31;
    const int gid = l >> 2, tig = l & 3;
    const int wn = (w >> 2) << 6;
    const int wr = (w & 3) << 5;
    if (t < 128) srinv[t] = 1.0f / (g_S[(b << 8) + r0 + t] + EPSV);
    __syncthreads();

    const float* xb = x + (size_t)b * MM * NN;
    const float* ub = u + (size_t)b * MM * RR;

    float4 acc[4][4];
    #pragma unroll
    for (int i = 0; i < 4; i++)
        #pragma unroll
        for (int j = 0; j < 4; j++) acc[i][j] = make_float4(0.f, 0.f, 0.f, 0.f);

    const int kkA = t >> 5;
    const int cf  = (t & 31) << 2;
    const float4 rv = *(const float4*)&srinv[cf];

    for (int k0 = kb; k0 < ke; k0 += 16) {
        float4 a0 = *(const float4*)(xb + (size_t)(k0 + kkA) * NN + n0 + cf);
        float4 a1 = *(const float4*)(xb + (size_t)(k0 + kkA + 8) * NN + n0 + cf);
        float4 b0 = *(const float4*)(ub + (size_t)(k0 + kkA) * RR + r0 + cf);
        float4 b1 = *(const float4*)(ub + (size_t)(k0 + kkA + 8) * RR + r0 + cf);
        __syncthreads();
        {
            uint4 qa0 = { f2tf32(a0.x), f2tf32(a0.y), f2tf32(a0.z), f2tf32(a0.w) };
            uint4 qa1 = { f2tf32(a1.x), f2tf32(a1.y), f2tf32(a1.z), f2tf32(a1.w) };
            uint4 qb0 = { f2tf32((b0.x + EPSV) * rv.x), f2tf32((b0.y + EPSV) * rv.y),
                          f2tf32((b0.z + EPSV) * rv.z), f2tf32((b0.w + EPSV) * rv.w) };
            uint4 qb1 = { f2tf32((b1.x + EPSV) * rv.x), f2tf32((b1.y + EPSV) * rv.y),
                          f2tf32((b1.z + EPSV) * rv.z), f2tf32((b1.w + EPSV) * rv.w) };
            *(uint4*)&As[kkA * LDP + cf]       = qa0;
            *(uint4*)&As[(kkA + 8) * LDP + cf] = qa1;
            *(uint4*)&Bs[kkA * LDP + cf]       = qb0;
            *(uint4*)&Bs[(kkA + 8) * LDP + cf] = qb1;
        }
        __syncthreads();
        #pragma unroll
        for (int kk = 0; kk < 16; kk += 8) {
            const uint32_t* Ak = &As[(kk + tig) * LDP];
            const uint32_t* Bk = &Bs[(kk + tig) * LDP];
            uint32_t af[4][4], bf[4][2];
            #pragma unroll
            for (int i = 0; i < 4; i++) {
                int base = wn + (i << 4) + gid;
                af[i][0] = Ak[base];
                af[i][1] = Ak[base + 8];
                af[i][2] = Ak[base + 4 * LDP];
                af[i][3] = Ak[base + 4 * LDP + 8];
            }
            #pragma unroll
            for (int j = 0; j < 4; j++) {
                int base = wr + (j << 3) + gid;
                bf[j][0] = Bk[base];
                bf[j][1] = Bk[base + 4 * LDP];
            }
            #pragma unroll
            for (int i = 0; i < 4; i++)
                #pragma unroll
                for (int j = 0; j < 4; j++)
                    mma_tf32(acc[i][j], af[i][0], af[i][1], af[i][2], af[i][3],
                             bf[j][0], bf[j][1]);
        }
    }

    float* pbase = g_part + ((size_t)(b * 4 + sp) * NN + n0 + wn + gid) * RR + r0 + wr + (tig << 1);
    #pragma unroll
    for (int i = 0; i < 4; i++) {
        #pragma unroll
        for (int j = 0; j < 4; j++) {
            float2 lo = { acc[i][j].x, acc[i][j].y };
            float2 hi = { acc[i][j].z, acc[i][j].w };
            float* p = pbase + (size_t)(i << 4) * RR + (j << 3);
            *(float2*)p = lo;
            *(float2*)(p + (size_t)8 * RR) = hi;
        }
    }
}

__global__ void k_vred(float* __restrict__ vout) {
    int i = blockIdx.x * blockDim.x + threadIdx.x;
    int b = i >> 17;
    int nr = i & 131071;
    float s = 0.f;
    #pragma unroll
    for (int sp = 0; sp < 4; sp++)
        s += g_part[((size_t)(b * 4 + sp)) * (NN * RR) + nr];
    vout[i] = s;
}

// ---------------------------------------------------------------------------
extern "C" void kernel_launch(void* const* d_in, const int* in_sizes, int n_in,
                              void* d_out, int out_size) {
    const float* x     = (const float*)d_in[0];
    const float* alpha = (const float*)d_in[1];
    const int*   inds  = (const int*)d_in[2];
    float* u = (float*)d_out;
    float* v = u + (size_t)BB * MM * RR;

    cudaFuncSetAttribute(k_gemm1_mma, cudaFuncAttributeMaxDynamicSharedMemorySize, G1_SMEM_BYTES);

    k_v2<<<(BB * RR) / 8, 256>>>(x, inds);
    k_prep_v<<<32, 256>>>(x, inds);
    k_gemm1_mma<<<BB * (MM / 64), 256, G1_SMEM_BYTES>>>(x, alpha, u);
    k_colsum_part<<<BB * 32, 256>>>(u);
    k_colsum_final<<<8, 256>>>();
    k_gemm2_mma<<<256, 256>>>(x, u);
    k_vred<<<(BB * NN * RR) / 256, 256>>>(v);
}

// round 8
// speedup vs baseline: 1.6367x; 1.0037x over previous
#include <cuda_runtime.h>
#include <cstdint>

#define BB 8
#define MM 8192
#define NN 512
#define RR 256
#define EPSV 1e-16f

// scratch (no allocations allowed)
__device__ float g_v2[BB * RR];
__device__ float g_S[BB * RR];
__device__ float g_Spart[BB * 32 * RR];
__device__ float g_part[BB * 4 * NN * RR];       // split-K partials for v
__device__ uint32_t g_vhi[BB * NN * RR];         // VT hi tf32, [b][n][r]
__device__ uint32_t g_vlo[BB * NN * RR];         // VT lo tf32

__device__ __forceinline__ uint32_t f2tf32(float f) {
    uint32_t r; asm("cvt.rna.tf32.f32 %0, %1;" : "=r"(r) : "f"(f)); return r;
}
__device__ __forceinline__ void mma_tf32(float4& d,
    uint32_t a0, uint32_t a1, uint32_t a2, uint32_t a3,
    uint32_t b0, uint32_t b1)
{
    asm volatile(
        "mma.sync.aligned.m16n8k8.row.col.f32.tf32.tf32.f32 "
        "{%0,%1,%2,%3}, {%4,%5,%6,%7}, {%8,%9}, {%0,%1,%2,%3};"
        : "+f"(d.x), "+f"(d.y), "+f"(d.z), "+f"(d.w)
        : "r"(a0), "r"(a1), "r"(a2), "r"(a3), "r"(b0), "r"(b1));
}
__device__ __forceinline__ uint32_t smem_u32(const void* p) {
    uint32_t a;
    asm("{ .reg .u64 t; cvta.to.shared.u64 t, %1; cvt.u32.u64 %0, t; }" : "=r"(a) : "l"(p));
    return a;
}
__device__ __forceinline__ void cpa16(uint32_t dst, const void* src) {
    asm volatile("cp.async.cg.shared.global [%0], [%1], 16;" :: "r"(dst), "l"(src));
}

// ---------------------------------------------------------------------------
// v2[b][r] = sum_n x[b, inds[r], n]^2
// ---------------------------------------------------------------------------
__global__ void k_v2(const float* __restrict__ x, const int* __restrict__ inds) {
    int gw = (blockIdx.x * blockDim.x + threadIdx.x) >> 5;
    int lane = threadIdx.x & 31;
    if (gw >= BB * RR) return;
    int b = gw >> 8, r = gw & 255;
    const float* row = x + ((size_t)b * MM + inds[r]) * NN;
    float s = 0.f;
    const float4* row4 = (const float4*)row;
    #pragma unroll
    for (int i = lane; i < NN / 4; i += 32) {
        float4 v = row4[i];
        s += v.x * v.x + v.y * v.y + v.z * v.z + v.w * v.w;
    }
    #pragma unroll
    for (int o = 16; o; o >>= 1) s += __shfl_xor_sync(0xffffffffu, s, o);
    if (lane == 0) g_v2[gw] = s;
}

// ---------------------------------------------------------------------------
// Precompute VT hi/lo: g_v{hi,lo}[b][n][r] = tf32split(x[b, inds[r], n])
// grid 32 (b x 4 n-chunks), 256 thr (t = r)
// ---------------------------------------------------------------------------
__global__ void k_prep_v(const float* __restrict__ x, const int* __restrict__ inds) {
    int b  = blockIdx.x >> 2;
    int nc = (blockIdx.x & 3) << 7;
    int r  = threadIdx.x;
    const float* row = x + ((size_t)b * MM + inds[r]) * NN + nc;
    uint32_t* vh = g_vhi + ((size_t)(b * NN + nc)) * RR + r;
    uint32_t* vl = g_vlo + ((size_t)(b * NN + nc)) * RR + r;
    for (int n = 0; n < 128; n += 4) {
        float4 q = *(const float4*)(row + n);
        const float* qa = &q.x;
        #pragma unroll
        for (int c = 0; c < 4; c++) {
            float vv = qa[c];
            uint32_t h = f2tf32(vv);
            vh[(size_t)(n + c) * RR] = h;
            vl[(size_t)(n + c) * RR] = f2tf32(vv - __uint_as_float(h));
        }
    }
}

// ---------------------------------------------------------------------------
// GEMM1 on tensor cores (3xTF32) + fused softmax, cp.async double-buffered.
// Block 256 thr (8 warps), tile 64(m) x 256(r full row), BK=16.
// A: x split on the fly (registers), double-buffered in smem [k][m] pitch 70.
// B: precomputed VT hi/lo pulled via cp.async, smem [k][r] pitch 264.
// Dynamic smem word map:
//   A[buf]: buf*2240  (hi at +0, lo at +1120), 16x70 each
//   B[buf]: 4480 + buf*8448 (hi +0, lo +4224), 16x264 each
//   sv2: 21376 (256) | sx2: 21632 (64) | red: 21696 (4*72)
// ---------------------------------------------------------------------------
#define G1_SMEM_WORDS 21984
#define G1_SMEM_BYTES (G1_SMEM_WORDS * 4)

__global__ __launch_bounds__(256, 1) void k_gemm1_mma(
    const float* __restrict__ x, const float* __restrict__ alpha,
    float* __restrict__ u)
{
    extern __shared__ uint32_t smw[];
    const uint32_t smb = smem_u32(smw);

    const int t  = threadIdx.x;
    const int b  = blockIdx.x >> 7;
    const int m0 = (blockIdx.x & 127) << 6;
    const int w = t >> 5, l = t & 31;
    const int gid = l >> 2, tig = l & 3;
    const int wm = w >> 2;                     // 0..1
    const int wr = w & 3;                      // 0..3

    float* sv2p = (float*)(smw + 21376);
    float* sx2p = (float*)(smw + 21632);
    float* redp = (float*)(smw + 21696);       // [4][72]

    sv2p[t] = g_v2[(b << 8) + t];
    const float aval = alpha[0];

    const float* xb = x + (size_t)b * MM * NN;
    const int arow = t >> 2, acb = (t & 3) << 2;
    const float* aptr = xb + (size_t)(m0 + arow) * NN + acb;

    // ---- B staging via cp.async (8 x 16B per thread per buffer) ----
    const uint32_t* vsrc[2] = { g_vhi + (size_t)b * NN * RR,
                                g_vlo + (size_t)b * NN * RR };
    #define STAGE_B(buf, k0)                                                     \
        do {                                                                     \
            uint32_t bb_ = smb + (4480u + (buf) * 8448u) * 4u;                   \
            _Pragma("unroll")                                                    \
            for (int j_ = 0; j_ < 8; j_++) {                                     \
                int c_  = (j_ << 8) + t;                                         \
                int hl_ = j_ >> 2;                                               \
                int rw_ = (c_ >> 6) & 15;                                        \
                int pc_ = (c_ & 63) << 2;                                        \
                uint32_t dst_ = bb_ + (hl_ * 4224u + rw_ * 264u + pc_) * 4u;     \
                cpa16(dst_, vsrc[hl_] + ((size_t)((k0) + rw_)) * RR + pc_);      \
            }                                                                    \
        } while (0)

    float4 acc[2][8];
    #pragma unroll
    for (int i = 0; i < 2; i++)
        #pragma unroll
        for (int j = 0; j < 8; j++) acc[i][j] = make_float4(0.f, 0.f, 0.f, 0.f);
    float xsq = 0.f;

    // prologue
    STAGE_B(0, 0);
    asm volatile("cp.async.commit_group;" ::: "memory");
    float4 av = *(const float4*)(aptr);

    for (int i = 0; i < 32; i++) {
        const int buf = i & 1;
        // STS A(i) (hi/lo split in registers)
        {
            const float* ap = &av.x;
            uint32_t* Ahw = smw + buf * 2240;
            #pragma unroll
            for (int c = 0; c < 4; c++) {
                float vv = ap[c];
                uint32_t h = f2tf32(vv);
                Ahw[(acb + c) * 70 + arow]        = h;
                Ahw[1120 + (acb + c) * 70 + arow] = f2tf32(vv - __uint_as_float(h));
                xsq += vv * vv;
            }
        }
        float4 avn;
        if (i < 31) avn = *(const float4*)(aptr + (i + 1) * 16);
        asm volatile("cp.async.wait_group 0;" ::: "memory");
        __syncthreads();
        if (i < 31) {
            STAGE_B(buf ^ 1, (i + 1) * 16);
            asm volatile("cp.async.commit_group;" ::: "memory");
        }
        // MMA on buf
        #pragma unroll
        for (int kk = 0; kk < 16; kk += 8) {
            const uint32_t* Ah = smw + buf * 2240 + (kk + tig) * 70 + (wm << 5);
            const uint32_t* Al = Ah + 1120;
            const uint32_t* Bh = smw + 4480 + buf * 8448 + (kk + tig) * 264 + (wr << 6);
            const uint32_t* Bl = Bh + 4224;
            uint32_t ah[2][4], al[2][4], bb[8][2];
            #pragma unroll
            for (int i2 = 0; i2 < 2; i2++) {
                int base = (i2 << 4) + gid;
                ah[i2][0] = Ah[base];
                ah[i2][1] = Ah[base + 8];
                ah[i2][2] = Ah[base + 4 * 70];
                ah[i2][3] = Ah[base + 4 * 70 + 8];
                al[i2][0] = Al[base];
                al[i2][1] = Al[base + 8];
                al[i2][2] = Al[base + 4 * 70];
                al[i2][3] = Al[base + 4 * 70 + 8];
            }
            #pragma unroll
            for (int j = 0; j < 8; j++) {
                int base = (j << 3) + gid;
                bb[j][0] = Bh[base];
                bb[j][1] = Bh[base + 4 * 264];
            }
            #pragma unroll
            for (int i2 = 0; i2 < 2; i2++)
                #pragma unroll
                for (int j = 0; j < 8; j++)
                    mma_tf32(acc[i2][j], ah[i2][0], ah[i2][1], ah[i2][2], ah[i2][3],
                             bb[j][0], bb[j][1]);
            #pragma unroll
            for (int i2 = 0; i2 < 2; i2++)
                #pragma unroll
                for (int j = 0; j < 8; j++)
                    mma_tf32(acc[i2][j], al[i2][0], al[i2][1], al[i2][2], al[i2][3],
                             bb[j][0], bb[j][1]);
            #pragma unroll
            for (int j = 0; j < 8; j++) {
                int base = (j << 3) + gid;
                bb[j][0] = Bl[base];
                bb[j][1] = Bl[base + 4 * 264];
            }
            #pragma unroll
            for (int i2 = 0; i2 < 2; i2++)
                #pragma unroll
                for (int j = 0; j < 8; j++)
                    mma_tf32(acc[i2][j], ah[i2][0], ah[i2][1], ah[i2][2], ah[i2][3],
                             bb[j][0], bb[j][1]);
        }
        av = avn;
    }

    // x2 per row
    xsq += __shfl_xor_sync(0xffffffffu, xsq, 1);
    xsq += __shfl_xor_sync(0xffffffffu, xsq, 2);
    if ((t & 3) == 0) sx2p[arow] = xsq;
    __syncthreads();

    // z = -relu(x2 - 2xv + v2)/alpha
    const int rlo = (wm << 5) + gid;
    float x2v[2][2];
    #pragma unroll
    for (int i = 0; i < 2; i++) {
        x2v[i][0] = sx2p[rlo + (i << 4)];
        x2v[i][1] = sx2p[rlo + (i << 4) + 8];
    }
    #pragma unroll
    for (int i = 0; i < 2; i++)
        #pragma unroll
        for (int j = 0; j < 8; j++) {
            int rr = (wr << 6) + (j << 3) + (tig << 1);
            float va = sv2p[rr], vb = sv2p[rr + 1];
            acc[i][j].x = -fmaxf(x2v[i][0] - 2.f * acc[i][j].x + va, 0.f) / aval;
            acc[i][j].y = -fmaxf(x2v[i][0] - 2.f * acc[i][j].y + vb, 0.f) / aval;
            acc[i][j].z = -fmaxf(x2v[i][1] - 2.f * acc[i][j].z + va, 0.f) / aval;
            acc[i][j].w = -fmaxf(x2v[i][1] - 2.f * acc[i][j].w + vb, 0.f) / aval;
        }

    // row max across 256 cols
    float mx[2][2] = { { -1e30f, -1e30f }, { -1e30f, -1e30f } };
    #pragma unroll
    for (int i = 0; i < 2; i++)
        #pragma unroll
        for (int j = 0; j < 8; j++) {
            mx[i][0] = fmaxf(mx[i][0], fmaxf(acc[i][j].x, acc[i][j].y));
            mx[i][1] = fmaxf(mx[i][1], fmaxf(acc[i][j].z, acc[i][j].w));
        }
    #pragma unroll
    for (int i = 0; i < 2; i++)
        #pragma unroll
        for (int h = 0; h < 2; h++) {
            mx[i][h] = fmaxf(mx[i][h], __shfl_xor_sync(0xffffffffu, mx[i][h], 1));
            mx[i][h] = fmaxf(mx[i][h], __shfl_xor_sync(0xffffffffu, mx[i][h], 2));
        }
    if (tig == 0) {
        #pragma unroll
        for (int i = 0; i < 2; i++)
            #pragma unroll
            for (int h = 0; h < 2; h++)
                redp[wr * 72 + rlo + (i << 4) + (h << 3)] = mx[i][h];
    }
    __syncthreads();
    float rmx[2][2];
    #pragma unroll
    for (int i = 0; i < 2; i++)
        #pragma unroll
        for (int h = 0; h < 2; h++) {
            int row = rlo + (i << 4) + (h << 3);
            rmx[i][h] = fmaxf(fmaxf(redp[row], redp[72 + row]),
                              fmaxf(redp[144 + row], redp[216 + row]));
        }

    // exp + row sums
    float sm[2][2] = { { 0.f, 0.f }, { 0.f, 0.f } };
    #pragma unroll
    for (int i = 0; i < 2; i++)
        #pragma unroll
        for (int j = 0; j < 8; j++) {
            acc[i][j].x = __expf(acc[i][j].x - rmx[i][0]);
            acc[i][j].y = __expf(acc[i][j].y - rmx[i][0]);
            acc[i][j].z = __expf(acc[i][j].z - rmx[i][1]);
            acc[i][j].w = __expf(acc[i][j].w - rmx[i][1]);
            sm[i][0] += acc[i][j].x + acc[i][j].y;
            sm[i][1] += acc[i][j].z + acc[i][j].w;
        }
    #pragma unroll
    for (int i = 0; i < 2; i++)
        #pragma unroll
        for (int h = 0; h < 2; h++) {
            sm[i][h] += __shfl_xor_sync(0xffffffffu, sm[i][h], 1);
            sm[i][h] += __shfl_xor_sync(0xffffffffu, sm[i][h], 2);
        }
    __syncthreads();
    if (tig == 0) {
        #pragma unroll
        for (int i = 0; i < 2; i++)
            #pragma unroll
            for (int h = 0; h < 2; h++)
                redp[wr * 72 + rlo + (i << 4) + (h << 3)] = sm[i][h];
    }
    __syncthreads();
    float inv[2][2];
    #pragma unroll
    for (int i = 0; i < 2; i++)
        #pragma unroll
        for (int h = 0; h < 2; h++) {
            int row = rlo + (i << 4) + (h << 3);
            inv[i][h] = 1.0f / (redp[row] + redp[72 + row] + redp[144 + row] + redp[216 + row]);
        }

    float* ub = u + ((size_t)b * MM + m0) * RR;
    #pragma unroll
    for (int i = 0; i < 2; i++) {
        int row = rlo + (i << 4);
        #pragma unroll
        for (int j = 0; j < 8; j++) {
            int col = (wr << 6) + (j << 3) + (tig << 1);
            float2 lo = { acc[i][j].x * inv[i][0], acc[i][j].y * inv[i][0] };
            float2 hi = { acc[i][j].z * inv[i][1], acc[i][j].w * inv[i][1] };
            *(float2*)(ub + (size_t)row * RR + col) = lo;
            *(float2*)(ub + (size_t)(row + 8) * RR + col) = hi;
        }
    }
    #undef STAGE_B
}

// ---------------------------------------------------------------------------
// Column sums of u (two deterministic passes)
// ---------------------------------------------------------------------------
__global__ void k_colsum_part(const float* __restrict__ u) {
    int b = blockIdx.x >> 5, chunk = blockIdx.x & 31;
    int r = threadIdx.x;
    const float* p = u + ((size_t)b * MM + (size_t)chunk * 256) * RR + r;
    float s0 = 0.f, s1 = 0.f, s2 = 0.f, s3 = 0.f;
    for (int m = 0; m < 256; m += 4) {
        s0 += p[(size_t)(m + 0) * RR];
        s1 += p[(size_t)(m + 1) * RR];
        s2 += p[(size_t)(m + 2) * RR];
        s3 += p[(size_t)(m + 3) * RR];
    }
    g_Spart[((size_t)blockIdx.x << 8) + r] = (s0 + s1) + (s2 + s3);
}

__global__ void k_colsum_final() {
    int i = blockIdx.x * blockDim.x + threadIdx.x;
    if (i >= BB * RR) return;
    int b = i >> 8, r = i & 255;
    float s = 0.f;
    #pragma unroll
    for (int c = 0; c < 32; c++) s += g_Spart[(((size_t)(b * 32 + c)) << 8) + r];
    g_S[i] = s;
}

// ---------------------------------------------------------------------------
// GEMM2 on mma.sync tf32 (unchanged, proven)
// ---------------------------------------------------------------------------
#define LDP 132

__global__ __launch_bounds__(256, 2) void k_gemm2_mma(
    const float* __restrict__ x, const float* __restrict__ u)
{
    const int blk = blockIdx.x;
    const int sp  = blk & 3;
    const int rt  = (blk >> 2) & 1;
    const int nt  = (blk >> 3) & 3;
    const int b   = blk >> 5;
    const int n0 = nt << 7, r0 = rt << 7;
    const int kb = sp * 2048, ke = kb + 2048;

    __shared__ uint32_t As[16 * LDP];
    __shared__ uint32_t Bs[16 * LDP];
    __shared__ float srinv[128];

    const int t = threadIdx.x;
    const int w = t >> 5, l = t & 31;
    const int gid = l >> 2, tig = l & 3;
    const int wn = (w >> 2) << 6;
    const int wr = (w & 3) << 5;
    if (t < 128) srinv[t] = 1.0f / (g_S[(b << 8) + r0 + t] + EPSV);
    __syncthreads();

    const float* xb = x + (size_t)b * MM * NN;
    const float* ub = u + (size_t)b * MM * RR;

    float4 acc[4][4];
    #pragma unroll
    for (int i = 0; i < 4; i++)
        #pragma unroll
        for (int j = 0; j < 4; j++) acc[i][j] = make_float4(0.f, 0.f, 0.f, 0.f);

    const int kkA = t >> 5;
    const int cf  = (t & 31) << 2;
    const float4 rv = *(const float4*)&srinv[cf];

    for (int k0 = kb; k0 < ke; k0 += 16) {
        float4 a0 = *(const float4*)(xb + (size_t)(k0 + kkA) * NN + n0 + cf);
        float4 a1 = *(const float4*)(xb + (size_t)(k0 + kkA + 8) * NN + n0 + cf);
        float4 b0 = *(const float4*)(ub + (size_t)(k0 + kkA) * RR + r0 + cf);
        float4 b1 = *(const float4*)(ub + (size_t)(k0 + kkA + 8) * RR + r0 + cf);
        __syncthreads();
        {
            uint4 qa0 = { f2tf32(a0.x), f2tf32(a0.y), f2tf32(a0.z), f2tf32(a0.w) };
            uint4 qa1 = { f2tf32(a1.x), f2tf32(a1.y), f2tf32(a1.z), f2tf32(a1.w) };
            uint4 qb0 = { f2tf32((b0.x + EPSV) * rv.x), f2tf32((b0.y + EPSV) * rv.y),
                          f2tf32((b0.z + EPSV) * rv.z), f2tf32((b0.w + EPSV) * rv.w) };
            uint4 qb1 = { f2tf32((b1.x + EPSV) * rv.x), f2tf32((b1.y + EPSV) * rv.y),
                          f2tf32((b1.z + EPSV) * rv.z), f2tf32((b1.w + EPSV) * rv.w) };
            *(uint4*)&As[kkA * LDP + cf]       = qa0;
            *(uint4*)&As[(kkA + 8) * LDP + cf] = qa1;
            *(uint4*)&Bs[kkA * LDP + cf]       = qb0;
            *(uint4*)&Bs[(kkA + 8) * LDP + cf] = qb1;
        }
        __syncthreads();
        #pragma unroll
        for (int kk = 0; kk < 16; kk += 8) {
            const uint32_t* Ak = &As[(kk + tig) * LDP];
            const uint32_t* Bk = &Bs[(kk + tig) * LDP];
            uint32_t af[4][4], bf[4][2];
            #pragma unroll
            for (int i = 0; i < 4; i++) {
                int base = wn + (i << 4) + gid;
                af[i][0] = Ak[base];
                af[i][1] = Ak[base + 8];
                af[i][2] = Ak[base + 4 * LDP];
                af[i][3] = Ak[base + 4 * LDP + 8];
            }
            #pragma unroll
            for (int j = 0; j < 4; j++) {
                int base = wr + (j << 3) + gid;
                bf[j][0] = Bk[base];
                bf[j][1] = Bk[base + 4 * LDP];
            }
            #pragma unroll
            for (int i = 0; i < 4; i++)
                #pragma unroll
                for (int j = 0; j < 4; j++)
                    mma_tf32(acc[i][j], af[i][0], af[i][1], af[i][2], af[i][3],
                             bf[j][0], bf[j][1]);
        }
    }

    float* pbase = g_part + ((size_t)(b * 4 + sp) * NN + n0 + wn + gid) * RR + r0 + wr + (tig << 1);
    #pragma unroll
    for (int i = 0; i < 4; i++) {
        #pragma unroll
        for (int j = 0; j < 4; j++) {
            float2 lo = { acc[i][j].x, acc[i][j].y };
            float2 hi = { acc[i][j].z, acc[i][j].w };
            float* p = pbase + (size_t)(i << 4) * RR + (j << 3);
            *(float2*)p = lo;
            *(float2*)(p + (size_t)8 * RR) = hi;
        }
    }
}

__global__ void k_vred(float* __restrict__ vout) {
    int i = blockIdx.x * blockDim.x + threadIdx.x;
    int b = i >> 17;
    int nr = i & 131071;
    float s = 0.f;
    #pragma unroll
    for (int sp = 0; sp < 4; sp++)
        s += g_part[((size_t)(b * 4 + sp)) * (NN * RR) + nr];
    vout[i] = s;
}

// ---------------------------------------------------------------------------
extern "C" void kernel_launch(void* const* d_in, const int* in_sizes, int n_in,
                              void* d_out, int out_size) {
    const float* x     = (const float*)d_in[0];
    const float* alpha = (const float*)d_in[1];
    const int*   inds  = (const int*)d_in[2];
    float* u = (float*)d_out;
    float* v = u + (size_t)BB * MM * RR;

    cudaFuncSetAttribute(k_gemm1_mma, cudaFuncAttributeMaxDynamicSharedMemorySize, G1_SMEM_BYTES);

    k_v2<<<(BB * RR) / 8, 256>>>(x, inds);
    k_prep_v<<<32, 256>>>(x, inds);
    k_gemm1_mma<<<BB * (MM / 64), 256, G1_SMEM_BYTES>>>(x, alpha, u);
    k_colsum_part<<<BB * 32, 256>>>(u);
    k_colsum_final<<<8, 256>>>();
    k_gemm2_mma<<<256, 256>>>(x, u);
    k_vred<<<(BB * NN * RR) / 256, 256>>>(v);
}

// round 9
// speedup vs baseline: 1.6368x; 1.0001x over previous
#include <cuda_runtime.h>
#include <cstdint>

#define BB 8
#define MM 8192
#define NN 512
#define RR 256
#define EPSV 1e-16f

// scratch (no allocations allowed)
__device__ float g_v2[BB * RR];
__device__ float g_S[BB * RR];
__device__ float g_Spart[BB * 32 * RR];
__device__ float g_part[BB * 4 * NN * RR];       // split-K partials for v
__device__ uint32_t g_vhi[BB * NN * RR];         // VT hi tf32, [b][n][r]
__device__ uint32_t g_vlo[BB * NN * RR];         // VT lo tf32

__device__ __forceinline__ uint32_t f2tf32(float f) {
    uint32_t r; asm("cvt.rna.tf32.f32 %0, %1;" : "=r"(r) : "f"(f)); return r;
}
__device__ __forceinline__ void mma_tf32(float4& d,
    uint32_t a0, uint32_t a1, uint32_t a2, uint32_t a3,
    uint32_t b0, uint32_t b1)
{
    asm volatile(
        "mma.sync.aligned.m16n8k8.row.col.f32.tf32.tf32.f32 "
        "{%0,%1,%2,%3}, {%4,%5,%6,%7}, {%8,%9}, {%0,%1,%2,%3};"
        : "+f"(d.x), "+f"(d.y), "+f"(d.z), "+f"(d.w)
        : "r"(a0), "r"(a1), "r"(a2), "r"(a3), "r"(b0), "r"(b1));
}
__device__ __forceinline__ uint32_t smem_u32(const void* p) {
    uint32_t a;
    asm("{ .reg .u64 t; cvta.to.shared.u64 t, %1; cvt.u32.u64 %0, t; }" : "=r"(a) : "l"(p));
    return a;
}
__device__ __forceinline__ void cpa16(uint32_t dst, const void* src) {
    asm volatile("cp.async.cg.shared.global [%0], [%1], 16;" :: "r"(dst), "l"(src));
}

// ---------------------------------------------------------------------------
// v2[b][r] = sum_n x[b, inds[r], n]^2
// ---------------------------------------------------------------------------
__global__ void k_v2(const float* __restrict__ x, const int* __restrict__ inds) {
    int gw = (blockIdx.x * blockDim.x + threadIdx.x) >> 5;
    int lane = threadIdx.x & 31;
    if (gw >= BB * RR) return;
    int b = gw >> 8, r = gw & 255;
    const float* row = x + ((size_t)b * MM + inds[r]) * NN;
    float s = 0.f;
    const float4* row4 = (const float4*)row;
    #pragma unroll
    for (int i = lane; i < NN / 4; i += 32) {
        float4 v = row4[i];
        s += v.x * v.x + v.y * v.y + v.z * v.z + v.w * v.w;
    }
    #pragma unroll
    for (int o = 16; o; o >>= 1) s += __shfl_xor_sync(0xffffffffu, s, o);
    if (lane == 0) g_v2[gw] = s;
}

// ---------------------------------------------------------------------------
// Precompute VT hi/lo: g_v{hi,lo}[b][n][r] = tf32split(x[b, inds[r], n])
// grid 32 (b x 4 n-chunks), 256 thr (t = r)
// ---------------------------------------------------------------------------
__global__ void k_prep_v(const float* __restrict__ x, const int* __restrict__ inds) {
    int b  = blockIdx.x >> 2;
    int nc = (blockIdx.x & 3) << 7;
    int r  = threadIdx.x;
    const float* row = x + ((size_t)b * MM + inds[r]) * NN + nc;
    uint32_t* vh = g_vhi + ((size_t)(b * NN + nc)) * RR + r;
    uint32_t* vl = g_vlo + ((size_t)(b * NN + nc)) * RR + r;
    for (int n = 0; n < 128; n += 4) {
        float4 q = *(const float4*)(row + n);
        const float* qa = &q.x;
        #pragma unroll
        for (int c = 0; c < 4; c++) {
            float vv = qa[c];
            uint32_t h = f2tf32(vv);
            vh[(size_t)(n + c) * RR] = h;
            vl[(size_t)(n + c) * RR] = f2tf32(vv - __uint_as_float(h));
        }
    }
}

// ---------------------------------------------------------------------------
// GEMM1 on tensor cores (3xTF32) + fused softmax, cp.async double-buffered.
// Block 256 thr (8 warps), tile 64(m) x 256(r full row), BK=16.
// A: x split on the fly (registers), double-buffered in smem [k][m] pitch 70.
// B: precomputed VT hi/lo pulled via cp.async, smem [k][r] pitch 264.
// Dynamic smem word map:
//   A[buf]: buf*2240  (hi at +0, lo at +1120), 16x70 each
//   B[buf]: 4480 + buf*8448 (hi +0, lo +4224), 16x264 each
//   sv2: 21376 (256) | sx2: 21632 (64) | red: 21696 (4*72)
// ---------------------------------------------------------------------------
#define G1_SMEM_WORDS 21984
#define G1_SMEM_BYTES (G1_SMEM_WORDS * 4)

__global__ __launch_bounds__(256, 1) void k_gemm1_mma(
    const float* __restrict__ x, const float* __restrict__ alpha,
    float* __restrict__ u)
{
    extern __shared__ uint32_t smw[];
    const uint32_t smb = smem_u32(smw);

    const int t  = threadIdx.x;
    const int b  = blockIdx.x >> 7;
    const int m0 = (blockIdx.x & 127) << 6;
    const int w = t >> 5, l = t & 31;
    const int gid = l >> 2, tig = l & 3;
    const int wm = w >> 2;                     // 0..1
    const int wr = w & 3;                      // 0..3

    float* sv2p = (float*)(smw + 21376);
    float* sx2p = (float*)(smw + 21632);
    float* redp = (float*)(smw + 21696);       // [4][72]

    sv2p[t] = g_v2[(b << 8) + t];
    const float aval = alpha[0];

    const float* xb = x + (size_t)b * MM * NN;
    const int arow = t >> 2, acb = (t & 3) << 2;
    const float* aptr = xb + (size_t)(m0 + arow) * NN + acb;

    // ---- B staging via cp.async (8 x 16B per thread per buffer) ----
    const uint32_t* vsrc[2] = { g_vhi + (size_t)b * NN * RR,
                                g_vlo + (size_t)b * NN * RR };
    #define STAGE_B(buf, k0)                                                     \
        do {                                                                     \
            uint32_t bb_ = smb + (4480u + (buf) * 8448u) * 4u;                   \
            _Pragma("unroll")                                                    \
            for (int j_ = 0; j_ < 8; j_++) {                                     \
                int c_  = (j_ << 8) + t;                                         \
                int hl_ = j_ >> 2;                                               \
                int rw_ = (c_ >> 6) & 15;                                        \
                int pc_ = (c_ & 63) << 2;                                        \
                uint32_t dst_ = bb_ + (hl_ * 4224u + rw_ * 264u + pc_) * 4u;     \
                cpa16(dst_, vsrc[hl_] + ((size_t)((k0) + rw_)) * RR + pc_);      \
            }                                                                    \
        } while (0)

    float4 acc[2][8];
    #pragma unroll
    for (int i = 0; i < 2; i++)
        #pragma unroll
        for (int j = 0; j < 8; j++) acc[i][j] = make_float4(0.f, 0.f, 0.f, 0.f);
    float xsq = 0.f;

    // prologue
    STAGE_B(0, 0);
    asm volatile("cp.async.commit_group;" ::: "memory");
    float4 av = *(const float4*)(aptr);

    for (int i = 0; i < 32; i++) {
        const int buf = i & 1;
        // STS A(i) (hi/lo split in registers)
        {
            const float* ap = &av.x;
            uint32_t* Ahw = smw + buf * 2240;
            #pragma unroll
            for (int c = 0; c < 4; c++) {
                float vv = ap[c];
                uint32_t h = f2tf32(vv);
                Ahw[(acb + c) * 70 + arow]        = h;
                Ahw[1120 + (acb + c) * 70 + arow] = f2tf32(vv - __uint_as_float(h));
                xsq += vv * vv;
            }
        }
        float4 avn;
        if (i < 31) avn = *(const float4*)(aptr + (i + 1) * 16);
        asm volatile("cp.async.wait_group 0;" ::: "memory");
        __syncthreads();
        if (i < 31) {
            STAGE_B(buf ^ 1, (i + 1) * 16);
            asm volatile("cp.async.commit_group;" ::: "memory");
        }
        // MMA on buf
        #pragma unroll
        for (int kk = 0; kk < 16; kk += 8) {
            const uint32_t* Ah = smw + buf * 2240 + (kk + tig) * 70 + (wm << 5);
            const uint32_t* Al = Ah + 1120;
            const uint32_t* Bh = smw + 4480 + buf * 8448 + (kk + tig) * 264 + (wr << 6);
            const uint32_t* Bl = Bh + 4224;
            uint32_t ah[2][4], al[2][4], bb[8][2];
            #pragma unroll
            for (int i2 = 0; i2 < 2; i2++) {
                int base = (i2 << 4) + gid;
                ah[i2][0] = Ah[base];
                ah[i2][1] = Ah[base + 8];
                ah[i2][2] = Ah[base + 4 * 70];
                ah[i2][3] = Ah[base + 4 * 70 + 8];
                al[i2][0] = Al[base];
                al[i2][1] = Al[base + 8];
                al[i2][2] = Al[base + 4 * 70];
                al[i2][3] = Al[base + 4 * 70 + 8];
            }
            #pragma unroll
            for (int j = 0; j < 8; j++) {
                int base = (j << 3) + gid;
                bb[j][0] = Bh[base];
                bb[j][1] = Bh[base + 4 * 264];
            }
            #pragma unroll
            for (int i2 = 0; i2 < 2; i2++)
                #pragma unroll
                for (int j = 0; j < 8; j++)
                    mma_tf32(acc[i2][j], ah[i2][0], ah[i2][1], ah[i2][2], ah[i2][3],
                             bb[j][0], bb[j][1]);
            #pragma unroll
            for (int i2 = 0; i2 < 2; i2++)
                #pragma unroll
                for (int j = 0; j < 8; j++)
                    mma_tf32(acc[i2][j], al[i2][0], al[i2][1], al[i2][2], al[i2][3],
                             bb[j][0], bb[j][1]);
            #pragma unroll
            for (int j = 0; j < 8; j++) {
                int base = (j << 3) + gid;
                bb[j][0] = Bl[base];
                bb[j][1] = Bl[base + 4 * 264];
            }
            #pragma unroll
            for (int i2 = 0; i2 < 2; i2++)
                #pragma unroll
                for (int j = 0; j < 8; j++)
                    mma_tf32(acc[i2][j], ah[i2][0], ah[i2][1], ah[i2][2], ah[i2][3],
                             bb[j][0], bb[j][1]);
        }
        av = avn;
    }

    // x2 per row
    xsq += __shfl_xor_sync(0xffffffffu, xsq, 1);
    xsq += __shfl_xor_sync(0xffffffffu, xsq, 2);
    if ((t & 3) == 0) sx2p[arow] = xsq;
    __syncthreads();

    // z = -relu(x2 - 2xv + v2)/alpha
    const int rlo = (wm << 5) + gid;
    float x2v[2][2];
    #pragma unroll
    for (int i = 0; i < 2; i++) {
        x2v[i][0] = sx2p[rlo + (i << 4)];
        x2v[i][1] = sx2p[rlo + (i << 4) + 8];
    }
    #pragma unroll
    for (int i = 0; i < 2; i++)
        #pragma unroll
        for (int j = 0; j < 8; j++) {
            int rr = (wr << 6) + (j << 3) + (tig << 1);
            float va = sv2p[rr], vb = sv2p[rr + 1];
            acc[i][j].x = -fmaxf(x2v[i][0] - 2.f * acc[i][j].x + va, 0.f) / aval;
            acc[i][j].y = -fmaxf(x2v[i][0] - 2.f * acc[i][j].y + vb, 0.f) / aval;
            acc[i][j].z = -fmaxf(x2v[i][1] - 2.f * acc[i][j].z + va, 0.f) / aval;
            acc[i][j].w = -fmaxf(x2v[i][1] - 2.f * acc[i][j].w + vb, 0.f) / aval;
        }

    // row max across 256 cols
    float mx[2][2] = { { -1e30f, -1e30f }, { -1e30f, -1e30f } };
    #pragma unroll
    for (int i = 0; i < 2; i++)
        #pragma unroll
        for (int j = 0; j < 8; j++) {
            mx[i][0] = fmaxf(mx[i][0], fmaxf(acc[i][j].x, acc[i][j].y));
            mx[i][1] = fmaxf(mx[i][1], fmaxf(acc[i][j].z, acc[i][j].w));
        }
    #pragma unroll
    for (int i = 0; i < 2; i++)
        #pragma unroll
        for (int h = 0; h < 2; h++) {
            mx[i][h] = fmaxf(mx[i][h], __shfl_xor_sync(0xffffffffu, mx[i][h], 1));
            mx[i][h] = fmaxf(mx[i][h], __shfl_xor_sync(0xffffffffu, mx[i][h], 2));
        }
    if (tig == 0) {
        #pragma unroll
        for (int i = 0; i < 2; i++)
            #pragma unroll
            for (int h = 0; h < 2; h++)
                redp[wr * 72 + rlo + (i << 4) + (h << 3)] = mx[i][h];
    }
    __syncthreads();
    float rmx[2][2];
    #pragma unroll
    for (int i = 0; i < 2; i++)
        #pragma unroll
        for (int h = 0; h < 2; h++) {
            int row = rlo + (i << 4) + (h << 3);
            rmx[i][h] = fmaxf(fmaxf(redp[row], redp[72 + row]),
                              fmaxf(redp[144 + row], redp[216 + row]));
        }

    // exp + row sums
    float sm[2][2] = { { 0.f, 0.f }, { 0.f, 0.f } };
    #pragma unroll
    for (int i = 0; i < 2; i++)
        #pragma unroll
        for (int j = 0; j < 8; j++) {
            acc[i][j].x = __expf(acc[i][j].x - rmx[i][0]);
            acc[i][j].y = __expf(acc[i][j].y - rmx[i][0]);
            acc[i][j].z = __expf(acc[i][j].z - rmx[i][1]);
            acc[i][j].w = __expf(acc[i][j].w - rmx[i][1]);
            sm[i][0] += acc[i][j].x + acc[i][j].y;
            sm[i][1] += acc[i][j].z + acc[i][j].w;
        }
    #pragma unroll
    for (int i = 0; i < 2; i++)
        #pragma unroll
        for (int h = 0; h < 2; h++) {
            sm[i][h] += __shfl_xor_sync(0xffffffffu, sm[i][h], 1);
            sm[i][h] += __shfl_xor_sync(0xffffffffu, sm[i][h], 2);
        }
    __syncthreads();
    if (tig == 0) {
        #pragma unroll
        for (int i = 0; i < 2; i++)
            #pragma unroll
            for (int h = 0; h < 2; h++)
                redp[wr * 72 + rlo + (i << 4) + (h << 3)] = sm[i][h];
    }
    __syncthreads();
    float inv[2][2];
    #pragma unroll
    for (int i = 0; i < 2; i++)
        #pragma unroll
        for (int h = 0; h < 2; h++) {
            int row = rlo + (i << 4) + (h << 3);
            inv[i][h] = 1.0f / (redp[row] + redp[72 + row] + redp[144 + row] + redp[216 + row]);
        }

    float* ub = u + ((size_t)b * MM + m0) * RR;
    #pragma unroll
    for (int i = 0; i < 2; i++) {
        int row = rlo + (i << 4);
        #pragma unroll
        for (int j = 0; j < 8; j++) {
            int col = (wr << 6) + (j << 3) + (tig << 1);
            float2 lo = { acc[i][j].x * inv[i][0], acc[i][j].y * inv[i][0] };
            float2 hi = { acc[i][j].z * inv[i][1], acc[i][j].w * inv[i][1] };
            *(float2*)(ub + (size_t)row * RR + col) = lo;
            *(float2*)(ub + (size_t)(row + 8) * RR + col) = hi;
        }
    }
    #undef STAGE_B
}

// ---------------------------------------------------------------------------
// Column sums of u (two deterministic passes)
// ---------------------------------------------------------------------------
__global__ void k_colsum_part(const float* __restrict__ u) {
    int b = blockIdx.x >> 5, chunk = blockIdx.x & 31;
    int r = threadIdx.x;
    const float* p = u + ((size_t)b * MM + (size_t)chunk * 256) * RR + r;
    float s0 = 0.f, s1 = 0.f, s2 = 0.f, s3 = 0.f;
    for (int m = 0; m < 256; m += 4) {
        s0 += p[(size_t)(m + 0) * RR];
        s1 += p[(size_t)(m + 1) * RR];
        s2 += p[(size_t)(m + 2) * RR];
        s3 += p[(size_t)(m + 3) * RR];
    }
    g_Spart[((size_t)blockIdx.x << 8) + r] = (s0 + s1) + (s2 + s3);
}

__global__ void k_colsum_final() {
    int i = blockIdx.x * blockDim.x + threadIdx.x;
    if (i >= BB * RR) return;
    int b = i >> 8, r = i & 255;
    float s = 0.f;
    #pragma unroll
    for (int c = 0; c < 32; c++) s += g_Spart[(((size_t)(b * 32 + c)) << 8) + r];
    g_S[i] = s;
}

// ---------------------------------------------------------------------------
// GEMM2 on mma.sync tf32 (unchanged, proven)
// ---------------------------------------------------------------------------
#define LDP 132

__global__ __launch_bounds__(256, 2) void k_gemm2_mma(
    const float* __restrict__ x, const float* __restrict__ u)
{
    const int blk = blockIdx.x;
    const int sp  = blk & 3;
    const int rt  = (blk >> 2) & 1;
    const int nt  = (blk >> 3) & 3;
    const int b   = blk >> 5;
    const int n0 = nt << 7, r0 = rt << 7;
    const int kb = sp * 2048, ke = kb + 2048;

    __shared__ uint32_t As[16 * LDP];
    __shared__ uint32_t Bs[16 * LDP];
    __shared__ float srinv[128];

    const int t = threadIdx.x;
    const int w = t >> 5, l = t & 31;
    const int gid = l >> 2, tig = l & 3;
    const int wn = (w >> 2) << 6;
    const int wr = (w & 3) << 5;
    if (t < 128) srinv[t] = 1.0f / (g_S[(b << 8) + r0 + t] + EPSV);
    __syncthreads();

    const float* xb = x + (size_t)b * MM * NN;
    const float* ub = u + (size_t)b * MM * RR;

    float4 acc[4][4];
    #pragma unroll
    for (int i = 0; i < 4; i++)
        #pragma unroll
        for (int j = 0; j < 4; j++) acc[i][j] = make_float4(0.f, 0.f, 0.f, 0.f);

    const int kkA = t >> 5;
    const int cf  = (t & 31) << 2;
    const float4 rv = *(const float4*)&srinv[cf];

    for (int k0 = kb; k0 < ke; k0 += 16) {
        float4 a0 = *(const float4*)(xb + (size_t)(k0 + kkA) * NN + n0 + cf);
        float4 a1 = *(const float4*)(xb + (size_t)(k0 + kkA + 8) * NN + n0 + cf);
        float4 b0 = *(const float4*)(ub + (size_t)(k0 + kkA) * RR + r0 + cf);
        float4 b1 = *(const float4*)(ub + (size_t)(k0 + kkA + 8) * RR + r0 + cf);
        __syncthreads();
        {
            uint4 qa0 = { f2tf32(a0.x), f2tf32(a0.y), f2tf32(a0.z), f2tf32(a0.w) };
            uint4 qa1 = { f2tf32(a1.x), f2tf32(a1.y), f2tf32(a1.z), f2tf32(a1.w) };
            uint4 qb0 = { f2tf32((b0.x + EPSV) * rv.x), f2tf32((b0.y + EPSV) * rv.y),
                          f2tf32((b0.z + EPSV) * rv.z), f2tf32((b0.w + EPSV) * rv.w) };
            uint4 qb1 = { f2tf32((b1.x + EPSV) * rv.x), f2tf32((b1.y + EPSV) * rv.y),
                          f2tf32((b1.z + EPSV) * rv.z), f2tf32((b1.w + EPSV) * rv.w) };
            *(uint4*)&As[kkA * LDP + cf]       = qa0;
            *(uint4*)&As[(kkA + 8) * LDP + cf] = qa1;
            *(uint4*)&Bs[kkA * LDP + cf]       = qb0;
            *(uint4*)&Bs[(kkA + 8) * LDP + cf] = qb1;
        }
        __syncthreads();
        #pragma unroll
        for (int kk = 0; kk < 16; kk += 8) {
            const uint32_t* Ak = &As[(kk + tig) * LDP];
            const uint32_t* Bk = &Bs[(kk + tig) * LDP];
            uint32_t af[4][4], bf[4][2];
            #pragma unroll
            for (int i = 0; i < 4; i++) {
                int base = wn + (i << 4) + gid;
                af[i][0] = Ak[base];
                af[i][1] = Ak[base + 8];
                af[i][2] = Ak[base + 4 * LDP];
                af[i][3] = Ak[base + 4 * LDP + 8];
            }
            #pragma unroll
            for (int j = 0; j < 4; j++) {
                int base = wr + (j << 3) + gid;
                bf[j][0] = Bk[base];
                bf[j][1] = Bk[base + 4 * LDP];
            }
            #pragma unroll
            for (int i = 0; i < 4; i++)
                #pragma unroll
                for (int j = 0; j < 4; j++)
                    mma_tf32(acc[i][j], af[i][0], af[i][1], af[i][2], af[i][3],
                             bf[j][0], bf[j][1]);
        }
    }

    float* pbase = g_part + ((size_t)(b * 4 + sp) * NN + n0 + wn + gid) * RR + r0 + wr + (tig << 1);
    #pragma unroll
    for (int i = 0; i < 4; i++) {
        #pragma unroll
        for (int j = 0; j < 4; j++) {
            float2 lo = { acc[i][j].x, acc[i][j].y };
            float2 hi = { acc[i][j].z, acc[i][j].w };
            float* p = pbase + (size_t)(i << 4) * RR + (j << 3);
            *(float2*)p = lo;
            *(float2*)(p + (size_t)8 * RR) = hi;
        }
    }
}

__global__ void k_vred(float* __restrict__ vout) {
    int i = blockIdx.x * blockDim.x + threadIdx.x;
    int b = i >> 17;
    int nr = i & 131071;
    float s = 0.f;
    #pragma unroll
    for (int sp = 0; sp < 4; sp++)
        s += g_part[((size_t)(b * 4 + sp)) * (NN * RR) + nr];
    vout[i] = s;
}

// ---------------------------------------------------------------------------
extern "C" void kernel_launch(void* const* d_in, const int* in_sizes, int n_in,
                              void* d_out, int out_size) {
    const float* x     = (const float*)d_in[0];
    const float* alpha = (const float*)d_in[1];
    const int*   inds  = (const int*)d_in[2];
    float* u = (float*)d_out;
    float* v = u + (size_t)BB * MM * RR;

    cudaFuncSetAttribute(k_gemm1_mma, cudaFuncAttributeMaxDynamicSharedMemorySize, G1_SMEM_BYTES);

    k_v2<<<(BB * RR) / 8, 256>>>(x, inds);
    k_prep_v<<<32, 256>>>(x, inds);
    k_gemm1_mma<<<BB * (MM / 64), 256, G1_SMEM_BYTES>>>(x, alpha, u);
    k_colsum_part<<<BB * 32, 256>>>(u);
    k_colsum_final<<<8, 256>>>();
    k_gemm2_mma<<<256, 256>>>(x, u);
    k_vred<<<(BB * NN * RR) / 256, 256>>>(v);
}

// round 10
// speedup vs baseline: 1.7822x; 1.0889x over previous
#include <cuda_runtime.h>
#include <cstdint>

#define BB 8
#define MM 8192
#define NN 512
#define RR 256
#define EPSV 1e-16f

// scratch (no allocations allowed)
__device__ float g_v2[BB * RR];
__device__ float g_S[BB * RR];
__device__ float g_Spart[BB * 32 * RR];
__device__ float g_part[BB * 4 * NN * RR];       // split-K partials for v
__device__ uint32_t g_vhi[BB * NN * RR];         // VT hi tf32, [b][n][r]
__device__ uint32_t g_vlo[BB * NN * RR];         // VT lo tf32

__device__ __forceinline__ uint32_t f2tf32(float f) {
    uint32_t r; asm("cvt.rna.tf32.f32 %0, %1;" : "=r"(r) : "f"(f)); return r;
}
__device__ __forceinline__ void mma_tf32(float4& d,
    uint32_t a0, uint32_t a1, uint32_t a2, uint32_t a3,
    uint32_t b0, uint32_t b1)
{
    asm volatile(
        "mma.sync.aligned.m16n8k8.row.col.f32.tf32.tf32.f32 "
        "{%0,%1,%2,%3}, {%4,%5,%6,%7}, {%8,%9}, {%0,%1,%2,%3};"
        : "+f"(d.x), "+f"(d.y), "+f"(d.z), "+f"(d.w)
        : "r"(a0), "r"(a1), "r"(a2), "r"(a3), "r"(b0), "r"(b1));
}
__device__ __forceinline__ uint32_t smem_u32(const void* p) {
    uint32_t a;
    asm("{ .reg .u64 t; cvta.to.shared.u64 t, %1; cvt.u32.u64 %0, t; }" : "=r"(a) : "l"(p));
    return a;
}
__device__ __forceinline__ void cpa16(uint32_t dst, const void* src) {
    asm volatile("cp.async.cg.shared.global [%0], [%1], 16;" :: "r"(dst), "l"(src));
}

// ---------------------------------------------------------------------------
// v2[b][r] = sum_n x[b, inds[r], n]^2
// ---------------------------------------------------------------------------
__global__ void k_v2(const float* __restrict__ x, const int* __restrict__ inds) {
    int gw = (blockIdx.x * blockDim.x + threadIdx.x) >> 5;
    int lane = threadIdx.x & 31;
    if (gw >= BB * RR) return;
    int b = gw >> 8, r = gw & 255;
    const float* row = x + ((size_t)b * MM + inds[r]) * NN;
    float s = 0.f;
    const float4* row4 = (const float4*)row;
    #pragma unroll
    for (int i = lane; i < NN / 4; i += 32) {
        float4 v = row4[i];
        s += v.x * v.x + v.y * v.y + v.z * v.z + v.w * v.w;
    }
    #pragma unroll
    for (int o = 16; o; o >>= 1) s += __shfl_xor_sync(0xffffffffu, s, o);
    if (lane == 0) g_v2[gw] = s;
}

// ---------------------------------------------------------------------------
// Precompute VT hi/lo: g_v{hi,lo}[b][n][r] = tf32split(x[b, inds[r], n])
// ---------------------------------------------------------------------------
__global__ void k_prep_v(const float* __restrict__ x, const int* __restrict__ inds) {
    int b  = blockIdx.x >> 2;
    int nc = (blockIdx.x & 3) << 7;
    int r  = threadIdx.x;
    const float* row = x + ((size_t)b * MM + inds[r]) * NN + nc;
    uint32_t* vh = g_vhi + ((size_t)(b * NN + nc)) * RR + r;
    uint32_t* vl = g_vlo + ((size_t)(b * NN + nc)) * RR + r;
    for (int n = 0; n < 128; n += 4) {
        float4 q = *(const float4*)(row + n);
        const float* qa = &q.x;
        #pragma unroll
        for (int c = 0; c < 4; c++) {
            float vv = qa[c];
            uint32_t h = f2tf32(vv);
            vh[(size_t)(n + c) * RR] = h;
            vl[(size_t)(n + c) * RR] = f2tf32(vv - __uint_as_float(h));
        }
    }
}

// ---------------------------------------------------------------------------
// GEMM1 on tensor cores (3xTF32) + fused softmax, cp.async double-buffered.
// Block 256 thr (8 warps), tile 64(m) x 256(r full row), BK=16, 2 CTAs/SM.
// ---------------------------------------------------------------------------
#define G1_SMEM_WORDS 21984
#define G1_SMEM_BYTES (G1_SMEM_WORDS * 4)

__global__ __launch_bounds__(256, 2) void k_gemm1_mma(
    const float* __restrict__ x, const float* __restrict__ alpha,
    float* __restrict__ u)
{
    extern __shared__ uint32_t smw[];
    const uint32_t smb = smem_u32(smw);

    const int t  = threadIdx.x;
    const int b  = blockIdx.x >> 7;
    const int m0 = (blockIdx.x & 127) << 6;
    const int w = t >> 5, l = t & 31;
    const int gid = l >> 2, tig = l & 3;
    const int wm = w >> 2;                     // 0..1
    const int wr = w & 3;                      // 0..3

    float* sv2p = (float*)(smw + 21376);
    float* sx2p = (float*)(smw + 21632);
    float* redp = (float*)(smw + 21696);       // [4][72]

    sv2p[t] = g_v2[(b << 8) + t];
    const float aval = alpha[0];

    const float* xb = x + (size_t)b * MM * NN;
    const int arow = t >> 2, acb = (t & 3) << 2;
    const float* aptr = xb + (size_t)(m0 + arow) * NN + acb;

    const uint32_t* vsrc[2] = { g_vhi + (size_t)b * NN * RR,
                                g_vlo + (size_t)b * NN * RR };
    #define STAGE_B(buf, k0)                                                     \
        do {                                                                     \
            uint32_t bb_ = smb + (4480u + (buf) * 8448u) * 4u;                   \
            _Pragma("unroll")                                                    \
            for (int j_ = 0; j_ < 8; j_++) {                                     \
                int c_  = (j_ << 8) + t;                                         \
                int hl_ = j_ >> 2;                                               \
                int rw_ = (c_ >> 6) & 15;                                        \
                int pc_ = (c_ & 63) << 2;                                        \
                uint32_t dst_ = bb_ + (hl_ * 4224u + rw_ * 264u + pc_) * 4u;     \
                cpa16(dst_, vsrc[hl_] + ((size_t)((k0) + rw_)) * RR + pc_);      \
            }                                                                    \
        } while (0)

    float4 acc[2][8];
    #pragma unroll
    for (int i = 0; i < 2; i++)
        #pragma unroll
        for (int j = 0; j < 8; j++) acc[i][j] = make_float4(0.f, 0.f, 0.f, 0.f);
    float xsq = 0.f;

    STAGE_B(0, 0);
    asm volatile("cp.async.commit_group;" ::: "memory");
    float4 av = *(const float4*)(aptr);

    for (int i = 0; i < 32; i++) {
        const int buf = i & 1;
        {
            const float* ap = &av.x;
            uint32_t* Ahw = smw + buf * 2240;
            #pragma unroll
            for (int c = 0; c < 4; c++) {
                float vv = ap[c];
                uint32_t h = f2tf32(vv);
                Ahw[(acb + c) * 70 + arow]        = h;
                Ahw[1120 + (acb + c) * 70 + arow] = f2tf32(vv - __uint_as_float(h));
                xsq += vv * vv;
            }
        }
        float4 avn;
        if (i < 31) avn = *(const float4*)(aptr + (i + 1) * 16);
        asm volatile("cp.async.wait_group 0;" ::: "memory");
        __syncthreads();
        if (i < 31) {
            STAGE_B(buf ^ 1, (i + 1) * 16);
            asm volatile("cp.async.commit_group;" ::: "memory");
        }
        #pragma unroll
        for (int kk = 0; kk < 16; kk += 8) {
            const uint32_t* Ah = smw + buf * 2240 + (kk + tig) * 70 + (wm << 5);
            const uint32_t* Al = Ah + 1120;
            const uint32_t* Bh = smw + 4480 + buf * 8448 + (kk + tig) * 264 + (wr << 6);
            const uint32_t* Bl = Bh + 4224;
            uint32_t ah[2][4], al[2][4], bb[8][2];
            #pragma unroll
            for (int i2 = 0; i2 < 2; i2++) {
                int base = (i2 << 4) + gid;
                ah[i2][0] = Ah[base];
                ah[i2][1] = Ah[base + 8];
                ah[i2][2] = Ah[base + 4 * 70];
                ah[i2][3] = Ah[base + 4 * 70 + 8];
                al[i2][0] = Al[base];
                al[i2][1] = Al[base + 8];
                al[i2][2] = Al[base + 4 * 70];
                al[i2][3] = Al[base + 4 * 70 + 8];
            }
            #pragma unroll
            for (int j = 0; j < 8; j++) {
                int base = (j << 3) + gid;
                bb[j][0] = Bh[base];
                bb[j][1] = Bh[base + 4 * 264];
            }
            #pragma unroll
            for (int i2 = 0; i2 < 2; i2++)
                #pragma unroll
                for (int j = 0; j < 8; j++)
                    mma_tf32(acc[i2][j], ah[i2][0], ah[i2][1], ah[i2][2], ah[i2][3],
                             bb[j][0], bb[j][1]);
            #pragma unroll
            for (int i2 = 0; i2 < 2; i2++)
                #pragma unroll
                for (int j = 0; j < 8; j++)
                    mma_tf32(acc[i2][j], al[i2][0], al[i2][1], al[i2][2], al[i2][3],
                             bb[j][0], bb[j][1]);
            #pragma unroll
            for (int j = 0; j < 8; j++) {
                int base = (j << 3) + gid;
                bb[j][0] = Bl[base];
                bb[j][1] = Bl[base + 4 * 264];
            }
            #pragma unroll
            for (int i2 = 0; i2 < 2; i2++)
                #pragma unroll
                for (int j = 0; j < 8; j++)
                    mma_tf32(acc[i2][j], ah[i2][0], ah[i2][1], ah[i2][2], ah[i2][3],
                             bb[j][0], bb[j][1]);
        }
        av = avn;
    }

    xsq += __shfl_xor_sync(0xffffffffu, xsq, 1);
    xsq += __shfl_xor_sync(0xffffffffu, xsq, 2);
    if ((t & 3) == 0) sx2p[arow] = xsq;
    __syncthreads();

    const int rlo = (wm << 5) + gid;
    float x2v[2][2];
    #pragma unroll
    for (int i = 0; i < 2; i++) {
        x2v[i][0] = sx2p[rlo + (i << 4)];
        x2v[i][1] = sx2p[rlo + (i << 4) + 8];
    }
    #pragma unroll
    for (int i = 0; i < 2; i++)
        #pragma unroll
        for (int j = 0; j < 8; j++) {
            int rr = (wr << 6) + (j << 3) + (tig << 1);
            float va = sv2p[rr], vb = sv2p[rr + 1];
            acc[i][j].x = -fmaxf(x2v[i][0] - 2.f * acc[i][j].x + va, 0.f) / aval;
            acc[i][j].y = -fmaxf(x2v[i][0] - 2.f * acc[i][j].y + vb, 0.f) / aval;
            acc[i][j].z = -fmaxf(x2v[i][1] - 2.f * acc[i][j].z + va, 0.f) / aval;
            acc[i][j].w = -fmaxf(x2v[i][1] - 2.f * acc[i][j].w + vb, 0.f) / aval;
        }

    float mx[2][2] = { { -1e30f, -1e30f }, { -1e30f, -1e30f } };
    #pragma unroll
    for (int i = 0; i < 2; i++)
        #pragma unroll
        for (int j = 0; j < 8; j++) {
            mx[i][0] = fmaxf(mx[i][0], fmaxf(acc[i][j].x, acc[i][j].y));
            mx[i][1] = fmaxf(mx[i][1], fmaxf(acc[i][j].z, acc[i][j].w));
        }
    #pragma unroll
    for (int i = 0; i < 2; i++)
        #pragma unroll
        for (int h = 0; h < 2; h++) {
            mx[i][h] = fmaxf(mx[i][h], __shfl_xor_sync(0xffffffffu, mx[i][h], 1));
            mx[i][h] = fmaxf(mx[i][h], __shfl_xor_sync(0xffffffffu, mx[i][h], 2));
        }
    if (tig == 0) {
        #pragma unroll
        for (int i = 0; i < 2; i++)
            #pragma unroll
            for (int h = 0; h < 2; h++)
                redp[wr * 72 + rlo + (i << 4) + (h << 3)] = mx[i][h];
    }
    __syncthreads();
    float rmx[2][2];
    #pragma unroll
    for (int i = 0; i < 2; i++)
        #pragma unroll
        for (int h = 0; h < 2; h++) {
            int row = rlo + (i << 4) + (h << 3);
            rmx[i][h] = fmaxf(fmaxf(redp[row], redp[72 + row]),
                              fmaxf(redp[144 + row], redp[216 + row]));
        }

    float sm[2][2] = { { 0.f, 0.f }, { 0.f, 0.f } };
    #pragma unroll
    for (int i = 0; i < 2; i++)
        #pragma unroll
        for (int j = 0; j < 8; j++) {
            acc[i][j].x = __expf(acc[i][j].x - rmx[i][0]);
            acc[i][j].y = __expf(acc[i][j].y - rmx[i][0]);
            acc[i][j].z = __expf(acc[i][j].z - rmx[i][1]);
            acc[i][j].w = __expf(acc[i][j].w - rmx[i][1]);
            sm[i][0] += acc[i][j].x + acc[i][j].y;
            sm[i][1] += acc[i][j].z + acc[i][j].w;
        }
    #pragma unroll
    for (int i = 0; i < 2; i++)
        #pragma unroll
        for (int h = 0; h < 2; h++) {
            sm[i][h] += __shfl_xor_sync(0xffffffffu, sm[i][h], 1);
            sm[i][h] += __shfl_xor_sync(0xffffffffu, sm[i][h], 2);
        }
    __syncthreads();
    if (tig == 0) {
        #pragma unroll
        for (int i = 0; i < 2; i++)
            #pragma unroll
            for (int h = 0; h < 2; h++)
                redp[wr * 72 + rlo + (i << 4) + (h << 3)] = sm[i][h];
    }
    __syncthreads();
    float inv[2][2];
    #pragma unroll
    for (int i = 0; i < 2; i++)
        #pragma unroll
        for (int h = 0; h < 2; h++) {
            int row = rlo + (i << 4) + (h << 3);
            inv[i][h] = 1.0f / (redp[row] + redp[72 + row] + redp[144 + row] + redp[216 + row]);
        }

    float* ub = u + ((size_t)b * MM + m0) * RR;
    #pragma unroll
    for (int i = 0; i < 2; i++) {
        int row = rlo + (i << 4);
        #pragma unroll
        for (int j = 0; j < 8; j++) {
            int col = (wr << 6) + (j << 3) + (tig << 1);
            float2 lo = { acc[i][j].x * inv[i][0], acc[i][j].y * inv[i][0] };
            float2 hi = { acc[i][j].z * inv[i][1], acc[i][j].w * inv[i][1] };
            *(float2*)(ub + (size_t)row * RR + col) = lo;
            *(float2*)(ub + (size_t)(row + 8) * RR + col) = hi;
        }
    }
    #undef STAGE_B
}

// ---------------------------------------------------------------------------
// Column sums of u (two deterministic passes)
// ---------------------------------------------------------------------------
__global__ void k_colsum_part(const float* __restrict__ u) {
    int b = blockIdx.x >> 5, chunk = blockIdx.x & 31;
    int r = threadIdx.x;
    const float* p = u + ((size_t)b * MM + (size_t)chunk * 256) * RR + r;
    float s0 = 0.f, s1 = 0.f, s2 = 0.f, s3 = 0.f;
    for (int m = 0; m < 256; m += 4) {
        s0 += p[(size_t)(m + 0) * RR];
        s1 += p[(size_t)(m + 1) * RR];
        s2 += p[(size_t)(m + 2) * RR];
        s3 += p[(size_t)(m + 3) * RR];
    }
    g_Spart[((size_t)blockIdx.x << 8) + r] = (s0 + s1) + (s2 + s3);
}

__global__ void k_colsum_final() {
    int i = blockIdx.x * blockDim.x + threadIdx.x;
    if (i >= BB * RR) return;
    int b = i >> 8, r = i & 255;
    float s = 0.f;
    #pragma unroll
    for (int c = 0; c < 32; c++) s += g_Spart[(((size_t)(b * 32 + c)) << 8) + r];
    g_S[i] = s;
}

// ---------------------------------------------------------------------------
// GEMM2 on mma.sync tf32. Pitch 136 (mod 32 = 8): conflict-free frag loads.
// ---------------------------------------------------------------------------
#define LDP 136

__global__ __launch_bounds__(256, 2) void k_gemm2_mma(
    const float* __restrict__ x, const float* __restrict__ u)
{
    const int blk = blockIdx.x;
    const int sp  = blk & 3;
    const int rt  = (blk >> 2) & 1;
    const int nt  = (blk >> 3) & 3;
    const int b   = blk >> 5;
    const int n0 = nt << 7, r0 = rt << 7;
    const int kb = sp * 2048, ke = kb + 2048;

    __shared__ uint32_t As[16 * LDP];
    __shared__ uint32_t Bs[16 * LDP];
    __shared__ float srinv[128];

    const int t = threadIdx.x;
    const int w = t >> 5, l = t & 31;
    const int gid = l >> 2, tig = l & 3;
    const int wn = (w >> 2) << 6;
    const int wr = (w & 3) << 5;
    if (t < 128) srinv[t] = 1.0f / (g_S[(b << 8) + r0 + t] + EPSV);
    __syncthreads();

    const float* xb = x + (size_t)b * MM * NN;
    const float* ub = u + (size_t)b * MM * RR;

    float4 acc[4][4];
    #pragma unroll
    for (int i = 0; i < 4; i++)
        #pragma unroll
        for (int j = 0; j < 4; j++) acc[i][j] = make_float4(0.f, 0.f, 0.f, 0.f);

    const int kkA = t >> 5;
    const int cf  = (t & 31) << 2;
    const float4 rv = *(const float4*)&srinv[cf];

    for (int k0 = kb; k0 < ke; k0 += 16) {
        float4 a0 = *(const float4*)(xb + (size_t)(k0 + kkA) * NN + n0 + cf);
        float4 a1 = *(const float4*)(xb + (size_t)(k0 + kkA + 8) * NN + n0 + cf);
        float4 b0 = *(const float4*)(ub + (size_t)(k0 + kkA) * RR + r0 + cf);
        float4 b1 = *(const float4*)(ub + (size_t)(k0 + kkA + 8) * RR + r0 + cf);
        __syncthreads();
        {
            uint4 qa0 = { f2tf32(a0.x), f2tf32(a0.y), f2tf32(a0.z), f2tf32(a0.w) };
            uint4 qa1 = { f2tf32(a1.x), f2tf32(a1.y), f2tf32(a1.z), f2tf32(a1.w) };
            uint4 qb0 = { f2tf32((b0.x + EPSV) * rv.x), f2tf32((b0.y + EPSV) * rv.y),
                          f2tf32((b0.z + EPSV) * rv.z), f2tf32((b0.w + EPSV) * rv.w) };
            uint4 qb1 = { f2tf32((b1.x + EPSV) * rv.x), f2tf32((b1.y + EPSV) * rv.y),
                          f2tf32((b1.z + EPSV) * rv.z), f2tf32((b1.w + EPSV) * rv.w) };
            *(uint4*)&As[kkA * LDP + cf]       = qa0;
            *(uint4*)&As[(kkA + 8) * LDP + cf] = qa1;
            *(uint4*)&Bs[kkA * LDP + cf]       = qb0;
            *(uint4*)&Bs[(kkA + 8) * LDP + cf] = qb1;
        }
        __syncthreads();
        #pragma unroll
        for (int kk = 0; kk < 16; kk += 8) {
            const uint32_t* Ak = &As[(kk + tig) * LDP];
            const uint32_t* Bk = &Bs[(kk + tig) * LDP];
            uint32_t af[4][4], bf[4][2];
            #pragma unroll
            for (int i = 0; i < 4; i++) {
                int base = wn + (i << 4) + gid;
                af[i][0] = Ak[base];
                af[i][1] = Ak[base + 8];
                af[i][2] = Ak[base + 4 * LDP];
                af[i][3] = Ak[base + 4 * LDP + 8];
            }
            #pragma unroll
            for (int j = 0; j < 4; j++) {
                int base = wr + (j << 3) + gid;
                bf[j][0] = Bk[base];
                bf[j][1] = Bk[base + 4 * LDP];
            }
            #pragma unroll
            for (int i = 0; i < 4; i++)
                #pragma unroll
                for (int j = 0; j < 4; j++)
                    mma_tf32(acc[i][j], af[i][0], af[i][1], af[i][2], af[i][3],
                             bf[j][0], bf[j][1]);
        }
    }

    float* pbase = g_part + ((size_t)(b * 4 + sp) * NN + n0 + wn + gid) * RR + r0 + wr + (tig << 1);
    #pragma unroll
    for (int i = 0; i < 4; i++) {
        #pragma unroll
        for (int j = 0; j < 4; j++) {
            float2 lo = { acc[i][j].x, acc[i][j].y };
            float2 hi = { acc[i][j].z, acc[i][j].w };
            float* p = pbase + (size_t)(i << 4) * RR + (j << 3);
            *(float2*)p = lo;
            *(float2*)(p + (size_t)8 * RR) = hi;
        }
    }
}

__global__ void k_vred(float* __restrict__ vout) {
    int i = blockIdx.x * blockDim.x + threadIdx.x;
    int b = i >> 17;
    int nr = i & 131071;
    float s = 0.f;
    #pragma unroll
    for (int sp = 0; sp < 4; sp++)
        s += g_part[((size_t)(b * 4 + sp)) * (NN * RR) + nr];
    vout[i] = s;
}

// ---------------------------------------------------------------------------
extern "C" void kernel_launch(void* const* d_in, const int* in_sizes, int n_in,
                              void* d_out, int out_size) {
    const float* x     = (const float*)d_in[0];
    const float* alpha = (const float*)d_in[1];
    const int*   inds  = (const int*)d_in[2];
    float* u = (float*)d_out;
    float* v = u + (size_t)BB * MM * RR;

    cudaFuncSetAttribute(k_gemm1_mma, cudaFuncAttributeMaxDynamicSharedMemorySize, G1_SMEM_BYTES);

    k_v2<<<(BB * RR) / 8, 256>>>(x, inds);
    k_prep_v<<<32, 256>>>(x, inds);
    k_gemm1_mma<<<BB * (MM / 64), 256, G1_SMEM_BYTES>>>(x, alpha, u);
    k_colsum_part<<<BB * 32, 256>>>(u);
    k_colsum_final<<<8, 256>>>();
    k_gemm2_mma<<<256, 256>>>(x, u);
    k_vred<<<(BB * NN * RR) / 256, 256>>>(v);
}

// round 11
// speedup vs baseline: 1.7894x; 1.0040x over previous
#include <cuda_runtime.h>
#include <cstdint>

#define BB 8
#define MM 8192
#define NN 512
#define RR 256
#define EPSV 1e-16f

// scratch (no allocations allowed)
__device__ float g_v2[BB * RR];
__device__ float g_S[BB * RR];
__device__ float g_Spart[BB * 32 * RR];
__device__ float g_part[BB * 4 * NN * RR];       // split-K partials for v
__device__ uint32_t g_vhi[BB * NN * RR];         // VT hi tf32, [b][n][r]
__device__ uint32_t g_vlo[BB * NN * RR];         // VT lo tf32

__device__ __forceinline__ uint32_t f2tf32(float f) {
    uint32_t r; asm("cvt.rna.tf32.f32 %0, %1;" : "=r"(r) : "f"(f)); return r;
}
__device__ __forceinline__ void mma_tf32(float4& d,
    uint32_t a0, uint32_t a1, uint32_t a2, uint32_t a3,
    uint32_t b0, uint32_t b1)
{
    asm volatile(
        "mma.sync.aligned.m16n8k8.row.col.f32.tf32.tf32.f32 "
        "{%0,%1,%2,%3}, {%4,%5,%6,%7}, {%8,%9}, {%0,%1,%2,%3};"
        : "+f"(d.x), "+f"(d.y), "+f"(d.z), "+f"(d.w)
        : "r"(a0), "r"(a1), "r"(a2), "r"(a3), "r"(b0), "r"(b1));
}
__device__ __forceinline__ uint32_t smem_u32(const void* p) {
    uint32_t a;
    asm("{ .reg .u64 t; cvta.to.shared.u64 t, %1; cvt.u32.u64 %0, t; }" : "=r"(a) : "l"(p));
    return a;
}
__device__ __forceinline__ void cpa16(uint32_t dst, const void* src) {
    asm volatile("cp.async.cg.shared.global [%0], [%1], 16;" :: "r"(dst), "l"(src));
}

// ---------------------------------------------------------------------------
// v2[b][r] = sum_n x[b, inds[r], n]^2
// ---------------------------------------------------------------------------
__global__ void k_v2(const float* __restrict__ x, const int* __restrict__ inds) {
    int gw = (blockIdx.x * blockDim.x + threadIdx.x) >> 5;
    int lane = threadIdx.x & 31;
    if (gw >= BB * RR) return;
    int b = gw >> 8, r = gw & 255;
    const float* row = x + ((size_t)b * MM + inds[r]) * NN;
    float s = 0.f;
    const float4* row4 = (const float4*)row;
    #pragma unroll
    for (int i = lane; i < NN / 4; i += 32) {
        float4 v = row4[i];
        s += v.x * v.x + v.y * v.y + v.z * v.z + v.w * v.w;
    }
    #pragma unroll
    for (int o = 16; o; o >>= 1) s += __shfl_xor_sync(0xffffffffu, s, o);
    if (lane == 0) g_v2[gw] = s;
}

// ---------------------------------------------------------------------------
// Precompute VT hi/lo: g_v{hi,lo}[b][n][r] = tf32split(x[b, inds[r], n])
// ---------------------------------------------------------------------------
__global__ void k_prep_v(const float* __restrict__ x, const int* __restrict__ inds) {
    int b  = blockIdx.x >> 2;
    int nc = (blockIdx.x & 3) << 7;
    int r  = threadIdx.x;
    const float* row = x + ((size_t)b * MM + inds[r]) * NN + nc;
    uint32_t* vh = g_vhi + ((size_t)(b * NN + nc)) * RR + r;
    uint32_t* vl = g_vlo + ((size_t)(b * NN + nc)) * RR + r;
    for (int n = 0; n < 128; n += 4) {
        float4 q = *(const float4*)(row + n);
        const float* qa = &q.x;
        #pragma unroll
        for (int c = 0; c < 4; c++) {
            float vv = qa[c];
            uint32_t h = f2tf32(vv);
            vh[(size_t)(n + c) * RR] = h;
            vl[(size_t)(n + c) * RR] = f2tf32(vv - __uint_as_float(h));
        }
    }
}

// ---------------------------------------------------------------------------
// GEMM1 on tensor cores (3xTF32) + fused softmax, cp.async double-buffered.
// Block 256 thr (8 warps), tile 64(m) x 256(r full row), BK=16, 2 CTAs/SM.
// ---------------------------------------------------------------------------
#define G1_SMEM_WORDS 21984
#define G1_SMEM_BYTES (G1_SMEM_WORDS * 4)

__global__ __launch_bounds__(256, 2) void k_gemm1_mma(
    const float* __restrict__ x, const float* __restrict__ alpha,
    float* __restrict__ u)
{
    extern __shared__ uint32_t smw[];
    const uint32_t smb = smem_u32(smw);

    const int t  = threadIdx.x;
    const int b  = blockIdx.x >> 7;
    const int m0 = (blockIdx.x & 127) << 6;
    const int w = t >> 5, l = t & 31;
    const int gid = l >> 2, tig = l & 3;
    const int wm = w >> 2;                     // 0..1
    const int wr = w & 3;                      // 0..3

    float* sv2p = (float*)(smw + 21376);
    float* sx2p = (float*)(smw + 21632);
    float* redp = (float*)(smw + 21696);       // [4][72]

    sv2p[t] = g_v2[(b << 8) + t];
    const float aval = alpha[0];

    const float* xb = x + (size_t)b * MM * NN;
    const int arow = t >> 2, acb = (t & 3) << 2;
    const float* aptr = xb + (size_t)(m0 + arow) * NN + acb;

    const uint32_t* vsrc[2] = { g_vhi + (size_t)b * NN * RR,
                                g_vlo + (size_t)b * NN * RR };
    #define STAGE_B(buf, k0)                                                     \
        do {                                                                     \
            uint32_t bb_ = smb + (4480u + (buf) * 8448u) * 4u;                   \
            _Pragma("unroll")                                                    \
            for (int j_ = 0; j_ < 8; j_++) {                                     \
                int c_  = (j_ << 8) + t;                                         \
                int hl_ = j_ >> 2;                                               \
                int rw_ = (c_ >> 6) & 15;                                        \
                int pc_ = (c_ & 63) << 2;                                        \
                uint32_t dst_ = bb_ + (hl_ * 4224u + rw_ * 264u + pc_) * 4u;     \
                cpa16(dst_, vsrc[hl_] + ((size_t)((k0) + rw_)) * RR + pc_);      \
            }                                                                    \
        } while (0)

    float4 acc[2][8];
    #pragma unroll
    for (int i = 0; i < 2; i++)
        #pragma unroll
        for (int j = 0; j < 8; j++) acc[i][j] = make_float4(0.f, 0.f, 0.f, 0.f);
    float xsq = 0.f;

    STAGE_B(0, 0);
    asm volatile("cp.async.commit_group;" ::: "memory");
    float4 av = *(const float4*)(aptr);

    for (int i = 0; i < 32; i++) {
        const int buf = i & 1;
        {
            const float* ap = &av.x;
            uint32_t* Ahw = smw + buf * 2240;
            #pragma unroll
            for (int c = 0; c < 4; c++) {
                float vv = ap[c];
                uint32_t h = f2tf32(vv);
                Ahw[(acb + c) * 70 + arow]        = h;
                Ahw[1120 + (acb + c) * 70 + arow] = f2tf32(vv - __uint_as_float(h));
                xsq += vv * vv;
            }
        }
        float4 avn;
        if (i < 31) avn = *(const float4*)(aptr + (i + 1) * 16);
        asm volatile("cp.async.wait_group 0;" ::: "memory");
        __syncthreads();
        if (i < 31) {
            STAGE_B(buf ^ 1, (i + 1) * 16);
            asm volatile("cp.async.commit_group;" ::: "memory");
        }
        #pragma unroll
        for (int kk = 0; kk < 16; kk += 8) {
            const uint32_t* Ah = smw + buf * 2240 + (kk + tig) * 70 + (wm << 5);
            const uint32_t* Al = Ah + 1120;
            const uint32_t* Bh = smw + 4480 + buf * 8448 + (kk + tig) * 264 + (wr << 6);
            const uint32_t* Bl = Bh + 4224;
            uint32_t ah[2][4], al[2][4], bb[8][2];
            #pragma unroll
            for (int i2 = 0; i2 < 2; i2++) {
                int base = (i2 << 4) + gid;
                ah[i2][0] = Ah[base];
                ah[i2][1] = Ah[base + 8];
                ah[i2][2] = Ah[base + 4 * 70];
                ah[i2][3] = Ah[base + 4 * 70 + 8];
                al[i2][0] = Al[base];
                al[i2][1] = Al[base + 8];
                al[i2][2] = Al[base + 4 * 70];
                al[i2][3] = Al[base + 4 * 70 + 8];
            }
            #pragma unroll
            for (int j = 0; j < 8; j++) {
                int base = (j << 3) + gid;
                bb[j][0] = Bh[base];
                bb[j][1] = Bh[base + 4 * 264];
            }
            #pragma unroll
            for (int i2 = 0; i2 < 2; i2++)
                #pragma unroll
                for (int j = 0; j < 8; j++)
                    mma_tf32(acc[i2][j], ah[i2][0], ah[i2][1], ah[i2][2], ah[i2][3],
                             bb[j][0], bb[j][1]);
            #pragma unroll
            for (int i2 = 0; i2 < 2; i2++)
                #pragma unroll
                for (int j = 0; j < 8; j++)
                    mma_tf32(acc[i2][j], al[i2][0], al[i2][1], al[i2][2], al[i2][3],
                             bb[j][0], bb[j][1]);
            #pragma unroll
            for (int j = 0; j < 8; j++) {
                int base = (j << 3) + gid;
                bb[j][0] = Bl[base];
                bb[j][1] = Bl[base + 4 * 264];
            }
            #pragma unroll
            for (int i2 = 0; i2 < 2; i2++)
                #pragma unroll
                for (int j = 0; j < 8; j++)
                    mma_tf32(acc[i2][j], ah[i2][0], ah[i2][1], ah[i2][2], ah[i2][3],
                             bb[j][0], bb[j][1]);
        }
        av = avn;
    }

    xsq += __shfl_xor_sync(0xffffffffu, xsq, 1);
    xsq += __shfl_xor_sync(0xffffffffu, xsq, 2);
    if ((t & 3) == 0) sx2p[arow] = xsq;
    __syncthreads();

    const int rlo = (wm << 5) + gid;
    float x2v[2][2];
    #pragma unroll
    for (int i = 0; i < 2; i++) {
        x2v[i][0] = sx2p[rlo + (i << 4)];
        x2v[i][1] = sx2p[rlo + (i << 4) + 8];
    }
    #pragma unroll
    for (int i = 0; i < 2; i++)
        #pragma unroll
        for (int j = 0; j < 8; j++) {
            int rr = (wr << 6) + (j << 3) + (tig << 1);
            float va = sv2p[rr], vb = sv2p[rr + 1];
            acc[i][j].x = -fmaxf(x2v[i][0] - 2.f * acc[i][j].x + va, 0.f) / aval;
            acc[i][j].y = -fmaxf(x2v[i][0] - 2.f * acc[i][j].y + vb, 0.f) / aval;
            acc[i][j].z = -fmaxf(x2v[i][1] - 2.f * acc[i][j].z + va, 0.f) / aval;
            acc[i][j].w = -fmaxf(x2v[i][1] - 2.f * acc[i][j].w + vb, 0.f) / aval;
        }

    float mx[2][2] = { { -1e30f, -1e30f }, { -1e30f, -1e30f } };
    #pragma unroll
    for (int i = 0; i < 2; i++)
        #pragma unroll
        for (int j = 0; j < 8; j++) {
            mx[i][0] = fmaxf(mx[i][0], fmaxf(acc[i][j].x, acc[i][j].y));
            mx[i][1] = fmaxf(mx[i][1], fmaxf(acc[i][j].z, acc[i][j].w));
        }
    #pragma unroll
    for (int i = 0; i < 2; i++)
        #pragma unroll
        for (int h = 0; h < 2; h++) {
            mx[i][h] = fmaxf(mx[i][h], __shfl_xor_sync(0xffffffffu, mx[i][h], 1));
            mx[i][h] = fmaxf(mx[i][h], __shfl_xor_sync(0xffffffffu, mx[i][h], 2));
        }
    if (tig == 0) {
        #pragma unroll
        for (int i = 0; i < 2; i++)
            #pragma unroll
            for (int h = 0; h < 2; h++)
                redp[wr * 72 + rlo + (i << 4) + (h << 3)] = mx[i][h];
    }
    __syncthreads();
    float rmx[2][2];
    #pragma unroll
    for (int i = 0; i < 2; i++)
        #pragma unroll
        for (int h = 0; h < 2; h++) {
            int row = rlo + (i << 4) + (h << 3);
            rmx[i][h] = fmaxf(fmaxf(redp[row], redp[72 + row]),
                              fmaxf(redp[144 + row], redp[216 + row]));
        }

    float sm[2][2] = { { 0.f, 0.f }, { 0.f, 0.f } };
    #pragma unroll
    for (int i = 0; i < 2; i++)
        #pragma unroll
        for (int j = 0; j < 8; j++) {
            acc[i][j].x = __expf(acc[i][j].x - rmx[i][0]);
            acc[i][j].y = __expf(acc[i][j].y - rmx[i][0]);
            acc[i][j].z = __expf(acc[i][j].z - rmx[i][1]);
            acc[i][j].w = __expf(acc[i][j].w - rmx[i][1]);
            sm[i][0] += acc[i][j].x + acc[i][j].y;
            sm[i][1] += acc[i][j].z + acc[i][j].w;
        }
    #pragma unroll
    for (int i = 0; i < 2; i++)
        #pragma unroll
        for (int h = 0; h < 2; h++) {
            sm[i][h] += __shfl_xor_sync(0xffffffffu, sm[i][h], 1);
            sm[i][h] += __shfl_xor_sync(0xffffffffu, sm[i][h], 2);
        }
    __syncthreads();
    if (tig == 0) {
        #pragma unroll
        for (int i = 0; i < 2; i++)
            #pragma unroll
            for (int h = 0; h < 2; h++)
                redp[wr * 72 + rlo + (i << 4) + (h << 3)] = sm[i][h];
    }
    __syncthreads();
    float inv[2][2];
    #pragma unroll
    for (int i = 0; i < 2; i++)
        #pragma unroll
        for (int h = 0; h < 2; h++) {
            int row = rlo + (i << 4) + (h << 3);
            inv[i][h] = 1.0f / (redp[row] + redp[72 + row] + redp[144 + row] + redp[216 + row]);
        }

    float* ub = u + ((size_t)b * MM + m0) * RR;
    #pragma unroll
    for (int i = 0; i < 2; i++) {
        int row = rlo + (i << 4);
        #pragma unroll
        for (int j = 0; j < 8; j++) {
            int col = (wr << 6) + (j << 3) + (tig << 1);
            float2 lo = { acc[i][j].x * inv[i][0], acc[i][j].y * inv[i][0] };
            float2 hi = { acc[i][j].z * inv[i][1], acc[i][j].w * inv[i][1] };
            *(float2*)(ub + (size_t)row * RR + col) = lo;
            *(float2*)(ub + (size_t)(row + 8) * RR + col) = hi;
        }
    }
    #undef STAGE_B
}

// ---------------------------------------------------------------------------
// Column sums of u (two deterministic passes)
// ---------------------------------------------------------------------------
__global__ void k_colsum_part(const float* __restrict__ u) {
    int b = blockIdx.x >> 5, chunk = blockIdx.x & 31;
    int r = threadIdx.x;
    const float* p = u + ((size_t)b * MM + (size_t)chunk * 256) * RR + r;
    float s0 = 0.f, s1 = 0.f, s2 = 0.f, s3 = 0.f;
    for (int m = 0; m < 256; m += 4) {
        s0 += p[(size_t)(m + 0) * RR];
        s1 += p[(size_t)(m + 1) * RR];
        s2 += p[(size_t)(m + 2) * RR];
        s3 += p[(size_t)(m + 3) * RR];
    }
    g_Spart[((size_t)blockIdx.x << 8) + r] = (s0 + s1) + (s2 + s3);
}

__global__ void k_colsum_final() {
    int i = blockIdx.x * blockDim.x + threadIdx.x;
    if (i >= BB * RR) return;
    int b = i >> 8, r = i & 255;
    float s = 0.f;
    #pragma unroll
    for (int c = 0; c < 32; c++) s += g_Spart[(((size_t)(b * 32 + c)) << 8) + r];
    g_S[i] = s;
}

// ---------------------------------------------------------------------------
// GEMM2 on mma.sync tf32. Pitch 136 (mod 32 = 8): conflict-free frag loads.
// ---------------------------------------------------------------------------
#define LDP 136

__global__ __launch_bounds__(256, 2) void k_gemm2_mma(
    const float* __restrict__ x, const float* __restrict__ u)
{
    const int blk = blockIdx.x;
    const int sp  = blk & 3;
    const int rt  = (blk >> 2) & 1;
    const int nt  = (blk >> 3) & 3;
    const int b   = blk >> 5;
    const int n0 = nt << 7, r0 = rt << 7;
    const int kb = sp * 2048, ke = kb + 2048;

    __shared__ uint32_t As[16 * LDP];
    __shared__ uint32_t Bs[16 * LDP];
    __shared__ float srinv[128];

    const int t = threadIdx.x;
    const int w = t >> 5, l = t & 31;
    const int gid = l >> 2, tig = l & 3;
    const int wn = (w >> 2) << 6;
    const int wr = (w & 3) << 5;
    if (t < 128) srinv[t] = 1.0f / (g_S[(b << 8) + r0 + t] + EPSV);
    __syncthreads();

    const float* xb = x + (size_t)b * MM * NN;
    const float* ub = u + (size_t)b * MM * RR;

    float4 acc[4][4];
    #pragma unroll
    for (int i = 0; i < 4; i++)
        #pragma unroll
        for (int j = 0; j < 4; j++) acc[i][j] = make_float4(0.f, 0.f, 0.f, 0.f);

    const int kkA = t >> 5;
    const int cf  = (t & 31) << 2;
    const float4 rv = *(const float4*)&srinv[cf];

    for (int k0 = kb; k0 < ke; k0 += 16) {
        float4 a0 = *(const float4*)(xb + (size_t)(k0 + kkA) * NN + n0 + cf);
        float4 a1 = *(const float4*)(xb + (size_t)(k0 + kkA + 8) * NN + n0 + cf);
        float4 b0 = *(const float4*)(ub + (size_t)(k0 + kkA) * RR + r0 + cf);
        float4 b1 = *(const float4*)(ub + (size_t)(k0 + kkA + 8) * RR + r0 + cf);
        __syncthreads();
        {
            uint4 qa0 = { f2tf32(a0.x), f2tf32(a0.y), f2tf32(a0.z), f2tf32(a0.w) };
            uint4 qa1 = { f2tf32(a1.x), f2tf32(a1.y), f2tf32(a1.z), f2tf32(a1.w) };
            uint4 qb0 = { f2tf32((b0.x + EPSV) * rv.x), f2tf32((b0.y + EPSV) * rv.y),
                          f2tf32((b0.z + EPSV) * rv.z), f2tf32((b0.w + EPSV) * rv.w) };
            uint4 qb1 = { f2tf32((b1.x + EPSV) * rv.x), f2tf32((b1.y + EPSV) * rv.y),
                          f2tf32((b1.z + EPSV) * rv.z), f2tf32((b1.w + EPSV) * rv.w) };
            *(uint4*)&As[kkA * LDP + cf]       = qa0;
            *(uint4*)&As[(kkA + 8) * LDP + cf] = qa1;
            *(uint4*)&Bs[kkA * LDP + cf]       = qb0;
            *(uint4*)&Bs[(kkA + 8) * LDP + cf] = qb1;
        }
        __syncthreads();
        #pragma unroll
        for (int kk = 0; kk < 16; kk += 8) {
            const uint32_t* Ak = &As[(kk + tig) * LDP];
            const uint32_t* Bk = &Bs[(kk + tig) * LDP];
            uint32_t af[4][4], bf[4][2];
            #pragma unroll
            for (int i = 0; i < 4; i++) {
                int base = wn + (i << 4) + gid;
                af[i][0] = Ak[base];
                af[i][1] = Ak[base + 8];
                af[i][2] = Ak[base + 4 * LDP];
                af[i][3] = Ak[base + 4 * LDP + 8];
            }
            #pragma unroll
            for (int j = 0; j < 4; j++) {
                int base = wr + (j << 3) + gid;
                bf[j][0] = Bk[base];
                bf[j][1] = Bk[base + 4 * LDP];
            }
            #pragma unroll
            for (int i = 0; i < 4; i++)
                #pragma unroll
                for (int j = 0; j < 4; j++)
                    mma_tf32(acc[i][j], af[i][0], af[i][1], af[i][2], af[i][3],
                             bf[j][0], bf[j][1]);
        }
    }

    float* pbase = g_part + ((size_t)(b * 4 + sp) * NN + n0 + wn + gid) * RR + r0 + wr + (tig << 1);
    #pragma unroll
    for (int i = 0; i < 4; i++) {
        #pragma unroll
        for (int j = 0; j < 4; j++) {
            float2 lo = { acc[i][j].x, acc[i][j].y };
            float2 hi = { acc[i][j].z, acc[i][j].w };
            float* p = pbase + (size_t)(i << 4) * RR + (j << 3);
            *(float2*)p = lo;
            *(float2*)(p + (size_t)8 * RR) = hi;
        }
    }
}

__global__ void k_vred(float* __restrict__ vout) {
    int i = blockIdx.x * blockDim.x + threadIdx.x;
    int b = i >> 17;
    int nr = i & 131071;
    float s = 0.f;
    #pragma unroll
    for (int sp = 0; sp < 4; sp++)
        s += g_part[((size_t)(b * 4 + sp)) * (NN * RR) + nr];
    vout[i] = s;
}

// ---------------------------------------------------------------------------
extern "C" void kernel_launch(void* const* d_in, const int* in_sizes, int n_in,
                              void* d_out, int out_size) {
    const float* x     = (const float*)d_in[0];
    const float* alpha = (const float*)d_in[1];
    const int*   inds  = (const int*)d_in[2];
    float* u = (float*)d_out;
    float* v = u + (size_t)BB * MM * RR;

    cudaFuncSetAttribute(k_gemm1_mma, cudaFuncAttributeMaxDynamicSharedMemorySize, G1_SMEM_BYTES);

    k_v2<<<(BB * RR) / 8, 256>>>(x, inds);
    k_prep_v<<<32, 256>>>(x, inds);
    k_gemm1_mma<<<BB * (MM / 64), 256, G1_SMEM_BYTES>>>(x, alpha, u);
    k_colsum_part<<<BB * 32, 256>>>(u);
    k_colsum_final<<<8, 256>>>();
    k_gemm2_mma<<<256, 256>>>(x, u);
    k_vred<<<(BB * NN * RR) / 256, 256>>>(v);
}

// round 12
// speedup vs baseline: 1.7916x; 1.0012x over previous
#include <cuda_runtime.h>
#include <cstdint>

#define BB 8
#define MM 8192
#define NN 512
#define RR 256
#define EPSV 1e-16f

// scratch (no allocations allowed)
__device__ float g_v2[BB * RR];
__device__ float g_S[BB * RR];
__device__ float g_Spart[BB * 32 * RR];
__device__ float g_part[BB * 4 * NN * RR];       // split-K partials for v
__device__ uint32_t g_vhi[BB * NN * RR];         // VT hi tf32, [b][n][r]
__device__ uint32_t g_vlo[BB * NN * RR];         // VT lo tf32

__device__ __forceinline__ uint32_t f2tf32(float f) {
    uint32_t r; asm("cvt.rna.tf32.f32 %0, %1;" : "=r"(r) : "f"(f)); return r;
}
__device__ __forceinline__ void mma_tf32(float4& d,
    uint32_t a0, uint32_t a1, uint32_t a2, uint32_t a3,
    uint32_t b0, uint32_t b1)
{
    asm volatile(
        "mma.sync.aligned.m16n8k8.row.col.f32.tf32.tf32.f32 "
        "{%0,%1,%2,%3}, {%4,%5,%6,%7}, {%8,%9}, {%0,%1,%2,%3};"
        : "+f"(d.x), "+f"(d.y), "+f"(d.z), "+f"(d.w)
        : "r"(a0), "r"(a1), "r"(a2), "r"(a3), "r"(b0), "r"(b1));
}
__device__ __forceinline__ uint32_t smem_u32(const void* p) {
    uint32_t a;
    asm("{ .reg .u64 t; cvta.to.shared.u64 t, %1; cvt.u32.u64 %0, t; }" : "=r"(a) : "l"(p));
    return a;
}
__device__ __forceinline__ void cpa16(uint32_t dst, const void* src) {
    asm volatile("cp.async.cg.shared.global [%0], [%1], 16;" :: "r"(dst), "l"(src));
}

// ---------------------------------------------------------------------------
// v2[b][r] = sum_n x[b, inds[r], n]^2
// ---------------------------------------------------------------------------
__global__ void k_v2(const float* __restrict__ x, const int* __restrict__ inds) {
    int gw = (blockIdx.x * blockDim.x + threadIdx.x) >> 5;
    int lane = threadIdx.x & 31;
    if (gw >= BB * RR) return;
    int b = gw >> 8, r = gw & 255;
    const float* row = x + ((size_t)b * MM + inds[r]) * NN;
    float s = 0.f;
    const float4* row4 = (const float4*)row;
    #pragma unroll
    for (int i = lane; i < NN / 4; i += 32) {
        float4 v = row4[i];
        s += v.x * v.x + v.y * v.y + v.z * v.z + v.w * v.w;
    }
    #pragma unroll
    for (int o = 16; o; o >>= 1) s += __shfl_xor_sync(0xffffffffu, s, o);
    if (lane == 0) g_v2[gw] = s;
}

// ---------------------------------------------------------------------------
// Precompute VT hi/lo: g_v{hi,lo}[b][n][r] = tf32split(x[b, inds[r], n])
// ---------------------------------------------------------------------------
__global__ void k_prep_v(const float* __restrict__ x, const int* __restrict__ inds) {
    int b  = blockIdx.x >> 2;
    int nc = (blockIdx.x & 3) << 7;
    int r  = threadIdx.x;
    const float* row = x + ((size_t)b * MM + inds[r]) * NN + nc;
    uint32_t* vh = g_vhi + ((size_t)(b * NN + nc)) * RR + r;
    uint32_t* vl = g_vlo + ((size_t)(b * NN + nc)) * RR + r;
    for (int n = 0; n < 128; n += 4) {
        float4 q = *(const float4*)(row + n);
        const float* qa = &q.x;
        #pragma unroll
        for (int c = 0; c < 4; c++) {
            float vv = qa[c];
            uint32_t h = f2tf32(vv);
            vh[(size_t)(n + c) * RR] = h;
            vl[(size_t)(n + c) * RR] = f2tf32(vv - __uint_as_float(h));
        }
    }
}

// ---------------------------------------------------------------------------
// GEMM1 on tensor cores (3xTF32) + fused softmax, cp.async double-buffered.
// Block 256 thr (8 warps), tile 64(m) x 256(r full row), BK=16, 2 CTAs/SM.
// ---------------------------------------------------------------------------
#define G1_SMEM_WORDS 21984
#define G1_SMEM_BYTES (G1_SMEM_WORDS * 4)

__global__ __launch_bounds__(256, 2) void k_gemm1_mma(
    const float* __restrict__ x, const float* __restrict__ alpha,
    float* __restrict__ u)
{
    extern __shared__ uint32_t smw[];
    const uint32_t smb = smem_u32(smw);

    const int t  = threadIdx.x;
    const int b  = blockIdx.x >> 7;
    const int m0 = (blockIdx.x & 127) << 6;
    const int w = t >> 5, l = t & 31;
    const int gid = l >> 2, tig = l & 3;
    const int wm = w >> 2;                     // 0..1
    const int wr = w & 3;                      // 0..3

    float* sv2p = (float*)(smw + 21376);
    float* sx2p = (float*)(smw + 21632);
    float* redp = (float*)(smw + 21696);       // [4][72]

    sv2p[t] = g_v2[(b << 8) + t];
    const float aval = alpha[0];

    const float* xb = x + (size_t)b * MM * NN;
    const int arow = t >> 2, acb = (t & 3) << 2;
    const float* aptr = xb + (size_t)(m0 + arow) * NN + acb;

    const uint32_t* vsrc[2] = { g_vhi + (size_t)b * NN * RR,
                                g_vlo + (size_t)b * NN * RR };
    #define STAGE_B(buf, k0)                                                     \
        do {                                                                     \
            uint32_t bb_ = smb + (4480u + (buf) * 8448u) * 4u;                   \
            _Pragma("unroll")                                                    \
            for (int j_ = 0; j_ < 8; j_++) {                                     \
                int c_  = (j_ << 8) + t;                                         \
                int hl_ = j_ >> 2;                                               \
                int rw_ = (c_ >> 6) & 15;                                        \
                int pc_ = (c_ & 63) << 2;                                        \
                uint32_t dst_ = bb_ + (hl_ * 4224u + rw_ * 264u + pc_) * 4u;     \
                cpa16(dst_, vsrc[hl_] + ((size_t)((k0) + rw_)) * RR + pc_);      \
            }                                                                    \
        } while (0)

    float4 acc[2][8];
    #pragma unroll
    for (int i = 0; i < 2; i++)
        #pragma unroll
        for (int j = 0; j < 8; j++) acc[i][j] = make_float4(0.f, 0.f, 0.f, 0.f);
    float xsq = 0.f;

    STAGE_B(0, 0);
    asm volatile("cp.async.commit_group;" ::: "memory");
    float4 av = *(const float4*)(aptr);

    for (int i = 0; i < 32; i++) {
        const int buf = i & 1;
        {
            const float* ap = &av.x;
            uint32_t* Ahw = smw + buf * 2240;
            #pragma unroll
            for (int c = 0; c < 4; c++) {
                float vv = ap[c];
                uint32_t h = f2tf32(vv);
                Ahw[(acb + c) * 70 + arow]        = h;
                Ahw[1120 + (acb + c) * 70 + arow] = f2tf32(vv - __uint_as_float(h));
                xsq += vv * vv;
            }
        }
        float4 avn;
        if (i < 31) avn = *(const float4*)(aptr + (i + 1) * 16);
        asm volatile("cp.async.wait_group 0;" ::: "memory");
        __syncthreads();
        if (i < 31) {
            STAGE_B(buf ^ 1, (i + 1) * 16);
            asm volatile("cp.async.commit_group;" ::: "memory");
        }
        #pragma unroll
        for (int kk = 0; kk < 16; kk += 8) {
            const uint32_t* Ah = smw + buf * 2240 + (kk + tig) * 70 + (wm << 5);
            const uint32_t* Al = Ah + 1120;
            const uint32_t* Bh = smw + 4480 + buf * 8448 + (kk + tig) * 264 + (wr << 6);
            const uint32_t* Bl = Bh + 4224;
            uint32_t ah[2][4], al[2][4], bb[8][2];
            #pragma unroll
            for (int i2 = 0; i2 < 2; i2++) {
                int base = (i2 << 4) + gid;
                ah[i2][0] = Ah[base];
                ah[i2][1] = Ah[base + 8];
                ah[i2][2] = Ah[base + 4 * 70];
                ah[i2][3] = Ah[base + 4 * 70 + 8];
                al[i2][0] = Al[base];
                al[i2][1] = Al[base + 8];
                al[i2][2] = Al[base + 4 * 70];
                al[i2][3] = Al[base + 4 * 70 + 8];
            }
            #pragma unroll
            for (int j = 0; j < 8; j++) {
                int base = (j << 3) + gid;
                bb[j][0] = Bh[base];
                bb[j][1] = Bh[base + 4 * 264];
            }
            #pragma unroll
            for (int i2 = 0; i2 < 2; i2++)
                #pragma unroll
                for (int j = 0; j < 8; j++)
                    mma_tf32(acc[i2][j], ah[i2][0], ah[i2][1], ah[i2][2], ah[i2][3],
                             bb[j][0], bb[j][1]);
            #pragma unroll
            for (int i2 = 0; i2 < 2; i2++)
                #pragma unroll
                for (int j = 0; j < 8; j++)
                    mma_tf32(acc[i2][j], al[i2][0], al[i2][1], al[i2][2], al[i2][3],
                             bb[j][0], bb[j][1]);
            #pragma unroll
            for (int j = 0; j < 8; j++) {
                int base = (j << 3) + gid;
                bb[j][0] = Bl[base];
                bb[j][1] = Bl[base + 4 * 264];
            }
            #pragma unroll
            for (int i2 = 0; i2 < 2; i2++)
                #pragma unroll
                for (int j = 0; j < 8; j++)
                    mma_tf32(acc[i2][j], ah[i2][0], ah[i2][1], ah[i2][2], ah[i2][3],
                             bb[j][0], bb[j][1]);
        }
        av = avn;
    }

    xsq += __shfl_xor_sync(0xffffffffu, xsq, 1);
    xsq += __shfl_xor_sync(0xffffffffu, xsq, 2);
    if ((t & 3) == 0) sx2p[arow] = xsq;
    __syncthreads();

    const int rlo = (wm << 5) + gid;
    float x2v[2][2];
    #pragma unroll
    for (int i = 0; i < 2; i++) {
        x2v[i][0] = sx2p[rlo + (i << 4)];
        x2v[i][1] = sx2p[rlo + (i << 4) + 8];
    }
    #pragma unroll
    for (int i = 0; i < 2; i++)
        #pragma unroll
        for (int j = 0; j < 8; j++) {
            int rr = (wr << 6) + (j << 3) + (tig << 1);
            float va = sv2p[rr], vb = sv2p[rr + 1];
            acc[i][j].x = -fmaxf(x2v[i][0] - 2.f * acc[i][j].x + va, 0.f) / aval;
            acc[i][j].y = -fmaxf(x2v[i][0] - 2.f * acc[i][j].y + vb, 0.f) / aval;
            acc[i][j].z = -fmaxf(x2v[i][1] - 2.f * acc[i][j].z + va, 0.f) / aval;
            acc[i][j].w = -fmaxf(x2v[i][1] - 2.f * acc[i][j].w + vb, 0.f) / aval;
        }

    float mx[2][2] = { { -1e30f, -1e30f }, { -1e30f, -1e30f } };
    #pragma unroll
    for (int i = 0; i < 2; i++)
        #pragma unroll
        for (int j = 0; j < 8; j++) {
            mx[i][0] = fmaxf(mx[i][0], fmaxf(acc[i][j].x, acc[i][j].y));
            mx[i][1] = fmaxf(mx[i][1], fmaxf(acc[i][j].z, acc[i][j].w));
        }
    #pragma unroll
    for (int i = 0; i < 2; i++)
        #pragma unroll
        for (int h = 0; h < 2; h++) {
            mx[i][h] = fmaxf(mx[i][h], __shfl_xor_sync(0xffffffffu, mx[i][h], 1));
            mx[i][h] = fmaxf(mx[i][h], __shfl_xor_sync(0xffffffffu, mx[i][h], 2));
        }
    if (tig == 0) {
        #pragma unroll
        for (int i = 0; i < 2; i++)
            #pragma unroll
            for (int h = 0; h < 2; h++)
                redp[wr * 72 + rlo + (i << 4) + (h << 3)] = mx[i][h];
    }
    __syncthreads();
    float rmx[2][2];
    #pragma unroll
    for (int i = 0; i < 2; i++)
        #pragma unroll
        for (int h = 0; h < 2; h++) {
            int row = rlo + (i << 4) + (h << 3);
            rmx[i][h] = fmaxf(fmaxf(redp[row], redp[72 + row]),
                              fmaxf(redp[144 + row], redp[216 + row]));
        }

    float sm[2][2] = { { 0.f, 0.f }, { 0.f, 0.f } };
    #pragma unroll
    for (int i = 0; i < 2; i++)
        #pragma unroll
        for (int j = 0; j < 8; j++) {
            acc[i][j].x = __expf(acc[i][j].x - rmx[i][0]);
            acc[i][j].y = __expf(acc[i][j].y - rmx[i][0]);
            acc[i][j].z = __expf(acc[i][j].z - rmx[i][1]);
            acc[i][j].w = __expf(acc[i][j].w - rmx[i][1]);
            sm[i][0] += acc[i][j].x + acc[i][j].y;
            sm[i][1] += acc[i][j].z + acc[i][j].w;
        }
    #pragma unroll
    for (int i = 0; i < 2; i++)
        #pragma unroll
        for (int h = 0; h < 2; h++) {
            sm[i][h] += __shfl_xor_sync(0xffffffffu, sm[i][h], 1);
            sm[i][h] += __shfl_xor_sync(0xffffffffu, sm[i][h], 2);
        }
    __syncthreads();
    if (tig == 0) {
        #pragma unroll
        for (int i = 0; i < 2; i++)
            #pragma unroll
            for (int h = 0; h < 2; h++)
                redp[wr * 72 + rlo + (i << 4) + (h << 3)] = sm[i][h];
    }
    __syncthreads();
    float inv[2][2];
    #pragma unroll
    for (int i = 0; i < 2; i++)
        #pragma unroll
        for (int h = 0; h < 2; h++) {
            int row = rlo + (i << 4) + (h << 3);
            inv[i][h] = 1.0f / (redp[row] + redp[72 + row] + redp[144 + row] + redp[216 + row]);
        }

    float* ub = u + ((size_t)b * MM + m0) * RR;
    #pragma unroll
    for (int i = 0; i < 2; i++) {
        int row = rlo + (i << 4);
        #pragma unroll
        for (int j = 0; j < 8; j++) {
            int col = (wr << 6) + (j << 3) + (tig << 1);
            float2 lo = { acc[i][j].x * inv[i][0], acc[i][j].y * inv[i][0] };
            float2 hi = { acc[i][j].z * inv[i][1], acc[i][j].w * inv[i][1] };
            *(float2*)(ub + (size_t)row * RR + col) = lo;
            *(float2*)(ub + (size_t)(row + 8) * RR + col) = hi;
        }
    }
    #undef STAGE_B
}

// ---------------------------------------------------------------------------
// Column sums of u (two deterministic passes)
// ---------------------------------------------------------------------------
__global__ void k_colsum_part(const float* __restrict__ u) {
    int b = blockIdx.x >> 5, chunk = blockIdx.x & 31;
    int r = threadIdx.x;
    const float* p = u + ((size_t)b * MM + (size_t)chunk * 256) * RR + r;
    float s0 = 0.f, s1 = 0.f, s2 = 0.f, s3 = 0.f;
    for (int m = 0; m < 256; m += 4) {
        s0 += p[(size_t)(m + 0) * RR];
        s1 += p[(size_t)(m + 1) * RR];
        s2 += p[(size_t)(m + 2) * RR];
        s3 += p[(size_t)(m + 3) * RR];
    }
    g_Spart[((size_t)blockIdx.x << 8) + r] = (s0 + s1) + (s2 + s3);
}

__global__ void k_colsum_final() {
    int i = blockIdx.x * blockDim.x + threadIdx.x;
    if (i >= BB * RR) return;
    int b = i >> 8, r = i & 255;
    float s = 0.f;
    #pragma unroll
    for (int c = 0; c < 32; c++) s += g_Spart[(((size_t)(b * 32 + c)) << 8) + r];
    g_S[i] = s;
}

// ---------------------------------------------------------------------------
// GEMM2 on mma.sync tf32. Pitch 136 (mod 32 = 8): conflict-free frag loads.
// ---------------------------------------------------------------------------
#define LDP 136

__global__ __launch_bounds__(256, 2) void k_gemm2_mma(
    const float* __restrict__ x, const float* __restrict__ u)
{
    const int blk = blockIdx.x;
    const int sp  = blk & 3;
    const int rt  = (blk >> 2) & 1;
    const int nt  = (blk >> 3) & 3;
    const int b   = blk >> 5;
    const int n0 = nt << 7, r0 = rt << 7;
    const int kb = sp * 2048, ke = kb + 2048;

    __shared__ uint32_t As[16 * LDP];
    __shared__ uint32_t Bs[16 * LDP];
    __shared__ float srinv[128];

    const int t = threadIdx.x;
    const int w = t >> 5, l = t & 31;
    const int gid = l >> 2, tig = l & 3;
    const int wn = (w >> 2) << 6;
    const int wr = (w & 3) << 5;
    if (t < 128) srinv[t] = 1.0f / (g_S[(b << 8) + r0 + t] + EPSV);
    __syncthreads();

    const float* xb = x + (size_t)b * MM * NN;
    const float* ub = u + (size_t)b * MM * RR;

    float4 acc[4][4];
    #pragma unroll
    for (int i = 0; i < 4; i++)
        #pragma unroll
        for (int j = 0; j < 4; j++) acc[i][j] = make_float4(0.f, 0.f, 0.f, 0.f);

    const int kkA = t >> 5;
    const int cf  = (t & 31) << 2;
    const float4 rv = *(const float4*)&srinv[cf];

    for (int k0 = kb; k0 < ke; k0 += 16) {
        float4 a0 = *(const float4*)(xb + (size_t)(k0 + kkA) * NN + n0 + cf);
        float4 a1 = *(const float4*)(xb + (size_t)(k0 + kkA + 8) * NN + n0 + cf);
        float4 b0 = *(const float4*)(ub + (size_t)(k0 + kkA) * RR + r0 + cf);
        float4 b1 = *(const float4*)(ub + (size_t)(k0 + kkA + 8) * RR + r0 + cf);
        __syncthreads();
        {
            uint4 qa0 = { f2tf32(a0.x), f2tf32(a0.y), f2tf32(a0.z), f2tf32(a0.w) };
            uint4 qa1 = { f2tf32(a1.x), f2tf32(a1.y), f2tf32(a1.z), f2tf32(a1.w) };
            uint4 qb0 = { f2tf32((b0.x + EPSV) * rv.x), f2tf32((b0.y + EPSV) * rv.y),
                          f2tf32((b0.z + EPSV) * rv.z), f2tf32((b0.w + EPSV) * rv.w) };
            uint4 qb1 = { f2tf32((b1.x + EPSV) * rv.x), f2tf32((b1.y + EPSV) * rv.y),
                          f2tf32((b1.z + EPSV) * rv.z), f2tf32((b1.w + EPSV) * rv.w) };
            *(uint4*)&As[kkA * LDP + cf]       = qa0;
            *(uint4*)&As[(kkA + 8) * LDP + cf] = qa1;
            *(uint4*)&Bs[kkA * LDP + cf]       = qb0;
            *(uint4*)&Bs[(kkA + 8) * LDP + cf] = qb1;
        }
        __syncthreads();
        #pragma unroll
        for (int kk = 0; kk < 16; kk += 8) {
            const uint32_t* Ak = &As[(kk + tig) * LDP];
            const uint32_t* Bk = &Bs[(kk + tig) * LDP];
            uint32_t af[4][4], bf[4][2];
            #pragma unroll
            for (int i = 0; i < 4; i++) {
                int base = wn + (i << 4) + gid;
                af[i][0] = Ak[base];
                af[i][1] = Ak[base + 8];
                af[i][2] = Ak[base + 4 * LDP];
                af[i][3] = Ak[base + 4 * LDP + 8];
            }
            #pragma unroll
            for (int j = 0; j < 4; j++) {
                int base = wr + (j << 3) + gid;
                bf[j][0] = Bk[base];
                bf[j][1] = Bk[base + 4 * LDP];
            }
            #pragma unroll
            for (int i = 0; i < 4; i++)
                #pragma unroll
                for (int j = 0; j < 4; j++)
                    mma_tf32(acc[i][j], af[i][0], af[i][1], af[i][2], af[i][3],
                             bf[j][0], bf[j][1]);
        }
    }

    float* pbase = g_part + ((size_t)(b * 4 + sp) * NN + n0 + wn + gid) * RR + r0 + wr + (tig << 1);
    #pragma unroll
    for (int i = 0; i < 4; i++) {
        #pragma unroll
        for (int j = 0; j < 4; j++) {
            float2 lo = { acc[i][j].x, acc[i][j].y };
            float2 hi = { acc[i][j].z, acc[i][j].w };
            float* p = pbase + (size_t)(i << 4) * RR + (j << 3);
            *(float2*)p = lo;
            *(float2*)(p + (size_t)8 * RR) = hi;
        }
    }
}

__global__ void k_vred(float* __restrict__ vout) {
    int i = blockIdx.x * blockDim.x + threadIdx.x;
    int b = i >> 17;
    int nr = i & 131071;
    float s = 0.f;
    #pragma unroll
    for (int sp = 0; sp < 4; sp++)
        s += g_part[((size_t)(b * 4 + sp)) * (NN * RR) + nr];
    vout[i] = s;
}

// ---------------------------------------------------------------------------
extern "C" void kernel_launch(void* const* d_in, const int* in_sizes, int n_in,
                              void* d_out, int out_size) {
    const float* x     = (const float*)d_in[0];
    const float* alpha = (const float*)d_in[1];
    const int*   inds  = (const int*)d_in[2];
    float* u = (float*)d_out;
    float* v = u + (size_t)BB * MM * RR;

    cudaFuncSetAttribute(k_gemm1_mma, cudaFuncAttributeMaxDynamicSharedMemorySize, G1_SMEM_BYTES);

    k_v2<<<(BB * RR) / 8, 256>>>(x, inds);
    k_prep_v<<<32, 256>>>(x, inds);
    k_gemm1_mma<<<BB * (MM / 64), 256, G1_SMEM_BYTES>>>(x, alpha, u);
    k_colsum_part<<<BB * 32, 256>>>(u);
    k_colsum_final<<<8, 256>>>();
    k_gemm2_mma<<<256, 256>>>(x, u);
    k_vred<<<(BB * NN * RR) / 256, 256>>>(v);
}

// round 13
// speedup vs baseline: 1.7917x; 1.0001x over previous
#include <cuda_runtime.h>
#include <cstdint>

#define BB 8
#define MM 8192
#define NN 512
#define RR 256
#define EPSV 1e-16f

// scratch (no allocations allowed)
__device__ float g_v2[BB * RR];
__device__ float g_S[BB * RR];
__device__ float g_Spart[BB * 32 * RR];
__device__ float g_part[BB * 4 * NN * RR];       // split-K partials for v
__device__ uint32_t g_vhi[BB * NN * RR];         // VT hi tf32, [b][n][r]
__device__ uint32_t g_vlo[BB * NN * RR];         // VT lo tf32

__device__ __forceinline__ uint32_t f2tf32(float f) {
    uint32_t r; asm("cvt.rna.tf32.f32 %0, %1;" : "=r"(r) : "f"(f)); return r;
}
__device__ __forceinline__ void mma_tf32(float4& d,
    uint32_t a0, uint32_t a1, uint32_t a2, uint32_t a3,
    uint32_t b0, uint32_t b1)
{
    asm volatile(
        "mma.sync.aligned.m16n8k8.row.col.f32.tf32.tf32.f32 "
        "{%0,%1,%2,%3}, {%4,%5,%6,%7}, {%8,%9}, {%0,%1,%2,%3};"
        : "+f"(d.x), "+f"(d.y), "+f"(d.z), "+f"(d.w)
        : "r"(a0), "r"(a1), "r"(a2), "r"(a3), "r"(b0), "r"(b1));
}
__device__ __forceinline__ uint32_t smem_u32(const void* p) {
    uint32_t a;
    asm("{ .reg .u64 t; cvta.to.shared.u64 t, %1; cvt.u32.u64 %0, t; }" : "=r"(a) : "l"(p));
    return a;
}
__device__ __forceinline__ void cpa16(uint32_t dst, const void* src) {
    asm volatile("cp.async.cg.shared.global [%0], [%1], 16;" :: "r"(dst), "l"(src));
}

// ---------------------------------------------------------------------------
// v2[b][r] = sum_n x[b, inds[r], n]^2
// ---------------------------------------------------------------------------
__global__ void k_v2(const float* __restrict__ x, const int* __restrict__ inds) {
    int gw = (blockIdx.x * blockDim.x + threadIdx.x) >> 5;
    int lane = threadIdx.x & 31;
    if (gw >= BB * RR) return;
    int b = gw >> 8, r = gw & 255;
    const float* row = x + ((size_t)b * MM + inds[r]) * NN;
    float s = 0.f;
    const float4* row4 = (const float4*)row;
    #pragma unroll
    for (int i = lane; i < NN / 4; i += 32) {
        float4 v = row4[i];
        s += v.x * v.x + v.y * v.y + v.z * v.z + v.w * v.w;
    }
    #pragma unroll
    for (int o = 16; o; o >>= 1) s += __shfl_xor_sync(0xffffffffu, s, o);
    if (lane == 0) g_v2[gw] = s;
}

// ---------------------------------------------------------------------------
// Precompute VT hi/lo: g_v{hi,lo}[b][n][r] = tf32split(x[b, inds[r], n])
// ---------------------------------------------------------------------------
__global__ void k_prep_v(const float* __restrict__ x, const int* __restrict__ inds) {
    int b  = blockIdx.x >> 2;
    int nc = (blockIdx.x & 3) << 7;
    int r  = threadIdx.x;
    const float* row = x + ((size_t)b * MM + inds[r]) * NN + nc;
    uint32_t* vh = g_vhi + ((size_t)(b * NN + nc)) * RR + r;
    uint32_t* vl = g_vlo + ((size_t)(b * NN + nc)) * RR + r;
    for (int n = 0; n < 128; n += 4) {
        float4 q = *(const float4*)(row + n);
        const float* qa = &q.x;
        #pragma unroll
        for (int c = 0; c < 4; c++) {
            float vv = qa[c];
            uint32_t h = f2tf32(vv);
            vh[(size_t)(n + c) * RR] = h;
            vl[(size_t)(n + c) * RR] = f2tf32(vv - __uint_as_float(h));
        }
    }
}

// ---------------------------------------------------------------------------
// GEMM1 on tensor cores (3xTF32) + fused softmax, cp.async double-buffered.
// Block 256 thr (8 warps), tile 64(m) x 256(r full row), BK=16, 2 CTAs/SM.
// ---------------------------------------------------------------------------
#define G1_SMEM_WORDS 21984
#define G1_SMEM_BYTES (G1_SMEM_WORDS * 4)

__global__ __launch_bounds__(256, 2) void k_gemm1_mma(
    const float* __restrict__ x, const float* __restrict__ alpha,
    float* __restrict__ u)
{
    extern __shared__ uint32_t smw[];
    const uint32_t smb = smem_u32(smw);

    const int t  = threadIdx.x;
    const int b  = blockIdx.x >> 7;
    const int m0 = (blockIdx.x & 127) << 6;
    const int w = t >> 5, l = t & 31;
    const int gid = l >> 2, tig = l & 3;
    const int wm = w >> 2;                     // 0..1
    const int wr = w & 3;                      // 0..3

    float* sv2p = (float*)(smw + 21376);
    float* sx2p = (float*)(smw + 21632);
    float* redp = (float*)(smw + 21696);       // [4][72]

    sv2p[t] = g_v2[(b << 8) + t];
    const float aval = alpha[0];

    const float* xb = x + (size_t)b * MM * NN;
    const int arow = t >> 2, acb = (t & 3) << 2;
    const float* aptr = xb + (size_t)(m0 + arow) * NN + acb;

    const uint32_t* vsrc[2] = { g_vhi + (size_t)b * NN * RR,
                                g_vlo + (size_t)b * NN * RR };
    #define STAGE_B(buf, k0)                                                     \
        do {                                                                     \
            uint32_t bb_ = smb + (4480u + (buf) * 8448u) * 4u;                   \
            _Pragma("unroll")                                                    \
            for (int j_ = 0; j_ < 8; j_++) {                                     \
                int c_  = (j_ << 8) + t;                                         \
                int hl_ = j_ >> 2;                                               \
                int rw_ = (c_ >> 6) & 15;                                        \
                int pc_ = (c_ & 63) << 2;                                        \
                uint32_t dst_ = bb_ + (hl_ * 4224u + rw_ * 264u + pc_) * 4u;     \
                cpa16(dst_, vsrc[hl_] + ((size_t)((k0) + rw_)) * RR + pc_);      \
            }                                                                    \
        } while (0)

    float4 acc[2][8];
    #pragma unroll
    for (int i = 0; i < 2; i++)
        #pragma unroll
        for (int j = 0; j < 8; j++) acc[i][j] = make_float4(0.f, 0.f, 0.f, 0.f);
    float xsq = 0.f;

    STAGE_B(0, 0);
    asm volatile("cp.async.commit_group;" ::: "memory");
    float4 av = *(const float4*)(aptr);

    for (int i = 0; i < 32; i++) {
        const int buf = i & 1;
        {
            const float* ap = &av.x;
            uint32_t* Ahw = smw + buf * 2240;
            #pragma unroll
            for (int c = 0; c < 4; c++) {
                float vv = ap[c];
                uint32_t h = f2tf32(vv);
                Ahw[(acb + c) * 70 + arow]        = h;
                Ahw[1120 + (acb + c) * 70 + arow] = f2tf32(vv - __uint_as_float(h));
                xsq += vv * vv;
            }
        }
        float4 avn;
        if (i < 31) avn = *(const float4*)(aptr + (i + 1) * 16);
        asm volatile("cp.async.wait_group 0;" ::: "memory");
        __syncthreads();
        if (i < 31) {
            STAGE_B(buf ^ 1, (i + 1) * 16);
            asm volatile("cp.async.commit_group;" ::: "memory");
        }
        #pragma unroll
        for (int kk = 0; kk < 16; kk += 8) {
            const uint32_t* Ah = smw + buf * 2240 + (kk + tig) * 70 + (wm << 5);
            const uint32_t* Al = Ah + 1120;
            const uint32_t* Bh = smw + 4480 + buf * 8448 + (kk + tig) * 264 + (wr << 6);
            const uint32_t* Bl = Bh + 4224;
            uint32_t ah[2][4], al[2][4], bb[8][2];
            #pragma unroll
            for (int i2 = 0; i2 < 2; i2++) {
                int base = (i2 << 4) + gid;
                ah[i2][0] = Ah[base];
                ah[i2][1] = Ah[base + 8];
                ah[i2][2] = Ah[base + 4 * 70];
                ah[i2][3] = Ah[base + 4 * 70 + 8];
                al[i2][0] = Al[base];
                al[i2][1] = Al[base + 8];
                al[i2][2] = Al[base + 4 * 70];
                al[i2][3] = Al[base + 4 * 70 + 8];
            }
            #pragma unroll
            for (int j = 0; j < 8; j++) {
                int base = (j << 3) + gid;
                bb[j][0] = Bh[base];
                bb[j][1] = Bh[base + 4 * 264];
            }
            #pragma unroll
            for (int i2 = 0; i2 < 2; i2++)
                #pragma unroll
                for (int j = 0; j < 8; j++)
                    mma_tf32(acc[i2][j], ah[i2][0], ah[i2][1], ah[i2][2], ah[i2][3],
                             bb[j][0], bb[j][1]);
            #pragma unroll
            for (int i2 = 0; i2 < 2; i2++)
                #pragma unroll
                for (int j = 0; j < 8; j++)
                    mma_tf32(acc[i2][j], al[i2][0], al[i2][1], al[i2][2], al[i2][3],
                             bb[j][0], bb[j][1]);
            #pragma unroll
            for (int j = 0; j < 8; j++) {
                int base = (j << 3) + gid;
                bb[j][0] = Bl[base];
                bb[j][1] = Bl[base + 4 * 264];
            }
            #pragma unroll
            for (int i2 = 0; i2 < 2; i2++)
                #pragma unroll
                for (int j = 0; j < 8; j++)
                    mma_tf32(acc[i2][j], ah[i2][0], ah[i2][1], ah[i2][2], ah[i2][3],
                             bb[j][0], bb[j][1]);
        }
        av = avn;
    }

    xsq += __shfl_xor_sync(0xffffffffu, xsq, 1);
    xsq += __shfl_xor_sync(0xffffffffu, xsq, 2);
    if ((t & 3) == 0) sx2p[arow] = xsq;
    __syncthreads();

    const int rlo = (wm << 5) + gid;
    float x2v[2][2];
    #pragma unroll
    for (int i = 0; i < 2; i++) {
        x2v[i][0] = sx2p[rlo + (i << 4)];
        x2v[i][1] = sx2p[rlo + (i << 4) + 8];
    }
    #pragma unroll
    for (int i = 0; i < 2; i++)
        #pragma unroll
        for (int j = 0; j < 8; j++) {
            int rr = (wr << 6) + (j << 3) + (tig << 1);
            float va = sv2p[rr], vb = sv2p[rr + 1];
            acc[i][j].x = -fmaxf(x2v[i][0] - 2.f * acc[i][j].x + va, 0.f) / aval;
            acc[i][j].y = -fmaxf(x2v[i][0] - 2.f * acc[i][j].y + vb, 0.f) / aval;
            acc[i][j].z = -fmaxf(x2v[i][1] - 2.f * acc[i][j].z + va, 0.f) / aval;
            acc[i][j].w = -fmaxf(x2v[i][1] - 2.f * acc[i][j].w + vb, 0.f) / aval;
        }

    float mx[2][2] = { { -1e30f, -1e30f }, { -1e30f, -1e30f } };
    #pragma unroll
    for (int i = 0; i < 2; i++)
        #pragma unroll
        for (int j = 0; j < 8; j++) {
            mx[i][0] = fmaxf(mx[i][0], fmaxf(acc[i][j].x, acc[i][j].y));
            mx[i][1] = fmaxf(mx[i][1], fmaxf(acc[i][j].z, acc[i][j].w));
        }
    #pragma unroll
    for (int i = 0; i < 2; i++)
        #pragma unroll
        for (int h = 0; h < 2; h++) {
            mx[i][h] = fmaxf(mx[i][h], __shfl_xor_sync(0xffffffffu, mx[i][h], 1));
            mx[i][h] = fmaxf(mx[i][h], __shfl_xor_sync(0xffffffffu, mx[i][h], 2));
        }
    if (tig == 0) {
        #pragma unroll
        for (int i = 0; i < 2; i++)
            #pragma unroll
            for (int h = 0; h < 2; h++)
                redp[wr * 72 + rlo + (i << 4) + (h << 3)] = mx[i][h];
    }
    __syncthreads();
    float rmx[2][2];
    #pragma unroll
    for (int i = 0; i < 2; i++)
        #pragma unroll
        for (int h = 0; h < 2; h++) {
            int row = rlo + (i << 4) + (h << 3);
            rmx[i][h] = fmaxf(fmaxf(redp[row], redp[72 + row]),
                              fmaxf(redp[144 + row], redp[216 + row]));
        }

    float sm[2][2] = { { 0.f, 0.f }, { 0.f, 0.f } };
    #pragma unroll
    for (int i = 0; i < 2; i++)
        #pragma unroll
        for (int j = 0; j < 8; j++) {
            acc[i][j].x = __expf(acc[i][j].x - rmx[i][0]);
            acc[i][j].y = __expf(acc[i][j].y - rmx[i][0]);
            acc[i][j].z = __expf(acc[i][j].z - rmx[i][1]);
            acc[i][j].w = __expf(acc[i][j].w - rmx[i][1]);
            sm[i][0] += acc[i][j].x + acc[i][j].y;
            sm[i][1] += acc[i][j].z + acc[i][j].w;
        }
    #pragma unroll
    for (int i = 0; i < 2; i++)
        #pragma unroll
        for (int h = 0; h < 2; h++) {
            sm[i][h] += __shfl_xor_sync(0xffffffffu, sm[i][h], 1);
            sm[i][h] += __shfl_xor_sync(0xffffffffu, sm[i][h], 2);
        }
    __syncthreads();
    if (tig == 0) {
        #pragma unroll
        for (int i = 0; i < 2; i++)
            #pragma unroll
            for (int h = 0; h < 2; h++)
                redp[wr * 72 + rlo + (i << 4) + (h << 3)] = sm[i][h];
    }
    __syncthreads();
    float inv[2][2];
    #pragma unroll
    for (int i = 0; i < 2; i++)
        #pragma unroll
        for (int h = 0; h < 2; h++) {
            int row = rlo + (i << 4) + (h << 3);
            inv[i][h] = 1.0f / (redp[row] + redp[72 + row] + redp[144 + row] + redp[216 + row]);
        }

    float* ub = u + ((size_t)b * MM + m0) * RR;
    #pragma unroll
    for (int i = 0; i < 2; i++) {
        int row = rlo + (i << 4);
        #pragma unroll
        for (int j = 0; j < 8; j++) {
            int col = (wr << 6) + (j << 3) + (tig << 1);
            float2 lo = { acc[i][j].x * inv[i][0], acc[i][j].y * inv[i][0] };
            float2 hi = { acc[i][j].z * inv[i][1], acc[i][j].w * inv[i][1] };
            *(float2*)(ub + (size_t)row * RR + col) = lo;
            *(float2*)(ub + (size_t)(row + 8) * RR + col) = hi;
        }
    }
    #undef STAGE_B
}

// ---------------------------------------------------------------------------
// Column sums of u (two deterministic passes)
// ---------------------------------------------------------------------------
__global__ void k_colsum_part(const float* __restrict__ u) {
    int b = blockIdx.x >> 5, chunk = blockIdx.x & 31;
    int r = threadIdx.x;
    const float* p = u + ((size_t)b * MM + (size_t)chunk * 256) * RR + r;
    float s0 = 0.f, s1 = 0.f, s2 = 0.f, s3 = 0.f;
    for (int m = 0; m < 256; m += 4) {
        s0 += p[(size_t)(m + 0) * RR];
        s1 += p[(size_t)(m + 1) * RR];
        s2 += p[(size_t)(m + 2) * RR];
        s3 += p[(size_t)(m + 3) * RR];
    }
    g_Spart[((size_t)blockIdx.x << 8) + r] = (s0 + s1) + (s2 + s3);
}

__global__ void k_colsum_final() {
    int i = blockIdx.x * blockDim.x + threadIdx.x;
    if (i >= BB * RR) return;
    int b = i >> 8, r = i & 255;
    float s = 0.f;
    #pragma unroll
    for (int c = 0; c < 32; c++) s += g_Spart[(((size_t)(b * 32 + c)) << 8) + r];
    g_S[i] = s;
}

// ---------------------------------------------------------------------------
// GEMM2 on mma.sync tf32. Pitch 136 (mod 32 = 8): conflict-free frag loads.
// ---------------------------------------------------------------------------
#define LDP 136

__global__ __launch_bounds__(256, 2) void k_gemm2_mma(
    const float* __restrict__ x, const float* __restrict__ u)
{
    const int blk = blockIdx.x;
    const int sp  = blk & 3;
    const int rt  = (blk >> 2) & 1;
    const int nt  = (blk >> 3) & 3;
    const int b   = blk >> 5;
    const int n0 = nt << 7, r0 = rt << 7;
    const int kb = sp * 2048, ke = kb + 2048;

    __shared__ uint32_t As[16 * LDP];
    __shared__ uint32_t Bs[16 * LDP];
    __shared__ float srinv[128];

    const int t = threadIdx.x;
    const int w = t >> 5, l = t & 31;
    const int gid = l >> 2, tig = l & 3;
    const int wn = (w >> 2) << 6;
    const int wr = (w & 3) << 5;
    if (t < 128) srinv[t] = 1.0f / (g_S[(b << 8) + r0 + t] + EPSV);
    __syncthreads();

    const float* xb = x + (size_t)b * MM * NN;
    const float* ub = u + (size_t)b * MM * RR;

    float4 acc[4][4];
    #pragma unroll
    for (int i = 0; i < 4; i++)
        #pragma unroll
        for (int j = 0; j < 4; j++) acc[i][j] = make_float4(0.f, 0.f, 0.f, 0.f);

    const int kkA = t >> 5;
    const int cf  = (t & 31) << 2;
    const float4 rv = *(const float4*)&srinv[cf];

    for (int k0 = kb; k0 < ke; k0 += 16) {
        float4 a0 = *(const float4*)(xb + (size_t)(k0 + kkA) * NN + n0 + cf);
        float4 a1 = *(const float4*)(xb + (size_t)(k0 + kkA + 8) * NN + n0 + cf);
        float4 b0 = *(const float4*)(ub + (size_t)(k0 + kkA) * RR + r0 + cf);
        float4 b1 = *(const float4*)(ub + (size_t)(k0 + kkA + 8) * RR + r0 + cf);
        __syncthreads();
        {
            uint4 qa0 = { f2tf32(a0.x), f2tf32(a0.y), f2tf32(a0.z), f2tf32(a0.w) };
            uint4 qa1 = { f2tf32(a1.x), f2tf32(a1.y), f2tf32(a1.z), f2tf32(a1.w) };
            uint4 qb0 = { f2tf32((b0.x + EPSV) * rv.x), f2tf32((b0.y + EPSV) * rv.y),
                          f2tf32((b0.z + EPSV) * rv.z), f2tf32((b0.w + EPSV) * rv.w) };
            uint4 qb1 = { f2tf32((b1.x + EPSV) * rv.x), f2tf32((b1.y + EPSV) * rv.y),
                          f2tf32((b1.z + EPSV) * rv.z), f2tf32((b1.w + EPSV) * rv.w) };
            *(uint4*)&As[kkA * LDP + cf]       = qa0;
            *(uint4*)&As[(kkA + 8) * LDP + cf] = qa1;
            *(uint4*)&Bs[kkA * LDP + cf]       = qb0;
            *(uint4*)&Bs[(kkA + 8) * LDP + cf] = qb1;
        }
        __syncthreads();
        #pragma unroll
        for (int kk = 0; kk < 16; kk += 8) {
            const uint32_t* Ak = &As[(kk + tig) * LDP];
            const uint32_t* Bk = &Bs[(kk + tig) * LDP];
            uint32_t af[4][4], bf[4][2];
            #pragma unroll
            for (int i = 0; i < 4; i++) {
                int base = wn + (i << 4) + gid;
                af[i][0] = Ak[base];
                af[i][1] = Ak[base + 8];
                af[i][2] = Ak[base + 4 * LDP];
                af[i][3] = Ak[base + 4 * LDP + 8];
            }
            #pragma unroll
            for (int j = 0; j < 4; j++) {
                int base = wr + (j << 3) + gid;
                bf[j][0] = Bk[base];
                bf[j][1] = Bk[base + 4 * LDP];
            }
            #pragma unroll
            for (int i = 0; i < 4; i++)
                #pragma unroll
                for (int j = 0; j < 4; j++)
                    mma_tf32(acc[i][j], af[i][0], af[i][1], af[i][2], af[i][3],
                             bf[j][0], bf[j][1]);
        }
    }

    float* pbase = g_part + ((size_t)(b * 4 + sp) * NN + n0 + wn + gid) * RR + r0 + wr + (tig << 1);
    #pragma unroll
    for (int i = 0; i < 4; i++) {
        #pragma unroll
        for (int j = 0; j < 4; j++) {
            float2 lo = { acc[i][j].x, acc[i][j].y };
            float2 hi = { acc[i][j].z, acc[i][j].w };
            float* p = pbase + (size_t)(i << 4) * RR + (j << 3);
            *(float2*)p = lo;
            *(float2*)(p + (size_t)8 * RR) = hi;
        }
    }
}

__global__ void k_vred(float* __restrict__ vout) {
    int i = blockIdx.x * blockDim.x + threadIdx.x;
    int b = i >> 17;
    int nr = i & 131071;
    float s = 0.f;
    #pragma unroll
    for (int sp = 0; sp < 4; sp++)
        s += g_part[((size_t)(b * 4 + sp)) * (NN * RR) + nr];
    vout[i] = s;
}

// ---------------------------------------------------------------------------
extern "C" void kernel_launch(void* const* d_in, const int* in_sizes, int n_in,
                              void* d_out, int out_size) {
    const float* x     = (const float*)d_in[0];
    const float* alpha = (const float*)d_in[1];
    const int*   inds  = (const int*)d_in[2];
    float* u = (float*)d_out;
    float* v = u + (size_t)BB * MM * RR;

    cudaFuncSetAttribute(k_gemm1_mma, cudaFuncAttributeMaxDynamicSharedMemorySize, G1_SMEM_BYTES);

    k_v2<<<(BB * RR) / 8, 256>>>(x, inds);
    k_prep_v<<<32, 256>>>(x, inds);
    k_gemm1_mma<<<BB * (MM / 64), 256, G1_SMEM_BYTES>>>(x, alpha, u);
    k_colsum_part<<<BB * 32, 256>>>(u);
    k_colsum_final<<<8, 256>>>();
    k_gemm2_mma<<<256, 256>>>(x, u);
    k_vred<<<(BB * NN * RR) / 256, 256>>>(v);
}

// round 14
// speedup vs baseline: 1.7920x; 1.0002x over previous
#include <cuda_runtime.h>
#include <cstdint>

#define BB 8
#define MM 8192
#define NN 512
#define RR 256
#define EPSV 1e-16f

// scratch (no allocations allowed)
__device__ float g_v2[BB * RR];
__device__ float g_S[BB * RR];
__device__ float g_Spart[BB * 32 * RR];
__device__ float g_part[BB * 4 * NN * RR];       // split-K partials for v
__device__ uint32_t g_vhi[BB * NN * RR];         // VT hi tf32, [b][n][r]
__device__ uint32_t g_vlo[BB * NN * RR];         // VT lo tf32

__device__ __forceinline__ uint32_t f2tf32(float f) {
    uint32_t r; asm("cvt.rna.tf32.f32 %0, %1;" : "=r"(r) : "f"(f)); return r;
}
__device__ __forceinline__ void mma_tf32(float4& d,
    uint32_t a0, uint32_t a1, uint32_t a2, uint32_t a3,
    uint32_t b0, uint32_t b1)
{
    asm volatile(
        "mma.sync.aligned.m16n8k8.row.col.f32.tf32.tf32.f32 "
        "{%0,%1,%2,%3}, {%4,%5,%6,%7}, {%8,%9}, {%0,%1,%2,%3};"
        : "+f"(d.x), "+f"(d.y), "+f"(d.z), "+f"(d.w)
        : "r"(a0), "r"(a1), "r"(a2), "r"(a3), "r"(b0), "r"(b1));
}
__device__ __forceinline__ uint32_t smem_u32(const void* p) {
    uint32_t a;
    asm("{ .reg .u64 t; cvta.to.shared.u64 t, %1; cvt.u32.u64 %0, t; }" : "=r"(a) : "l"(p));
    return a;
}
__device__ __forceinline__ void cpa16(uint32_t dst, const void* src) {
    asm volatile("cp.async.cg.shared.global [%0], [%1], 16;" :: "r"(dst), "l"(src));
}

// ---------------------------------------------------------------------------
// v2[b][r] = sum_n x[b, inds[r], n]^2
// ---------------------------------------------------------------------------
__global__ void k_v2(const float* __restrict__ x, const int* __restrict__ inds) {
    int gw = (blockIdx.x * blockDim.x + threadIdx.x) >> 5;
    int lane = threadIdx.x & 31;
    if (gw >= BB * RR) return;
    int b = gw >> 8, r = gw & 255;
    const float* row = x + ((size_t)b * MM + inds[r]) * NN;
    float s = 0.f;
    const float4* row4 = (const float4*)row;
    #pragma unroll
    for (int i = lane; i < NN / 4; i += 32) {
        float4 v = row4[i];
        s += v.x * v.x + v.y * v.y + v.z * v.z + v.w * v.w;
    }
    #pragma unroll
    for (int o = 16; o; o >>= 1) s += __shfl_xor_sync(0xffffffffu, s, o);
    if (lane == 0) g_v2[gw] = s;
}

// ---------------------------------------------------------------------------
// Precompute VT hi/lo: g_v{hi,lo}[b][n][r] = tf32split(x[b, inds[r], n])
// ---------------------------------------------------------------------------
__global__ void k_prep_v(const float* __restrict__ x, const int* __restrict__ inds) {
    int b  = blockIdx.x >> 2;
    int nc = (blockIdx.x & 3) << 7;
    int r  = threadIdx.x;
    const float* row = x + ((size_t)b * MM + inds[r]) * NN + nc;
    uint32_t* vh = g_vhi + ((size_t)(b * NN + nc)) * RR + r;
    uint32_t* vl = g_vlo + ((size_t)(b * NN + nc)) * RR + r;
    for (int n = 0; n < 128; n += 4) {
        float4 q = *(const float4*)(row + n);
        const float* qa = &q.x;
        #pragma unroll
        for (int c = 0; c < 4; c++) {
            float vv = qa[c];
            uint32_t h = f2tf32(vv);
            vh[(size_t)(n + c) * RR] = h;
            vl[(size_t)(n + c) * RR] = f2tf32(vv - __uint_as_float(h));
        }
    }
}

// ---------------------------------------------------------------------------
// GEMM1 on tensor cores (3xTF32) + fused softmax, cp.async double-buffered.
// Block 256 thr (8 warps), tile 64(m) x 256(r full row), BK=16, 2 CTAs/SM.
// ---------------------------------------------------------------------------
#define G1_SMEM_WORDS 21984
#define G1_SMEM_BYTES (G1_SMEM_WORDS * 4)

__global__ __launch_bounds__(256, 2) void k_gemm1_mma(
    const float* __restrict__ x, const float* __restrict__ alpha,
    float* __restrict__ u)
{
    extern __shared__ uint32_t smw[];
    const uint32_t smb = smem_u32(smw);

    const int t  = threadIdx.x;
    const int b  = blockIdx.x >> 7;
    const int m0 = (blockIdx.x & 127) << 6;
    const int w = t >> 5, l = t & 31;
    const int gid = l >> 2, tig = l & 3;
    const int wm = w >> 2;                     // 0..1
    const int wr = w & 3;                      // 0..3

    float* sv2p = (float*)(smw + 21376);
    float* sx2p = (float*)(smw + 21632);
    float* redp = (float*)(smw + 21696);       // [4][72]

    sv2p[t] = g_v2[(b << 8) + t];
    const float aval = alpha[0];

    const float* xb = x + (size_t)b * MM * NN;
    const int arow = t >> 2, acb = (t & 3) << 2;
    const float* aptr = xb + (size_t)(m0 + arow) * NN + acb;

    const uint32_t* vsrc[2] = { g_vhi + (size_t)b * NN * RR,
                                g_vlo + (size_t)b * NN * RR };
    #define STAGE_B(buf, k0)                                                     \
        do {                                                                     \
            uint32_t bb_ = smb + (4480u + (buf) * 8448u) * 4u;                   \
            _Pragma("unroll")                                                    \
            for (int j_ = 0; j_ < 8; j_++) {                                     \
                int c_  = (j_ << 8) + t;                                         \
                int hl_ = j_ >> 2;                                               \
                int rw_ = (c_ >> 6) & 15;                                        \
                int pc_ = (c_ & 63) << 2;                                        \
                uint32_t dst_ = bb_ + (hl_ * 4224u + rw_ * 264u + pc_) * 4u;     \
                cpa16(dst_, vsrc[hl_] + ((size_t)((k0) + rw_)) * RR + pc_);      \
            }                                                                    \
        } while (0)

    float4 acc[2][8];
    #pragma unroll
    for (int i = 0; i < 2; i++)
        #pragma unroll
        for (int j = 0; j < 8; j++) acc[i][j] = make_float4(0.f, 0.f, 0.f, 0.f);
    float xsq = 0.f;

    STAGE_B(0, 0);
    asm volatile("cp.async.commit_group;" ::: "memory");
    float4 av = *(const float4*)(aptr);

    for (int i = 0; i < 32; i++) {
        const int buf = i & 1;
        {
            const float* ap = &av.x;
            uint32_t* Ahw = smw + buf * 2240;
            #pragma unroll
            for (int c = 0; c < 4; c++) {
                float vv = ap[c];
                uint32_t h = f2tf32(vv);
                Ahw[(acb + c) * 70 + arow]        = h;
                Ahw[1120 + (acb + c) * 70 + arow] = f2tf32(vv - __uint_as_float(h));
                xsq += vv * vv;
            }
        }
        float4 avn;
        if (i < 31) avn = *(const float4*)(aptr + (i + 1) * 16);
        asm volatile("cp.async.wait_group 0;" ::: "memory");
        __syncthreads();
        if (i < 31) {
            STAGE_B(buf ^ 1, (i + 1) * 16);
            asm volatile("cp.async.commit_group;" ::: "memory");
        }
        #pragma unroll
        for (int kk = 0; kk < 16; kk += 8) {
            const uint32_t* Ah = smw + buf * 2240 + (kk + tig) * 70 + (wm << 5);
            const uint32_t* Al = Ah + 1120;
            const uint32_t* Bh = smw + 4480 + buf * 8448 + (kk + tig) * 264 + (wr << 6);
            const uint32_t* Bl = Bh + 4224;
            uint32_t ah[2][4], al[2][4], bb[8][2];
            #pragma unroll
            for (int i2 = 0; i2 < 2; i2++) {
                int base = (i2 << 4) + gid;
                ah[i2][0] = Ah[base];
                ah[i2][1] = Ah[base + 8];
                ah[i2][2] = Ah[base + 4 * 70];
                ah[i2][3] = Ah[base + 4 * 70 + 8];
                al[i2][0] = Al[base];
                al[i2][1] = Al[base + 8];
                al[i2][2] = Al[base + 4 * 70];
                al[i2][3] = Al[base + 4 * 70 + 8];
            }
            #pragma unroll
            for (int j = 0; j < 8; j++) {
                int base = (j << 3) + gid;
                bb[j][0] = Bh[base];
                bb[j][1] = Bh[base + 4 * 264];
            }
            #pragma unroll
            for (int i2 = 0; i2 < 2; i2++)
                #pragma unroll
                for (int j = 0; j < 8; j++)
                    mma_tf32(acc[i2][j], ah[i2][0], ah[i2][1], ah[i2][2], ah[i2][3],
                             bb[j][0], bb[j][1]);
            #pragma unroll
            for (int i2 = 0; i2 < 2; i2++)
                #pragma unroll
                for (int j = 0; j < 8; j++)
                    mma_tf32(acc[i2][j], al[i2][0], al[i2][1], al[i2][2], al[i2][3],
                             bb[j][0], bb[j][1]);
            #pragma unroll
            for (int j = 0; j < 8; j++) {
                int base = (j << 3) + gid;
                bb[j][0] = Bl[base];
                bb[j][1] = Bl[base + 4 * 264];
            }
            #pragma unroll
            for (int i2 = 0; i2 < 2; i2++)
                #pragma unroll
                for (int j = 0; j < 8; j++)
                    mma_tf32(acc[i2][j], ah[i2][0], ah[i2][1], ah[i2][2], ah[i2][3],
                             bb[j][0], bb[j][1]);
        }
        av = avn;
    }

    xsq += __shfl_xor_sync(0xffffffffu, xsq, 1);
    xsq += __shfl_xor_sync(0xffffffffu, xsq, 2);
    if ((t & 3) == 0) sx2p[arow] = xsq;
    __syncthreads();

    const int rlo = (wm << 5) + gid;
    float x2v[2][2];
    #pragma unroll
    for (int i = 0; i < 2; i++) {
        x2v[i][0] = sx2p[rlo + (i << 4)];
        x2v[i][1] = sx2p[rlo + (i << 4) + 8];
    }
    #pragma unroll
    for (int i = 0; i < 2; i++)
        #pragma unroll
        for (int j = 0; j < 8; j++) {
            int rr = (wr << 6) + (j << 3) + (tig << 1);
            float va = sv2p[rr], vb = sv2p[rr + 1];
            acc[i][j].x = -fmaxf(x2v[i][0] - 2.f * acc[i][j].x + va, 0.f) / aval;
            acc[i][j].y = -fmaxf(x2v[i][0] - 2.f * acc[i][j].y + vb, 0.f) / aval;
            acc[i][j].z = -fmaxf(x2v[i][1] - 2.f * acc[i][j].z + va, 0.f) / aval;
            acc[i][j].w = -fmaxf(x2v[i][1] - 2.f * acc[i][j].w + vb, 0.f) / aval;
        }

    float mx[2][2] = { { -1e30f, -1e30f }, { -1e30f, -1e30f } };
    #pragma unroll
    for (int i = 0; i < 2; i++)
        #pragma unroll
        for (int j = 0; j < 8; j++) {
            mx[i][0] = fmaxf(mx[i][0], fmaxf(acc[i][j].x, acc[i][j].y));
            mx[i][1] = fmaxf(mx[i][1], fmaxf(acc[i][j].z, acc[i][j].w));
        }
    #pragma unroll
    for (int i = 0; i < 2; i++)
        #pragma unroll
        for (int h = 0; h < 2; h++) {
            mx[i][h] = fmaxf(mx[i][h], __shfl_xor_sync(0xffffffffu, mx[i][h], 1));
            mx[i][h] = fmaxf(mx[i][h], __shfl_xor_sync(0xffffffffu, mx[i][h], 2));
        }
    if (tig == 0) {
        #pragma unroll
        for (int i = 0; i < 2; i++)
            #pragma unroll
            for (int h = 0; h < 2; h++)
                redp[wr * 72 + rlo + (i << 4) + (h << 3)] = mx[i][h];
    }
    __syncthreads();
    float rmx[2][2];
    #pragma unroll
    for (int i = 0; i < 2; i++)
        #pragma unroll
        for (int h = 0; h < 2; h++) {
            int row = rlo + (i << 4) + (h << 3);
            rmx[i][h] = fmaxf(fmaxf(redp[row], redp[72 + row]),
                              fmaxf(redp[144 + row], redp[216 + row]));
        }

    float sm[2][2] = { { 0.f, 0.f }, { 0.f, 0.f } };
    #pragma unroll
    for (int i = 0; i < 2; i++)
        #pragma unroll
        for (int j = 0; j < 8; j++) {
            acc[i][j].x = __expf(acc[i][j].x - rmx[i][0]);
            acc[i][j].y = __expf(acc[i][j].y - rmx[i][0]);
            acc[i][j].z = __expf(acc[i][j].z - rmx[i][1]);
            acc[i][j].w = __expf(acc[i][j].w - rmx[i][1]);
            sm[i][0] += acc[i][j].x + acc[i][j].y;
            sm[i][1] += acc[i][j].z + acc[i][j].w;
        }
    #pragma unroll
    for (int i = 0; i < 2; i++)
        #pragma unroll
        for (int h = 0; h < 2; h++) {
            sm[i][h] += __shfl_xor_sync(0xffffffffu, sm[i][h], 1);
            sm[i][h] += __shfl_xor_sync(0xffffffffu, sm[i][h], 2);
        }
    __syncthreads();
    if (tig == 0) {
        #pragma unroll
        for (int i = 0; i < 2; i++)
            #pragma unroll
            for (int h = 0; h < 2; h++)
                redp[wr * 72 + rlo + (i << 4) + (h << 3)] = sm[i][h];
    }
    __syncthreads();
    float inv[2][2];
    #pragma unroll
    for (int i = 0; i < 2; i++)
        #pragma unroll
        for (int h = 0; h < 2; h++) {
            int row = rlo + (i << 4) + (h << 3);
            inv[i][h] = 1.0f / (redp[row] + redp[72 + row] + redp[144 + row] + redp[216 + row]);
        }

    float* ub = u + ((size_t)b * MM + m0) * RR;
    #pragma unroll
    for (int i = 0; i < 2; i++) {
        int row = rlo + (i << 4);
        #pragma unroll
        for (int j = 0; j < 8; j++) {
            int col = (wr << 6) + (j << 3) + (tig << 1);
            float2 lo = { acc[i][j].x * inv[i][0], acc[i][j].y * inv[i][0] };
            float2 hi = { acc[i][j].z * inv[i][1], acc[i][j].w * inv[i][1] };
            *(float2*)(ub + (size_t)row * RR + col) = lo;
            *(float2*)(ub + (size_t)(row + 8) * RR + col) = hi;
        }
    }
    #undef STAGE_B
}

// ---------------------------------------------------------------------------
// Column sums of u (two deterministic passes)
// ---------------------------------------------------------------------------
__global__ void k_colsum_part(const float* __restrict__ u) {
    int b = blockIdx.x >> 5, chunk = blockIdx.x & 31;
    int r = threadIdx.x;
    const float* p = u + ((size_t)b * MM + (size_t)chunk * 256) * RR + r;
    float s0 = 0.f, s1 = 0.f, s2 = 0.f, s3 = 0.f;
    for (int m = 0; m < 256; m += 4) {
        s0 += p[(size_t)(m + 0) * RR];
        s1 += p[(size_t)(m + 1) * RR];
        s2 += p[(size_t)(m + 2) * RR];
        s3 += p[(size_t)(m + 3) * RR];
    }
    g_Spart[((size_t)blockIdx.x << 8) + r] = (s0 + s1) + (s2 + s3);
}

__global__ void k_colsum_final() {
    int i = blockIdx.x * blockDim.x + threadIdx.x;
    if (i >= BB * RR) return;
    int b = i >> 8, r = i & 255;
    float s = 0.f;
    #pragma unroll
    for (int c = 0; c < 32; c++) s += g_Spart[(((size_t)(b * 32 + c)) << 8) + r];
    g_S[i] = s;
}

// ---------------------------------------------------------------------------
// GEMM2 on mma.sync tf32. Pitch 136 (mod 32 = 8): conflict-free frag loads.
// ---------------------------------------------------------------------------
#define LDP 136

__global__ __launch_bounds__(256, 2) void k_gemm2_mma(
    const float* __restrict__ x, const float* __restrict__ u)
{
    const int blk = blockIdx.x;
    const int sp  = blk & 3;
    const int rt  = (blk >> 2) & 1;
    const int nt  = (blk >> 3) & 3;
    const int b   = blk >> 5;
    const int n0 = nt << 7, r0 = rt << 7;
    const int kb = sp * 2048, ke = kb + 2048;

    __shared__ uint32_t As[16 * LDP];
    __shared__ uint32_t Bs[16 * LDP];
    __shared__ float srinv[128];

    const int t = threadIdx.x;
    const int w = t >> 5, l = t & 31;
    const int gid = l >> 2, tig = l & 3;
    const int wn = (w >> 2) << 6;
    const int wr = (w & 3) << 5;
    if (t < 128) srinv[t] = 1.0f / (g_S[(b << 8) + r0 + t] + EPSV);
    __syncthreads();

    const float* xb = x + (size_t)b * MM * NN;
    const float* ub = u + (size_t)b * MM * RR;

    float4 acc[4][4];
    #pragma unroll
    for (int i = 0; i < 4; i++)
        #pragma unroll
        for (int j = 0; j < 4; j++) acc[i][j] = make_float4(0.f, 0.f, 0.f, 0.f);

    const int kkA = t >> 5;
    const int cf  = (t & 31) << 2;
    const float4 rv = *(const float4*)&srinv[cf];

    for (int k0 = kb; k0 < ke; k0 += 16) {
        float4 a0 = *(const float4*)(xb + (size_t)(k0 + kkA) * NN + n0 + cf);
        float4 a1 = *(const float4*)(xb + (size_t)(k0 + kkA + 8) * NN + n0 + cf);
        float4 b0 = *(const float4*)(ub + (size_t)(k0 + kkA) * RR + r0 + cf);
        float4 b1 = *(const float4*)(ub + (size_t)(k0 + kkA + 8) * RR + r0 + cf);
        __syncthreads();
        {
            uint4 qa0 = { f2tf32(a0.x), f2tf32(a0.y), f2tf32(a0.z), f2tf32(a0.w) };
            uint4 qa1 = { f2tf32(a1.x), f2tf32(a1.y), f2tf32(a1.z), f2tf32(a1.w) };
            uint4 qb0 = { f2tf32((b0.x + EPSV) * rv.x), f2tf32((b0.y + EPSV) * rv.y),
                          f2tf32((b0.z + EPSV) * rv.z), f2tf32((b0.w + EPSV) * rv.w) };
            uint4 qb1 = { f2tf32((b1.x + EPSV) * rv.x), f2tf32((b1.y + EPSV) * rv.y),
                          f2tf32((b1.z + EPSV) * rv.z), f2tf32((b1.w + EPSV) * rv.w) };
            *(uint4*)&As[kkA * LDP + cf]       = qa0;
            *(uint4*)&As[(kkA + 8) * LDP + cf] = qa1;
            *(uint4*)&Bs[kkA * LDP + cf]       = qb0;
            *(uint4*)&Bs[(kkA + 8) * LDP + cf] = qb1;
        }
        __syncthreads();
        #pragma unroll
        for (int kk = 0; kk < 16; kk += 8) {
            const uint32_t* Ak = &As[(kk + tig) * LDP];
            const uint32_t* Bk = &Bs[(kk + tig) * LDP];
            uint32_t af[4][4], bf[4][2];
            #pragma unroll
            for (int i = 0; i < 4; i++) {
                int base = wn + (i << 4) + gid;
                af[i][0] = Ak[base];
                af[i][1] = Ak[base + 8];
                af[i][2] = Ak[base + 4 * LDP];
                af[i][3] = Ak[base + 4 * LDP + 8];
            }
            #pragma unroll
            for (int j = 0; j < 4; j++) {
                int base = wr + (j << 3) + gid;
                bf[j][0] = Bk[base];
                bf[j][1] = Bk[base + 4 * LDP];
            }
            #pragma unroll
            for (int i = 0; i < 4; i++)
                #pragma unroll
                for (int j = 0; j < 4; j++)
                    mma_tf32(acc[i][j], af[i][0], af[i][1], af[i][2], af[i][3],
                             bf[j][0], bf[j][1]);
        }
    }

    float* pbase = g_part + ((size_t)(b * 4 + sp) * NN + n0 + wn + gid) * RR + r0 + wr + (tig << 1);
    #pragma unroll
    for (int i = 0; i < 4; i++) {
        #pragma unroll
        for (int j = 0; j < 4; j++) {
            float2 lo = { acc[i][j].x, acc[i][j].y };
            float2 hi = { acc[i][j].z, acc[i][j].w };
            float* p = pbase + (size_t)(i << 4) * RR + (j << 3);
            *(float2*)p = lo;
            *(float2*)(p + (size_t)8 * RR) = hi;
        }
    }
}

__global__ void k_vred(float* __restrict__ vout) {
    int i = blockIdx.x * blockDim.x + threadIdx.x;
    int b = i >> 17;
    int nr = i & 131071;
    float s = 0.f;
    #pragma unroll
    for (int sp = 0; sp < 4; sp++)
        s += g_part[((size_t)(b * 4 + sp)) * (NN * RR) + nr];
    vout[i] = s;
}

// ---------------------------------------------------------------------------
extern "C" void kernel_launch(void* const* d_in, const int* in_sizes, int n_in,
                              void* d_out, int out_size) {
    const float* x     = (const float*)d_in[0];
    const float* alpha = (const float*)d_in[1];
    const int*   inds  = (const int*)d_in[2];
    float* u = (float*)d_out;
    float* v = u + (size_t)BB * MM * RR;

    cudaFuncSetAttribute(k_gemm1_mma, cudaFuncAttributeMaxDynamicSharedMemorySize, G1_SMEM_BYTES);

    k_v2<<<(BB * RR) / 8, 256>>>(x, inds);
    k_prep_v<<<32, 256>>>(x, inds);
    k_gemm1_mma<<<BB * (MM / 64), 256, G1_SMEM_BYTES>>>(x, alpha, u);
    k_colsum_part<<<BB * 32, 256>>>(u);
    k_colsum_final<<<8, 256>>>();
    k_gemm2_mma<<<256, 256>>>(x, u);
    k_vred<<<(BB * NN * RR) / 256, 256>>>(v);
}